// round 1
// baseline (speedup 1.0000x reference)
#include <cuda_runtime.h>
#include <cuda_bf16.h>
#include <math.h>

#define BATCH 512
#define NUM_CAPS 181
#define IN_CAPS 96
#define CAPS_DIM 16
#define KSEL 4
#define OI (NUM_CAPS * IN_CAPS)          // 17376
#define UHAT_TILE (IN_CAPS * CAPS_DIM)   // 1536
#define MLP_ROWS (BATCH * KSEL)          // 2048

// ---------------- scratch (device globals; no allocation allowed) -------------
__device__ float d_u[BATCH * IN_CAPS * CAPS_DIM];                 // 3 MB
__device__ float d_uhat[(size_t)BATCH * NUM_CAPS * IN_CAPS * CAPS_DIM]; // 569 MB
__device__ float d_bl[BATCH * OI];                                // 35.6 MB
__device__ float d_c[BATCH * OI];                                 // 35.6 MB
__device__ float d_x[BATCH * NUM_CAPS * CAPS_DIM];                // 5.9 MB
__device__ int   d_idx[BATCH * KSEL];
__device__ float d_g[MLP_ROWS * CAPS_DIM];
__device__ float d_m0[MLP_ROWS * 1024];
__device__ float d_m1[MLP_ROWS * 1024];

__device__ __forceinline__ float gelu_f(float x) {
    return 0.5f * x * (1.0f + erff(x * 0.70710678118654752f));
}

// ---------------- 1) fused conv stack + primary caps + squash ------------------
__global__ void conv_stack_kernel(const float* __restrict__ scm,
                                  const float* __restrict__ w1, const float* __restrict__ b1,
                                  const float* __restrict__ w2, const float* __restrict__ b2,
                                  const float* __restrict__ w3, const float* __restrict__ b3,
                                  const float* __restrict__ pw, const float* __restrict__ pb) {
    __shared__ float A[4608];   // in(192) -> h2(128*36) -> u(1536)
    __shared__ float Bf[6400];  // h1(64*49) -> h3(256*25)
    const int b = blockIdx.x, t = threadIdx.x;

    const float* in = scm + b * 192;
    for (int i = t; i < 192; i += 256) A[i] = in[i];
    __syncthreads();

    // conv1: 3x8x8 -> 64x7x7 (Bf)
    for (int idx = t; idx < 64 * 49; idx += 256) {
        int oc = idx / 49, r = idx % 49, y = r / 7, x = r % 7;
        float acc = b1[oc];
        const float* wp = w1 + oc * 12;
        #pragma unroll
        for (int ic = 0; ic < 3; ic++) {
            const float* ip = A + ic * 64 + y * 8 + x;
            acc += ip[0]*wp[0] + ip[1]*wp[1] + ip[8]*wp[2] + ip[9]*wp[3];
            wp += 4;
        }
        Bf[idx] = gelu_f(acc);
    }
    __syncthreads();

    // conv2: 64x7x7 -> 128x6x6 (A)
    for (int idx = t; idx < 128 * 36; idx += 256) {
        int oc = idx / 36, r = idx % 36, y = r / 6, x = r % 6;
        float acc = b2[oc];
        const float* wp = w2 + oc * 256;
        const float* base = Bf + y * 7 + x;
        for (int ic = 0; ic < 64; ic++) {
            const float* ip = base + ic * 49;
            acc += ip[0]*wp[0] + ip[1]*wp[1] + ip[7]*wp[2] + ip[8]*wp[3];
            wp += 4;
        }
        A[idx] = gelu_f(acc);
    }
    __syncthreads();

    // conv3: 128x6x6 -> 256x5x5 (Bf)
    for (int idx = t; idx < 256 * 25; idx += 256) {
        int oc = idx / 25, r = idx % 25, y = r / 5, x = r % 5;
        float acc = b3[oc];
        const float* wp = w3 + oc * 512;
        const float* base = A + y * 6 + x;
        for (int ic = 0; ic < 128; ic++) {
            const float* ip = base + ic * 36;
            acc += ip[0]*wp[0] + ip[1]*wp[1] + ip[6]*wp[2] + ip[7]*wp[3];
            wp += 4;
        }
        Bf[idx] = gelu_f(acc);
    }
    __syncthreads();

    // primary caps: 256x5x5 -> 96x4x4 (A[0..1535]); no activation
    for (int idx = t; idx < 96 * 16; idx += 256) {
        int g = idx / 16, r = idx % 16, y = r / 4, x = r % 4;
        float acc = pb[g];
        const float* wp = pw + g * 1024;
        const float* base = Bf + y * 5 + x;
        for (int ic = 0; ic < 256; ic++) {
            const float* ip = base + ic * 25;
            acc += ip[0]*wp[0] + ip[1]*wp[1] + ip[5]*wp[2] + ip[6]*wp[3];
            wp += 4;
        }
        A[idx] = acc;
    }
    __syncthreads();

    // squash per capsule, store u
    if (t < 96) {
        float n2 = 0.f;
        #pragma unroll
        for (int d = 0; d < 16; d++) { float v = A[t * 16 + d]; n2 += v * v; }
        float n = sqrtf(n2);
        float sc = (1.0f - expf(-n)) / (n + 1e-8f);
        #pragma unroll
        for (int d = 0; d < 16; d++)
            d_u[b * 1536 + t * 16 + d] = A[t * 16 + d] * sc;
    }
}

// ---------------- 2) u_hat = einsum('oidk,bik->boid') --------------------------
// block = (i-chunk of 16, o). W rows live in registers; loops over b.
__global__ void uhat_kernel(const float* __restrict__ capsW) {
    const int o = blockIdx.y, ic0 = blockIdx.x * 16;
    const int t = threadIdx.x, il = t >> 4, d = t & 15;
    float wr[16];
    const float* wp = capsW + (((size_t)o * 96 + ic0 + il) * 16 + d) * 16;
    #pragma unroll
    for (int k = 0; k < 16; k++) wr[k] = wp[k];

    __shared__ float us[4 * 256];
    for (int b0 = 0; b0 < BATCH; b0 += 4) {
        #pragma unroll
        for (int j = t; j < 1024; j += 256) {
            int bb = j >> 8, e = j & 255;
            us[j] = d_u[(b0 + bb) * 1536 + ic0 * 16 + e];
        }
        __syncthreads();
        #pragma unroll
        for (int bb = 0; bb < 4; bb++) {
            const float* ur = us + bb * 256 + il * 16;
            float acc = 0.f;
            #pragma unroll
            for (int k = 0; k < 16; k++) acc += wr[k] * ur[k];
            d_uhat[((size_t)(b0 + bb) * NUM_CAPS + o) * UHAT_TILE + ic0 * 16 + t] = acc;
        }
        __syncthreads();
    }
}

// ---------------- 3) routing ---------------------------------------------------
__global__ void initbl_kernel(const float* __restrict__ caps_b) {
    int i = blockIdx.x * 256 + threadIdx.x;
    if (i < BATCH * OI) d_bl[i] = caps_b[i % OI];
}

// softmax over out-caps axis: one thread per (b, i)
__global__ void softmax_kernel() {
    int b = blockIdx.x, i = threadIdx.x;  // 96 threads
    const float* base = d_bl + (size_t)b * OI + i;
    float m = -1e30f, s = 0.f;
    for (int o = 0; o < NUM_CAPS; o++) {
        float v = base[o * 96];
        float nm = fmaxf(m, v);
        s = s * expf(m - nm) + expf(v - nm);
        m = nm;
    }
    float inv = 1.0f / s;
    float* cb = d_c + (size_t)b * OI + i;
    for (int o = 0; o < NUM_CAPS; o++) cb[o * 96] = expf(base[o * 96] - m) * inv;
}

// per (b,o): s = sum_i c*u_hat ; v = squash(s) ; b += v . u_hat (or write x on last)
__global__ void route_kernel(int last) {
    const int o = blockIdx.x, b = blockIdx.y, t = threadIdx.x; // 128 threads
    __shared__ float red[128 * 17];
    __shared__ float vsh[16];
    float uh[16];
    float ci = 0.f;
    const size_t ub = ((size_t)(b * NUM_CAPS + o)) * UHAT_TILE;
    if (t < 96) {
        ci = d_c[(b * NUM_CAPS + o) * 96 + t];
        const float4* up = reinterpret_cast<const float4*>(d_uhat + ub + t * 16);
        #pragma unroll
        for (int q = 0; q < 4; q++) {
            float4 f = up[q];
            uh[4*q] = f.x; uh[4*q+1] = f.y; uh[4*q+2] = f.z; uh[4*q+3] = f.w;
        }
    } else {
        #pragma unroll
        for (int d = 0; d < 16; d++) uh[d] = 0.f;
    }
    #pragma unroll
    for (int d = 0; d < 16; d++) red[t * 17 + d] = ci * uh[d];
    __syncthreads();
    for (int s = 64; s > 0; s >>= 1) {
        if (t < s) {
            #pragma unroll
            for (int d = 0; d < 16; d++) red[t * 17 + d] += red[(t + s) * 17 + d];
        }
        __syncthreads();
    }
    if (t == 0) {
        float n2 = 0.f;
        #pragma unroll
        for (int d = 0; d < 16; d++) { float sv = red[d]; n2 += sv * sv; }
        float n = sqrtf(n2);
        float sc = (1.0f - expf(-n)) / (n + 1e-8f);
        #pragma unroll
        for (int d = 0; d < 16; d++) vsh[d] = red[d] * sc;
    }
    __syncthreads();
    if (last) {
        if (t < 16) d_x[(b * NUM_CAPS + o) * 16 + t] = vsh[t];
    } else if (t < 96) {
        float inc = 0.f;
        #pragma unroll
        for (int d = 0; d < 16; d++) inc += vsh[d] * uh[d];
        d_bl[(b * NUM_CAPS + o) * 96 + t] += inc;
    }
}

// ---------------- 4) length, peaks, top-K, gather ------------------------------
__global__ void finalize_kernel(float* __restrict__ outL) {
    const int b = blockIdx.x, t = threadIdx.x; // 256 threads
    __shared__ float len[192], lnN[192], pk[192], red[256];
    float L = 0.f;
    if (t < NUM_CAPS) {
        const float* xp = d_x + ((size_t)b * NUM_CAPS + t) * 16;
        float n2 = 0.f;
        #pragma unroll
        for (int d = 0; d < 16; d++) { float v = xp[d]; n2 += v * v; }
        L = sqrtf(n2);
        len[t] = L;
    }
    red[t] = (t < NUM_CAPS) ? L : 0.f;
    __syncthreads();
    for (int s = 128; s > 0; s >>= 1) {
        if (t < s) red[t] += red[t + s];
        __syncthreads();
    }
    float tot = red[0];
    if (t < NUM_CAPS) {
        float ln = len[t] / (tot + 1e-8f);
        lnN[t] = ln;
        outL[b * NUM_CAPS + t] = ln;
    }
    __syncthreads();
    if (t < NUM_CAPS) {
        int lo = t - 5 > 0 ? t - 5 : 0;
        int hi = t + 5 < 180 ? t + 5 : 180;
        float m = -1e30f;
        for (int o = lo; o <= hi; o++) m = fmaxf(m, lnN[o]);
        pk[t] = (lnN[t] == m) ? lnN[t] : 0.f;
    }
    __syncthreads();
    if (t == 0) {
        int sel[KSEL];
        for (int k = 0; k < KSEL; k++) {
            int best = -1; float bv = -1e30f;
            for (int o = 0; o < NUM_CAPS; o++)
                if (pk[o] > bv) { bv = pk[o]; best = o; }  // strict > => ties -> lowest idx
            sel[k] = best;
            pk[best] = -1e30f;
        }
        // sort ascending
        for (int a = 1; a < KSEL; a++) {
            int v = sel[a], j = a - 1;
            while (j >= 0 && sel[j] > v) { sel[j + 1] = sel[j]; j--; }
            sel[j + 1] = v;
        }
        for (int k = 0; k < KSEL; k++) {
            d_idx[b * KSEL + k] = sel[k];
            const float* xp = d_x + ((size_t)b * NUM_CAPS + sel[k]) * 16;
            float* gp = d_g + (b * KSEL + k) * 16;
            for (int d = 0; d < 16; d++) gp[d] = xp[d];
        }
    }
}

// ---------------- 5) MLP -------------------------------------------------------
// fc1: masked input -> only 16 rows of fc1_w matter
__global__ void fc1_kernel(const float* __restrict__ w, const float* __restrict__ bias) {
    const int r = blockIdx.y;
    const int j = blockIdx.x * 256 + threadIdx.x;  // < 1024
    __shared__ float gr[16];
    __shared__ int base;
    if (threadIdx.x < 16) gr[threadIdx.x] = d_g[r * 16 + threadIdx.x];
    if (threadIdx.x == 0) base = d_idx[r] * 16;
    __syncthreads();
    float acc = bias[j];
    #pragma unroll
    for (int d = 0; d < 16; d++) acc += gr[d] * w[(size_t)(base + d) * 1024 + j];
    d_m0[r * 1024 + j] = gelu_f(acc);
}

// generic tiled fp32 GEMM: C = act(A @ W + bias). M=2048, 64x64 tiles.
// asel/csel: 0 -> d_m0, 1 -> d_m1, 2 -> cout (head output, transposed write)
__global__ void gemm_kernel(int asel, int csel, const float* __restrict__ W,
                            const float* __restrict__ bias, float* cout,
                            int Kd, int N, int act, int transOut) {
    const float* A = (asel == 0) ? d_m0 : d_m1;
    float* C = (csel == 0) ? d_m0 : (csel == 1) ? d_m1 : cout;
    __shared__ float As[16][64];
    __shared__ float Ws[16][68];
    const int bm = blockIdx.y * 64, bn = blockIdx.x * 64;
    const int t = threadIdx.x, tx = t & 15, ty = t >> 4;
    float acc[4][4];
    #pragma unroll
    for (int p = 0; p < 4; p++)
        #pragma unroll
        for (int q = 0; q < 4; q++) acc[p][q] = 0.f;

    for (int k0 = 0; k0 < Kd; k0 += 16) {
        #pragma unroll
        for (int i = 0; i < 4; i++) {
            int l = t + i * 256, r = l >> 4, c = l & 15;
            As[c][r] = A[(size_t)(bm + r) * Kd + k0 + c];
        }
        #pragma unroll
        for (int i = 0; i < 4; i++) {
            int l = t + i * 256, r = l >> 6, c = l & 63;
            Ws[r][c] = W[(size_t)(k0 + r) * N + bn + c];
        }
        __syncthreads();
        #pragma unroll
        for (int kk = 0; kk < 16; kk++) {
            float a[4], bb[4];
            #pragma unroll
            for (int p = 0; p < 4; p++) a[p] = As[kk][ty * 4 + p];
            #pragma unroll
            for (int q = 0; q < 4; q++) bb[q] = Ws[kk][tx * 4 + q];
            #pragma unroll
            for (int p = 0; p < 4; p++)
                #pragma unroll
                for (int q = 0; q < 4; q++) acc[p][q] += a[p] * bb[q];
        }
        __syncthreads();
    }
    #pragma unroll
    for (int p = 0; p < 4; p++) {
        #pragma unroll
        for (int q = 0; q < 4; q++) {
            int m = bm + ty * 4 + p, n = bn + tx * 4 + q;
            float v = acc[p][q] + bias[n];
            if (act) v = gelu_f(v);
            if (!transOut) C[(size_t)m * N + n] = v;
            else C[(size_t)(m >> 2) * (N * 4) + n * 4 + (m & 3)] = v; // [b, 2A, K]
        }
    }
}

// ---------------- launch -------------------------------------------------------
extern "C" void kernel_launch(void* const* d_in, const int* in_sizes, int n_in,
                              void* d_out, int out_size) {
    const float* scm  = (const float*)d_in[0];
    // d_in[1] = K (always 4 in setup)
    const float* c1w = (const float*)d_in[2];  const float* c1b = (const float*)d_in[3];
    const float* c2w = (const float*)d_in[4];  const float* c2b = (const float*)d_in[5];
    const float* c3w = (const float*)d_in[6];  const float* c3b = (const float*)d_in[7];
    const float* pcw = (const float*)d_in[8];  const float* pcb = (const float*)d_in[9];
    const float* capsW = (const float*)d_in[10];
    const float* capsb = (const float*)d_in[11];
    const float* f1w = (const float*)d_in[12]; const float* f1b = (const float*)d_in[13];
    const float* f2w = (const float*)d_in[14]; const float* f2b = (const float*)d_in[15];
    const float* f3w = (const float*)d_in[16]; const float* f3b = (const float*)d_in[17];
    const float* f4w = (const float*)d_in[18]; const float* f4b = (const float*)d_in[19];
    const float* f5w = (const float*)d_in[20]; const float* f5b = (const float*)d_in[21];
    const float* hw  = (const float*)d_in[22]; const float* hb  = (const float*)d_in[23];

    float* outW = (float*)d_out;                       // [512, 128, 4]
    float* outL = outW + BATCH * 128 * KSEL;           // [512, 181]

    conv_stack_kernel<<<BATCH, 256>>>(scm, c1w, c1b, c2w, c2b, c3w, c3b, pcw, pcb);
    uhat_kernel<<<dim3(6, NUM_CAPS), 256>>>(capsW);
    initbl_kernel<<<(BATCH * OI + 255) / 256, 256>>>(capsb);
    for (int it = 0; it < 3; it++) {
        softmax_kernel<<<BATCH, 96>>>();
        route_kernel<<<dim3(NUM_CAPS, BATCH), 128>>>(it == 2 ? 1 : 0);
    }
    finalize_kernel<<<BATCH, 256>>>(outL);
    fc1_kernel<<<dim3(4, MLP_ROWS), 256>>>(f1w, f1b);
    gemm_kernel<<<dim3(12, 32), 256>>>(0, 1, f2w, f2b, nullptr, 1024, 768, 1, 0);
    gemm_kernel<<<dim3( 8, 32), 256>>>(1, 0, f3w, f3b, nullptr,  768, 512, 1, 0);
    gemm_kernel<<<dim3( 8, 32), 256>>>(0, 1, f4w, f4b, nullptr,  512, 512, 1, 0);
    gemm_kernel<<<dim3( 4, 32), 256>>>(1, 0, f5w, f5b, nullptr,  512, 256, 1, 0);
    gemm_kernel<<<dim3( 2, 32), 256>>>(0, 2, hw,  hb,  outW,     256, 128, 0, 1);
}

// round 2
// speedup vs baseline: 1.1990x; 1.1990x over previous
#include <cuda_runtime.h>
#include <cuda_bf16.h>
#include <math.h>

#define BATCH 512
#define NUM_CAPS 181
#define IN_CAPS 96
#define CAPS_DIM 16
#define KSEL 4
#define OI (NUM_CAPS * IN_CAPS)          // 17376
#define UHAT_TILE (IN_CAPS * CAPS_DIM)   // 1536
#define MLP_ROWS (BATCH * KSEL)          // 2048

// ---------------- scratch (device globals; no allocation allowed) -------------
__device__ float d_u[BATCH * IN_CAPS * CAPS_DIM];                 // 3 MB
__device__ float d_uhat[(size_t)BATCH * NUM_CAPS * IN_CAPS * CAPS_DIM]; // 569 MB
__device__ float d_bl[BATCH * OI];                                // 35.6 MB
__device__ float d_c[BATCH * OI];                                 // 35.6 MB
__device__ float d_x[BATCH * NUM_CAPS * CAPS_DIM];                // 5.9 MB
__device__ int   d_idx[BATCH * KSEL];
__device__ float d_g[MLP_ROWS * CAPS_DIM];
__device__ float d_m0[MLP_ROWS * 1024];
__device__ float d_m1[MLP_ROWS * 1024];

__device__ __forceinline__ float gelu_f(float x) {
    return 0.5f * x * (1.0f + erff(x * 0.70710678118654752f));
}

// ---------------- 1) fused conv stack + primary caps + squash ------------------
__global__ void conv_stack_kernel(const float* __restrict__ scm,
                                  const float* __restrict__ w1, const float* __restrict__ b1,
                                  const float* __restrict__ w2, const float* __restrict__ b2,
                                  const float* __restrict__ w3, const float* __restrict__ b3,
                                  const float* __restrict__ pw, const float* __restrict__ pb) {
    __shared__ float A[4608];   // in(192) -> h2(128*36) -> u(1536)
    __shared__ float Bf[6400];  // h1(64*49) -> h3(256*25)
    const int b = blockIdx.x, t = threadIdx.x;

    const float* in = scm + b * 192;
    for (int i = t; i < 192; i += 256) A[i] = in[i];
    __syncthreads();

    // conv1: 3x8x8 -> 64x7x7 (Bf)
    for (int idx = t; idx < 64 * 49; idx += 256) {
        int oc = idx / 49, r = idx % 49, y = r / 7, x = r % 7;
        float acc = b1[oc];
        const float* wp = w1 + oc * 12;
        #pragma unroll
        for (int ic = 0; ic < 3; ic++) {
            const float* ip = A + ic * 64 + y * 8 + x;
            acc += ip[0]*wp[0] + ip[1]*wp[1] + ip[8]*wp[2] + ip[9]*wp[3];
            wp += 4;
        }
        Bf[idx] = gelu_f(acc);
    }
    __syncthreads();

    // conv2: 64x7x7 -> 128x6x6 (A)
    for (int idx = t; idx < 128 * 36; idx += 256) {
        int oc = idx / 36, r = idx % 36, y = r / 6, x = r % 6;
        float acc = b2[oc];
        const float* wp = w2 + oc * 256;
        const float* base = Bf + y * 7 + x;
        for (int ic = 0; ic < 64; ic++) {
            const float* ip = base + ic * 49;
            acc += ip[0]*wp[0] + ip[1]*wp[1] + ip[7]*wp[2] + ip[8]*wp[3];
            wp += 4;
        }
        A[idx] = gelu_f(acc);
    }
    __syncthreads();

    // conv3: 128x6x6 -> 256x5x5 (Bf)
    for (int idx = t; idx < 256 * 25; idx += 256) {
        int oc = idx / 25, r = idx % 25, y = r / 5, x = r % 5;
        float acc = b3[oc];
        const float* wp = w3 + oc * 512;
        const float* base = A + y * 6 + x;
        for (int ic = 0; ic < 128; ic++) {
            const float* ip = base + ic * 36;
            acc += ip[0]*wp[0] + ip[1]*wp[1] + ip[6]*wp[2] + ip[7]*wp[3];
            wp += 4;
        }
        Bf[idx] = gelu_f(acc);
    }
    __syncthreads();

    // primary caps: 256x5x5 -> 96x4x4 (A[0..1535]); no activation
    for (int idx = t; idx < 96 * 16; idx += 256) {
        int g = idx / 16, r = idx % 16, y = r / 4, x = r % 4;
        float acc = pb[g];
        const float* wp = pw + g * 1024;
        const float* base = Bf + y * 5 + x;
        for (int ic = 0; ic < 256; ic++) {
            const float* ip = base + ic * 25;
            acc += ip[0]*wp[0] + ip[1]*wp[1] + ip[5]*wp[2] + ip[6]*wp[3];
            wp += 4;
        }
        A[idx] = acc;
    }
    __syncthreads();

    // squash per capsule, store u
    if (t < 96) {
        float n2 = 0.f;
        #pragma unroll
        for (int d = 0; d < 16; d++) { float v = A[t * 16 + d]; n2 += v * v; }
        float n = sqrtf(n2);
        float sc = (1.0f - expf(-n)) / (n + 1e-8f);
        #pragma unroll
        for (int d = 0; d < 16; d++)
            d_u[b * 1536 + t * 16 + d] = A[t * 16 + d] * sc;
    }
}

// ---------------- 2) u_hat = einsum('oidk,bik->boid') --------------------------
// block = (i-chunk of 16, o). W rows live in registers; loops over b.
__global__ void uhat_kernel(const float* __restrict__ capsW) {
    const int o = blockIdx.y, ic0 = blockIdx.x * 16;
    const int t = threadIdx.x, il = t >> 4, d = t & 15;
    float wr[16];
    const float* wp = capsW + (((size_t)o * 96 + ic0 + il) * 16 + d) * 16;
    #pragma unroll
    for (int k = 0; k < 16; k++) wr[k] = wp[k];

    __shared__ float us[4 * 256];
    for (int b0 = 0; b0 < BATCH; b0 += 4) {
        #pragma unroll
        for (int j = t; j < 1024; j += 256) {
            int bb = j >> 8, e = j & 255;
            us[j] = d_u[(b0 + bb) * 1536 + ic0 * 16 + e];
        }
        __syncthreads();
        #pragma unroll
        for (int bb = 0; bb < 4; bb++) {
            const float* ur = us + bb * 256 + il * 16;
            float acc = 0.f;
            #pragma unroll
            for (int k = 0; k < 16; k++) acc += wr[k] * ur[k];
            d_uhat[((size_t)(b0 + bb) * NUM_CAPS + o) * UHAT_TILE + ic0 * 16 + t] = acc;
        }
        __syncthreads();
    }
}

// ---------------- 3) routing ---------------------------------------------------
__global__ void initbl_kernel(const float* __restrict__ caps_b) {
    int i = blockIdx.x * 256 + threadIdx.x;
    if (i < BATCH * OI) d_bl[i] = caps_b[i % OI];
}

// softmax over out-caps axis. Block per b. Coalesced load into padded smem
// [o][i] (stride 97 -> conflict-free columns). One exp per element.
__global__ void softmax2_kernel() {
    extern __shared__ float sb[];            // 181*97 + 96 floats
    float* invs = sb + NUM_CAPS * 97;
    const int b = blockIdx.x, t = threadIdx.x;
    const float* blp = d_bl + (size_t)b * OI;
    for (int e = t; e < OI; e += 256) sb[(e / 96) * 97 + (e % 96)] = blp[e];
    __syncthreads();
    const int wid = t >> 5, lane = t & 31;
    for (int i = wid; i < 96; i += 8) {
        float m = -1e30f;
        for (int o = lane; o < NUM_CAPS; o += 32) m = fmaxf(m, sb[o * 97 + i]);
        #pragma unroll
        for (int s = 16; s; s >>= 1) m = fmaxf(m, __shfl_xor_sync(0xffffffffu, m, s));
        float s = 0.f;
        for (int o = lane; o < NUM_CAPS; o += 32) {
            float e2 = expf(sb[o * 97 + i] - m);
            sb[o * 97 + i] = e2;
            s += e2;
        }
        #pragma unroll
        for (int sh = 16; sh; sh >>= 1) s += __shfl_xor_sync(0xffffffffu, s, sh);
        if (lane == 0) invs[i] = 1.0f / s;
    }
    __syncthreads();
    float* cp = d_c + (size_t)b * OI;
    for (int e = t; e < OI; e += 256) cp[e] = sb[(e / 96) * 97 + (e % 96)] * invs[e % 96];
}

// warp-per-(b,o) routing step. u_hat tile (6KB) streamed into registers with
// 48 coalesced 128B loads; all reductions via shuffles; zero block barriers.
__global__ __launch_bounds__(256) void route2_kernel(int last) {
    __shared__ float incsh[8][96];
    const int wid = threadIdx.x >> 5, lane = threadIdx.x & 31;
    const int w = blockIdx.x * 8 + wid;            // w = b*181 + o, exact grid
    const int ih = lane >> 4;                      // which of 2 i's per load
    const float* up = d_uhat + (size_t)w * UHAT_TILE;
    const float* cp = d_c + (size_t)w * 96;
    float creg0 = cp[lane], creg1 = cp[32 + lane], creg2 = cp[64 + lane];

    float uvr[48];
    float acc = 0.f;
    #pragma unroll
    for (int it = 0; it < 48; it++) {
        float uv = up[it * 32 + lane];             // element i*16+d, i=2it+ih, d=lane&15
        uvr[it] = uv;
        float cv;
        if (it < 16)      cv = __shfl_sync(0xffffffffu, creg0, (2 * it + ih) & 31);
        else if (it < 32) cv = __shfl_sync(0xffffffffu, creg1, (2 * it + ih) & 31);
        else              cv = __shfl_sync(0xffffffffu, creg2, (2 * it + ih) & 31);
        acc += cv * uv;
    }
    // combine the two i-halves -> s[d] replicated in both halves
    acc += __shfl_xor_sync(0xffffffffu, acc, 16);
    // ||s||^2 over d (16-lane groups)
    float sq = acc * acc;
    sq += __shfl_xor_sync(0xffffffffu, sq, 8);
    sq += __shfl_xor_sync(0xffffffffu, sq, 4);
    sq += __shfl_xor_sync(0xffffffffu, sq, 2);
    sq += __shfl_xor_sync(0xffffffffu, sq, 1);
    float n = sqrtf(sq);
    float v = acc * ((1.0f - expf(-n)) / (n + 1e-8f));

    if (last) {
        if (lane < 16) d_x[(size_t)w * 16 + lane] = v;
    } else {
        #pragma unroll
        for (int it = 0; it < 48; it++) {
            float p = v * uvr[it];
            p += __shfl_xor_sync(0xffffffffu, p, 8);
            p += __shfl_xor_sync(0xffffffffu, p, 4);
            p += __shfl_xor_sync(0xffffffffu, p, 2);
            p += __shfl_xor_sync(0xffffffffu, p, 1);
            if ((lane & 15) == 0) incsh[wid][2 * it + ih] = p;
        }
        __syncwarp();
        float* blp = d_bl + (size_t)w * 96;
        #pragma unroll
        for (int r = 0; r < 3; r++) blp[r * 32 + lane] += incsh[wid][r * 32 + lane];
    }
}

// ---------------- 4) length, peaks, top-K, gather ------------------------------
__global__ void finalize_kernel(float* __restrict__ outL) {
    const int b = blockIdx.x, t = threadIdx.x; // 256 threads
    __shared__ float len[192], lnN[192], pk[192], red[256];
    float L = 0.f;
    if (t < NUM_CAPS) {
        const float* xp = d_x + ((size_t)b * NUM_CAPS + t) * 16;
        float n2 = 0.f;
        #pragma unroll
        for (int d = 0; d < 16; d++) { float v = xp[d]; n2 += v * v; }
        L = sqrtf(n2);
        len[t] = L;
    }
    red[t] = (t < NUM_CAPS) ? L : 0.f;
    __syncthreads();
    for (int s = 128; s > 0; s >>= 1) {
        if (t < s) red[t] += red[t + s];
        __syncthreads();
    }
    float tot = red[0];
    if (t < NUM_CAPS) {
        float ln = len[t] / (tot + 1e-8f);
        lnN[t] = ln;
        outL[b * NUM_CAPS + t] = ln;
    }
    __syncthreads();
    if (t < NUM_CAPS) {
        int lo = t - 5 > 0 ? t - 5 : 0;
        int hi = t + 5 < 180 ? t + 5 : 180;
        float m = -1e30f;
        for (int o = lo; o <= hi; o++) m = fmaxf(m, lnN[o]);
        pk[t] = (lnN[t] == m) ? lnN[t] : 0.f;
    }
    __syncthreads();
    if (t == 0) {
        int sel[KSEL];
        for (int k = 0; k < KSEL; k++) {
            int best = -1; float bv = -1e30f;
            for (int o = 0; o < NUM_CAPS; o++)
                if (pk[o] > bv) { bv = pk[o]; best = o; }  // strict > => ties -> lowest idx
            sel[k] = best;
            pk[best] = -1e30f;
        }
        // sort ascending
        for (int a = 1; a < KSEL; a++) {
            int v = sel[a], j = a - 1;
            while (j >= 0 && sel[j] > v) { sel[j + 1] = sel[j]; j--; }
            sel[j + 1] = v;
        }
        for (int k = 0; k < KSEL; k++) {
            d_idx[b * KSEL + k] = sel[k];
            const float* xp = d_x + ((size_t)b * NUM_CAPS + sel[k]) * 16;
            float* gp = d_g + (b * KSEL + k) * 16;
            for (int d = 0; d < 16; d++) gp[d] = xp[d];
        }
    }
}

// ---------------- 5) MLP -------------------------------------------------------
// fc1: masked input -> only 16 rows of fc1_w matter
__global__ void fc1_kernel(const float* __restrict__ w, const float* __restrict__ bias) {
    const int r = blockIdx.y;
    const int j = blockIdx.x * 256 + threadIdx.x;  // < 1024
    __shared__ float gr[16];
    __shared__ int base;
    if (threadIdx.x < 16) gr[threadIdx.x] = d_g[r * 16 + threadIdx.x];
    if (threadIdx.x == 0) base = d_idx[r] * 16;
    __syncthreads();
    float acc = bias[j];
    #pragma unroll
    for (int d = 0; d < 16; d++) acc += gr[d] * w[(size_t)(base + d) * 1024 + j];
    d_m0[r * 1024 + j] = gelu_f(acc);
}

// generic tiled fp32 GEMM: C = act(A @ W + bias). M=2048, 64x64 tiles.
// asel/csel: 0 -> d_m0, 1 -> d_m1, 2 -> cout (head output, transposed write)
__global__ void gemm_kernel(int asel, int csel, const float* __restrict__ W,
                            const float* __restrict__ bias, float* cout,
                            int Kd, int N, int act, int transOut) {
    const float* A = (asel == 0) ? d_m0 : d_m1;
    float* C = (csel == 0) ? d_m0 : (csel == 1) ? d_m1 : cout;
    __shared__ float As[16][64];
    __shared__ float Ws[16][68];
    const int bm = blockIdx.y * 64, bn = blockIdx.x * 64;
    const int t = threadIdx.x, tx = t & 15, ty = t >> 4;
    float acc[4][4];
    #pragma unroll
    for (int p = 0; p < 4; p++)
        #pragma unroll
        for (int q = 0; q < 4; q++) acc[p][q] = 0.f;

    for (int k0 = 0; k0 < Kd; k0 += 16) {
        #pragma unroll
        for (int i = 0; i < 4; i++) {
            int l = t + i * 256, r = l >> 4, c = l & 15;
            As[c][r] = A[(size_t)(bm + r) * Kd + k0 + c];
        }
        #pragma unroll
        for (int i = 0; i < 4; i++) {
            int l = t + i * 256, r = l >> 6, c = l & 63;
            Ws[r][c] = W[(size_t)(k0 + r) * N + bn + c];
        }
        __syncthreads();
        #pragma unroll
        for (int kk = 0; kk < 16; kk++) {
            float a[4], bb[4];
            #pragma unroll
            for (int p = 0; p < 4; p++) a[p] = As[kk][ty * 4 + p];
            #pragma unroll
            for (int q = 0; q < 4; q++) bb[q] = Ws[kk][tx * 4 + q];
            #pragma unroll
            for (int p = 0; p < 4; p++)
                #pragma unroll
                for (int q = 0; q < 4; q++) acc[p][q] += a[p] * bb[q];
        }
        __syncthreads();
    }
    #pragma unroll
    for (int p = 0; p < 4; p++) {
        #pragma unroll
        for (int q = 0; q < 4; q++) {
            int m = bm + ty * 4 + p, n = bn + tx * 4 + q;
            float v = acc[p][q] + bias[n];
            if (act) v = gelu_f(v);
            if (!transOut) C[(size_t)m * N + n] = v;
            else C[(size_t)(m >> 2) * (N * 4) + n * 4 + (m & 3)] = v; // [b, 2A, K]
        }
    }
}

// ---------------- launch -------------------------------------------------------
extern "C" void kernel_launch(void* const* d_in, const int* in_sizes, int n_in,
                              void* d_out, int out_size) {
    const float* scm  = (const float*)d_in[0];
    // d_in[1] = K (always 4 in setup)
    const float* c1w = (const float*)d_in[2];  const float* c1b = (const float*)d_in[3];
    const float* c2w = (const float*)d_in[4];  const float* c2b = (const float*)d_in[5];
    const float* c3w = (const float*)d_in[6];  const float* c3b = (const float*)d_in[7];
    const float* pcw = (const float*)d_in[8];  const float* pcb = (const float*)d_in[9];
    const float* capsW = (const float*)d_in[10];
    const float* capsb = (const float*)d_in[11];
    const float* f1w = (const float*)d_in[12]; const float* f1b = (const float*)d_in[13];
    const float* f2w = (const float*)d_in[14]; const float* f2b = (const float*)d_in[15];
    const float* f3w = (const float*)d_in[16]; const float* f3b = (const float*)d_in[17];
    const float* f4w = (const float*)d_in[18]; const float* f4b = (const float*)d_in[19];
    const float* f5w = (const float*)d_in[20]; const float* f5b = (const float*)d_in[21];
    const float* hw  = (const float*)d_in[22]; const float* hb  = (const float*)d_in[23];

    float* outW = (float*)d_out;                       // [512, 128, 4]
    float* outL = outW + BATCH * 128 * KSEL;           // [512, 181]

    static int smax_smem_set = 0;
    const int smax_smem = (NUM_CAPS * 97 + 96) * sizeof(float);  // ~70.6 KB
    if (!smax_smem_set) {
        cudaFuncSetAttribute(softmax2_kernel,
                             cudaFuncAttributeMaxDynamicSharedMemorySize, smax_smem);
        smax_smem_set = 1;
    }

    conv_stack_kernel<<<BATCH, 256>>>(scm, c1w, c1b, c2w, c2b, c3w, c3b, pcw, pcb);
    uhat_kernel<<<dim3(6, NUM_CAPS), 256>>>(capsW);
    initbl_kernel<<<(BATCH * OI + 255) / 256, 256>>>(capsb);
    for (int it = 0; it < 3; it++) {
        softmax2_kernel<<<BATCH, 256, smax_smem>>>();
        route2_kernel<<<BATCH * NUM_CAPS / 8, 256>>>(it == 2 ? 1 : 0);
    }
    finalize_kernel<<<BATCH, 256>>>(outL);
    fc1_kernel<<<dim3(4, MLP_ROWS), 256>>>(f1w, f1b);
    gemm_kernel<<<dim3(12, 32), 256>>>(0, 1, f2w, f2b, nullptr, 1024, 768, 1, 0);
    gemm_kernel<<<dim3( 8, 32), 256>>>(1, 0, f3w, f3b, nullptr,  768, 512, 1, 0);
    gemm_kernel<<<dim3( 8, 32), 256>>>(0, 1, f4w, f4b, nullptr,  512, 512, 1, 0);
    gemm_kernel<<<dim3( 4, 32), 256>>>(1, 0, f5w, f5b, nullptr,  512, 256, 1, 0);
    gemm_kernel<<<dim3( 2, 32), 256>>>(0, 2, hw,  hb,  outW,     256, 128, 0, 1);
}

// round 3
// speedup vs baseline: 1.3258x; 1.1058x over previous
#include <cuda_runtime.h>
#include <cuda_bf16.h>
#include <math.h>

#define BATCH 512
#define NUM_CAPS 181
#define IN_CAPS 96
#define CAPS_DIM 16
#define KSEL 4
#define OI (NUM_CAPS * IN_CAPS)          // 17376
#define UHAT_TILE (IN_CAPS * CAPS_DIM)   // 1536
#define MLP_ROWS (BATCH * KSEL)          // 2048

// ---------------- scratch (device globals; no allocation allowed) -------------
__device__ float d_u[BATCH * IN_CAPS * CAPS_DIM];                 // 3 MB
__device__ float d_uhat[(size_t)BATCH * NUM_CAPS * IN_CAPS * CAPS_DIM]; // 569 MB
__device__ float d_bl[BATCH * OI];                                // 35.6 MB
__device__ float2 d_ms[BATCH * IN_CAPS];                          // softmax stats
__device__ float d_x[BATCH * NUM_CAPS * CAPS_DIM];                // 5.9 MB
__device__ int   d_idx[BATCH * KSEL];
__device__ float d_g[MLP_ROWS * CAPS_DIM];
__device__ float d_m0[MLP_ROWS * 1024];
__device__ float d_m1[MLP_ROWS * 1024];

__device__ __forceinline__ float gelu_f(float x) {
    return 0.5f * x * (1.0f + erff(x * 0.70710678118654752f));
}

// ---------------- 1) fused conv stack + primary caps + squash ------------------
__global__ void conv_stack_kernel(const float* __restrict__ scm,
                                  const float* __restrict__ w1, const float* __restrict__ b1,
                                  const float* __restrict__ w2, const float* __restrict__ b2,
                                  const float* __restrict__ w3, const float* __restrict__ b3,
                                  const float* __restrict__ pw, const float* __restrict__ pb) {
    __shared__ float A[4608];   // in(192) -> h2(128*36) -> u(1536)
    __shared__ float Bf[6400];  // h1(64*49) -> h3(256*25)
    const int b = blockIdx.x, t = threadIdx.x;

    const float* in = scm + b * 192;
    for (int i = t; i < 192; i += 256) A[i] = in[i];
    __syncthreads();

    // conv1: 3x8x8 -> 64x7x7 (Bf)
    for (int idx = t; idx < 64 * 49; idx += 256) {
        int oc = idx / 49, r = idx % 49, y = r / 7, x = r % 7;
        float acc = b1[oc];
        const float* wp = w1 + oc * 12;
        #pragma unroll
        for (int ic = 0; ic < 3; ic++) {
            const float* ip = A + ic * 64 + y * 8 + x;
            acc += ip[0]*wp[0] + ip[1]*wp[1] + ip[8]*wp[2] + ip[9]*wp[3];
            wp += 4;
        }
        Bf[idx] = gelu_f(acc);
    }
    __syncthreads();

    // conv2: 64x7x7 -> 128x6x6 (A)
    for (int idx = t; idx < 128 * 36; idx += 256) {
        int oc = idx / 36, r = idx % 36, y = r / 6, x = r % 6;
        float acc = b2[oc];
        const float* wp = w2 + oc * 256;
        const float* base = Bf + y * 7 + x;
        for (int ic = 0; ic < 64; ic++) {
            const float* ip = base + ic * 49;
            acc += ip[0]*wp[0] + ip[1]*wp[1] + ip[7]*wp[2] + ip[8]*wp[3];
            wp += 4;
        }
        A[idx] = gelu_f(acc);
    }
    __syncthreads();

    // conv3: 128x6x6 -> 256x5x5 (Bf)
    for (int idx = t; idx < 256 * 25; idx += 256) {
        int oc = idx / 25, r = idx % 25, y = r / 5, x = r % 5;
        float acc = b3[oc];
        const float* wp = w3 + oc * 512;
        const float* base = A + y * 6 + x;
        for (int ic = 0; ic < 128; ic++) {
            const float* ip = base + ic * 36;
            acc += ip[0]*wp[0] + ip[1]*wp[1] + ip[6]*wp[2] + ip[7]*wp[3];
            wp += 4;
        }
        Bf[idx] = gelu_f(acc);
    }
    __syncthreads();

    // primary caps: 256x5x5 -> 96x4x4 (A[0..1535]); no activation
    for (int idx = t; idx < 96 * 16; idx += 256) {
        int g = idx / 16, r = idx % 16, y = r / 4, x = r % 4;
        float acc = pb[g];
        const float* wp = pw + g * 1024;
        const float* base = Bf + y * 5 + x;
        for (int ic = 0; ic < 256; ic++) {
            const float* ip = base + ic * 25;
            acc += ip[0]*wp[0] + ip[1]*wp[1] + ip[5]*wp[2] + ip[6]*wp[3];
            wp += 4;
        }
        A[idx] = acc;
    }
    __syncthreads();

    // squash per capsule, store u
    if (t < 96) {
        float n2 = 0.f;
        #pragma unroll
        for (int d = 0; d < 16; d++) { float v = A[t * 16 + d]; n2 += v * v; }
        float n = sqrtf(n2);
        float sc = (1.0f - expf(-n)) / (n + 1e-8f);
        #pragma unroll
        for (int d = 0; d < 16; d++)
            d_u[b * 1536 + t * 16 + d] = A[t * 16 + d] * sc;
    }
}

// ---------------- 2) u_hat = einsum('oidk,bik->boid') --------------------------
__global__ void uhat_kernel(const float* __restrict__ capsW) {
    const int o = blockIdx.y, ic0 = blockIdx.x * 16;
    const int t = threadIdx.x, il = t >> 4, d = t & 15;
    float wr[16];
    const float* wp = capsW + (((size_t)o * 96 + ic0 + il) * 16 + d) * 16;
    #pragma unroll
    for (int k = 0; k < 16; k++) wr[k] = wp[k];

    __shared__ float us[4 * 256];
    for (int b0 = 0; b0 < BATCH; b0 += 4) {
        #pragma unroll
        for (int j = t; j < 1024; j += 256) {
            int bb = j >> 8, e = j & 255;
            us[j] = d_u[(b0 + bb) * 1536 + ic0 * 16 + e];
        }
        __syncthreads();
        #pragma unroll
        for (int bb = 0; bb < 4; bb++) {
            const float* ur = us + bb * 256 + il * 16;
            float acc = 0.f;
            #pragma unroll
            for (int k = 0; k < 16; k++) acc += wr[k] * ur[k];
            d_uhat[((size_t)(b0 + bb) * NUM_CAPS + o) * UHAT_TILE + ic0 * 16 + t] = acc;
        }
        __syncthreads();
    }
}

// ---------------- 3) routing ---------------------------------------------------
__global__ void initbl_kernel(const float* __restrict__ caps_b) {
    int i = blockIdx.x * 256 + threadIdx.x;
    if (i < BATCH * OI) d_bl[i] = caps_b[i % OI];
}

// softmax stats over out-caps axis: m and 1/sum per (b, i). Block per b,
// coalesced load into padded smem [o][i], warp-per-i reduction.
__global__ void softmax3_kernel() {
    extern __shared__ float sb[];            // 181*97 floats
    const int b = blockIdx.x, t = threadIdx.x;
    const float* blp = d_bl + (size_t)b * OI;
    for (int e = t; e < OI; e += 256) sb[(e / 96) * 97 + (e % 96)] = blp[e];
    __syncthreads();
    const int wid = t >> 5, lane = t & 31;
    for (int i = wid; i < 96; i += 8) {
        float m = -1e30f;
        for (int o = lane; o < NUM_CAPS; o += 32) m = fmaxf(m, sb[o * 97 + i]);
        #pragma unroll
        for (int s = 16; s; s >>= 1) m = fmaxf(m, __shfl_xor_sync(0xffffffffu, m, s));
        float s = 0.f;
        for (int o = lane; o < NUM_CAPS; o += 32) s += expf(sb[o * 97 + i] - m);
        #pragma unroll
        for (int sh = 16; sh; sh >>= 1) s += __shfl_xor_sync(0xffffffffu, s, sh);
        if (lane == 0) d_ms[b * 96 + i] = make_float2(m, 1.0f / s);
    }
}

// warp-per-(b,o) routing step, float4 everywhere.
// Element layout inside a float4 (lane l, iter j): i = j*8 + (l>>2),
// d = (l&3)*4 + component. c reconstructed from bl + softmax stats (3 exps).
template<bool LAST>
__global__ __launch_bounds__(256) void route3_kernel() {
    __shared__ float incsh[8][96];
    const int wid = threadIdx.x >> 5, lane = threadIdx.x & 31;
    const int w = blockIdx.x * 8 + wid;            // w = b*181 + o, exact grid
    const int b = w / NUM_CAPS;
    const float4* up = (const float4*)(d_uhat + (size_t)w * UHAT_TILE);
    float* blp = d_bl + (size_t)w * 96;

    float bl0 = blp[lane], bl1 = blp[32 + lane], bl2 = blp[64 + lane];
    const float2* msp = d_ms + b * 96;
    float2 ms0 = msp[lane], ms1 = msp[32 + lane], ms2 = msp[64 + lane];
    float c0 = expf(bl0 - ms0.x) * ms0.y;
    float c1 = expf(bl1 - ms1.x) * ms1.y;
    float c2 = expf(bl2 - ms2.x) * ms2.y;

    float4 uv[12];
    float4 acc = make_float4(0.f, 0.f, 0.f, 0.f);
    #pragma unroll
    for (int j = 0; j < 12; j++) {
        uv[j] = up[j * 32 + lane];
        float cr = (j < 4) ? c0 : (j < 8) ? c1 : c2;
        float cv = __shfl_sync(0xffffffffu, cr, ((j & 3) << 3) + (lane >> 2));
        acc.x += cv * uv[j].x; acc.y += cv * uv[j].y;
        acc.z += cv * uv[j].z; acc.w += cv * uv[j].w;
    }
    // reduce over i-partials (lanes differing in bits 2..4)
    #pragma unroll
    for (int m = 4; m <= 16; m <<= 1) {
        acc.x += __shfl_xor_sync(0xffffffffu, acc.x, m);
        acc.y += __shfl_xor_sync(0xffffffffu, acc.y, m);
        acc.z += __shfl_xor_sync(0xffffffffu, acc.z, m);
        acc.w += __shfl_xor_sync(0xffffffffu, acc.w, m);
    }
    // ||s||^2: partial over this lane's 4 d's, then across the 4 d-groups
    float sq = acc.x*acc.x + acc.y*acc.y + acc.z*acc.z + acc.w*acc.w;
    sq += __shfl_xor_sync(0xffffffffu, sq, 1);
    sq += __shfl_xor_sync(0xffffffffu, sq, 2);
    float n = sqrtf(sq);
    float sc = (1.0f - expf(-n)) / (n + 1e-8f);
    acc.x *= sc; acc.y *= sc; acc.z *= sc; acc.w *= sc;

    if (LAST) {
        if (lane < 4) ((float4*)(d_x + (size_t)w * 16))[lane] = acc;
    } else {
        #pragma unroll
        for (int j = 0; j < 12; j++) {
            float p = acc.x*uv[j].x + acc.y*uv[j].y + acc.z*uv[j].z + acc.w*uv[j].w;
            p += __shfl_xor_sync(0xffffffffu, p, 1);
            p += __shfl_xor_sync(0xffffffffu, p, 2);
            if ((lane & 3) == 0) incsh[wid][j * 8 + (lane >> 2)] = p;
        }
        __syncwarp();
        blp[lane]      = bl0 + incsh[wid][lane];
        blp[32 + lane] = bl1 + incsh[wid][32 + lane];
        blp[64 + lane] = bl2 + incsh[wid][64 + lane];
    }
}

// ---------------- 4) length, peaks, top-K, gather ------------------------------
__global__ void finalize_kernel(float* __restrict__ outL) {
    const int b = blockIdx.x, t = threadIdx.x; // 256 threads
    __shared__ float len[192], lnN[192], pk[192], red[256];
    float L = 0.f;
    if (t < NUM_CAPS) {
        const float* xp = d_x + ((size_t)b * NUM_CAPS + t) * 16;
        float n2 = 0.f;
        #pragma unroll
        for (int d = 0; d < 16; d++) { float v = xp[d]; n2 += v * v; }
        L = sqrtf(n2);
        len[t] = L;
    }
    red[t] = (t < NUM_CAPS) ? L : 0.f;
    __syncthreads();
    for (int s = 128; s > 0; s >>= 1) {
        if (t < s) red[t] += red[t + s];
        __syncthreads();
    }
    float tot = red[0];
    if (t < NUM_CAPS) {
        float ln = len[t] / (tot + 1e-8f);
        lnN[t] = ln;
        outL[b * NUM_CAPS + t] = ln;
    }
    __syncthreads();
    if (t < NUM_CAPS) {
        int lo = t - 5 > 0 ? t - 5 : 0;
        int hi = t + 5 < 180 ? t + 5 : 180;
        float m = -1e30f;
        for (int o = lo; o <= hi; o++) m = fmaxf(m, lnN[o]);
        pk[t] = (lnN[t] == m) ? lnN[t] : 0.f;
    }
    __syncthreads();
    if (t == 0) {
        int sel[KSEL];
        for (int k = 0; k < KSEL; k++) {
            int best = -1; float bv = -1e30f;
            for (int o = 0; o < NUM_CAPS; o++)
                if (pk[o] > bv) { bv = pk[o]; best = o; }  // strict > => ties -> lowest idx
            sel[k] = best;
            pk[best] = -1e30f;
        }
        for (int a = 1; a < KSEL; a++) {
            int v = sel[a], j = a - 1;
            while (j >= 0 && sel[j] > v) { sel[j + 1] = sel[j]; j--; }
            sel[j + 1] = v;
        }
        for (int k = 0; k < KSEL; k++) {
            d_idx[b * KSEL + k] = sel[k];
            const float* xp = d_x + ((size_t)b * NUM_CAPS + sel[k]) * 16;
            float* gp = d_g + (b * KSEL + k) * 16;
            for (int d = 0; d < 16; d++) gp[d] = xp[d];
        }
    }
}

// ---------------- 5) MLP -------------------------------------------------------
__global__ void fc1_kernel(const float* __restrict__ w, const float* __restrict__ bias) {
    const int r = blockIdx.y;
    const int j = blockIdx.x * 256 + threadIdx.x;  // < 1024
    __shared__ float gr[16];
    __shared__ int base;
    if (threadIdx.x < 16) gr[threadIdx.x] = d_g[r * 16 + threadIdx.x];
    if (threadIdx.x == 0) base = d_idx[r] * 16;
    __syncthreads();
    float acc = bias[j];
    #pragma unroll
    for (int d = 0; d < 16; d++) acc += gr[d] * w[(size_t)(base + d) * 1024 + j];
    d_m0[r * 1024 + j] = gelu_f(acc);
}

// tiled fp32 GEMM with float4 smem fragments: C = act(A @ W + bias). 64x64 tiles.
__global__ void gemm_kernel(int asel, int csel, const float* __restrict__ W,
                            const float* __restrict__ bias, float* cout,
                            int Kd, int N, int act, int transOut) {
    const float* A = (asel == 0) ? d_m0 : d_m1;
    float* C = (csel == 0) ? d_m0 : (csel == 1) ? d_m1 : cout;
    __shared__ float As[16][64];
    __shared__ float Ws[16][68];
    const int bm = blockIdx.y * 64, bn = blockIdx.x * 64;
    const int t = threadIdx.x, tx = t & 15, ty = t >> 4;
    float acc[4][4];
    #pragma unroll
    for (int p = 0; p < 4; p++)
        #pragma unroll
        for (int q = 0; q < 4; q++) acc[p][q] = 0.f;

    for (int k0 = 0; k0 < Kd; k0 += 16) {
        {   // A tile: 64 rows x 16 k, float4 loads, transposed scalar stores
            int r = t >> 2, cq = (t & 3) * 4;
            float4 a = *(const float4*)&A[(size_t)(bm + r) * Kd + k0 + cq];
            As[cq + 0][r] = a.x; As[cq + 1][r] = a.y;
            As[cq + 2][r] = a.z; As[cq + 3][r] = a.w;
        }
        {   // W tile: 16 rows x 64 n, float4 loads + stores
            int r = t >> 4, c4 = (t & 15) * 4;
            *(float4*)&Ws[r][c4] = *(const float4*)&W[(size_t)(k0 + r) * N + bn + c4];
        }
        __syncthreads();
        #pragma unroll
        for (int kk = 0; kk < 16; kk++) {
            float4 a4 = *(const float4*)&As[kk][ty * 4];
            float4 b4 = *(const float4*)&Ws[kk][tx * 4];
            float a[4] = {a4.x, a4.y, a4.z, a4.w};
            float bb[4] = {b4.x, b4.y, b4.z, b4.w};
            #pragma unroll
            for (int p = 0; p < 4; p++)
                #pragma unroll
                for (int q = 0; q < 4; q++) acc[p][q] += a[p] * bb[q];
        }
        __syncthreads();
    }
    #pragma unroll
    for (int p = 0; p < 4; p++) {
        #pragma unroll
        for (int q = 0; q < 4; q++) {
            int m = bm + ty * 4 + p, n = bn + tx * 4 + q;
            float v = acc[p][q] + bias[n];
            if (act) v = gelu_f(v);
            if (!transOut) C[(size_t)m * N + n] = v;
            else C[(size_t)(m >> 2) * (N * 4) + n * 4 + (m & 3)] = v; // [b, 2A, K]
        }
    }
}

// ---------------- launch -------------------------------------------------------
extern "C" void kernel_launch(void* const* d_in, const int* in_sizes, int n_in,
                              void* d_out, int out_size) {
    const float* scm  = (const float*)d_in[0];
    const float* c1w = (const float*)d_in[2];  const float* c1b = (const float*)d_in[3];
    const float* c2w = (const float*)d_in[4];  const float* c2b = (const float*)d_in[5];
    const float* c3w = (const float*)d_in[6];  const float* c3b = (const float*)d_in[7];
    const float* pcw = (const float*)d_in[8];  const float* pcb = (const float*)d_in[9];
    const float* capsW = (const float*)d_in[10];
    const float* capsb = (const float*)d_in[11];
    const float* f1w = (const float*)d_in[12]; const float* f1b = (const float*)d_in[13];
    const float* f2w = (const float*)d_in[14]; const float* f2b = (const float*)d_in[15];
    const float* f3w = (const float*)d_in[16]; const float* f3b = (const float*)d_in[17];
    const float* f4w = (const float*)d_in[18]; const float* f4b = (const float*)d_in[19];
    const float* f5w = (const float*)d_in[20]; const float* f5b = (const float*)d_in[21];
    const float* hw  = (const float*)d_in[22]; const float* hb  = (const float*)d_in[23];

    float* outW = (float*)d_out;                       // [512, 128, 4]
    float* outL = outW + BATCH * 128 * KSEL;           // [512, 181]

    static int smem_set = 0;
    const int smax_smem = (NUM_CAPS * 97) * sizeof(float);  // ~70.2 KB
    if (!smem_set) {
        cudaFuncSetAttribute(softmax3_kernel,
                             cudaFuncAttributeMaxDynamicSharedMemorySize, smax_smem);
        smem_set = 1;
    }

    conv_stack_kernel<<<BATCH, 256>>>(scm, c1w, c1b, c2w, c2b, c3w, c3b, pcw, pcb);
    uhat_kernel<<<dim3(6, NUM_CAPS), 256>>>(capsW);
    initbl_kernel<<<(BATCH * OI + 255) / 256, 256>>>(capsb);

    softmax3_kernel<<<BATCH, 256, smax_smem>>>();
    route3_kernel<false><<<BATCH * NUM_CAPS / 8, 256>>>();
    softmax3_kernel<<<BATCH, 256, smax_smem>>>();
    route3_kernel<false><<<BATCH * NUM_CAPS / 8, 256>>>();
    softmax3_kernel<<<BATCH, 256, smax_smem>>>();
    route3_kernel<true><<<BATCH * NUM_CAPS / 8, 256>>>();

    finalize_kernel<<<BATCH, 256>>>(outL);
    fc1_kernel<<<dim3(4, MLP_ROWS), 256>>>(f1w, f1b);
    gemm_kernel<<<dim3(12, 32), 256>>>(0, 1, f2w, f2b, nullptr, 1024, 768, 1, 0);
    gemm_kernel<<<dim3( 8, 32), 256>>>(1, 0, f3w, f3b, nullptr,  768, 512, 1, 0);
    gemm_kernel<<<dim3( 8, 32), 256>>>(0, 1, f4w, f4b, nullptr,  512, 512, 1, 0);
    gemm_kernel<<<dim3( 4, 32), 256>>>(1, 0, f5w, f5b, nullptr,  512, 256, 1, 0);
    gemm_kernel<<<dim3( 2, 32), 256>>>(0, 2, hw,  hb,  outW,     256, 128, 0, 1);
}

// round 4
// speedup vs baseline: 2.2277x; 1.6803x over previous
#include <cuda_runtime.h>
#include <cuda_bf16.h>
#include <math.h>

#define BATCH 512
#define NUM_CAPS 181
#define IN_CAPS 96
#define CAPS_DIM 16
#define KSEL 4
#define OI (NUM_CAPS * IN_CAPS)          // 17376
#define UHAT_TILE (IN_CAPS * CAPS_DIM)   // 1536
#define MLP_ROWS (BATCH * KSEL)          // 2048

// ---------------- scratch (device globals; no allocation allowed) -------------
__device__ float d_u[BATCH * IN_CAPS * CAPS_DIM];                 // 3 MB
__device__ float d_uhat[(size_t)BATCH * NUM_CAPS * IN_CAPS * CAPS_DIM]; // 569 MB
__device__ float d_bl[BATCH * OI];                                // 35.6 MB
__device__ float2 d_ms[BATCH * IN_CAPS];                          // softmax stats
__device__ float d_x[BATCH * NUM_CAPS * CAPS_DIM];                // 5.9 MB
__device__ int   d_idx[BATCH * KSEL];
__device__ float d_g[MLP_ROWS * CAPS_DIM];
__device__ float d_m0[MLP_ROWS * 1024];
__device__ float d_m1[MLP_ROWS * 1024];

__device__ __forceinline__ float gelu_f(float x) {
    return 0.5f * x * (1.0f + erff(x * 0.70710678118654752f));
}

// ---------------- 1) fused conv stack + primary caps + squash ------------------
// Register-tiled: thread owns one output channel + all its spatial outputs.
// Per input channel: 1 LDG.128 (2x2 weights) + rolling broadcast LDS rows.
__global__ __launch_bounds__(256) void conv_stack_kernel(
        const float* __restrict__ scm,
        const float* __restrict__ w1, const float* __restrict__ b1,
        const float* __restrict__ w2, const float* __restrict__ b2,
        const float* __restrict__ w3, const float* __restrict__ b3,
        const float* __restrict__ pw, const float* __restrict__ pb) {
    __shared__ float A[4608];   // in(192) -> h2(128*36) -> u(1536)
    __shared__ float Bf[6400];  // h1(64*49) -> h3(256*25)
    const int b = blockIdx.x, t = threadIdx.x;

    const float* in = scm + b * 192;
    for (int i = t; i < 192; i += 256) A[i] = in[i];
    __syncthreads();

    // conv1: 3x8x8 -> 64x7x7 (Bf). Small; simple per-output form.
    for (int idx = t; idx < 64 * 49; idx += 256) {
        int oc = idx / 49, r = idx % 49, y = r / 7, x = r % 7;
        float acc = b1[oc];
        const float* wp = w1 + oc * 12;
        #pragma unroll
        for (int ic = 0; ic < 3; ic++) {
            const float* ip = A + ic * 64 + y * 8 + x;
            acc += ip[0]*wp[0] + ip[1]*wp[1] + ip[8]*wp[2] + ip[9]*wp[3];
            wp += 4;
        }
        Bf[idx] = gelu_f(acc);
    }
    __syncthreads();

    // conv2: 64x7x7 (Bf) -> 128x6x6 (A). t -> (oc = t&127, row-half)
    {
        const int oc = t & 127, half = t >> 7, y0 = half * 3;
        float acc[18];
        #pragma unroll
        for (int p = 0; p < 18; p++) acc[p] = 0.f;
        for (int ic = 0; ic < 64; ic++) {
            float4 w = *(const float4*)(w2 + oc * 256 + ic * 4);
            const float* ip = Bf + ic * 49 + y0 * 7;
            float r0[7], r1[7];
            #pragma unroll
            for (int x = 0; x < 7; x++) r0[x] = ip[x];
            #pragma unroll
            for (int yy = 0; yy < 3; yy++) {
                #pragma unroll
                for (int x = 0; x < 7; x++) r1[x] = ip[(yy + 1) * 7 + x];
                #pragma unroll
                for (int x = 0; x < 6; x++)
                    acc[yy*6+x] += r0[x]*w.x + r0[x+1]*w.y + r1[x]*w.z + r1[x+1]*w.w;
                #pragma unroll
                for (int x = 0; x < 7; x++) r0[x] = r1[x];
            }
        }
        float bb = b2[oc];
        __syncthreads();   // conv1 consumers of A done; safe to overwrite
        #pragma unroll
        for (int yy = 0; yy < 3; yy++)
            #pragma unroll
            for (int x = 0; x < 6; x++)
                A[oc * 36 + (y0 + yy) * 6 + x] = gelu_f(acc[yy*6+x] + bb);
    }
    __syncthreads();

    // conv3: 128x6x6 (A) -> 256x5x5 (Bf). t -> oc
    {
        const int oc = t;
        float acc[25];
        #pragma unroll
        for (int p = 0; p < 25; p++) acc[p] = 0.f;
        for (int ic = 0; ic < 128; ic++) {
            float4 w = *(const float4*)(w3 + oc * 512 + ic * 4);
            const float* ip = A + ic * 36;
            float r0[6], r1[6];
            #pragma unroll
            for (int x = 0; x < 6; x++) r0[x] = ip[x];
            #pragma unroll
            for (int yy = 0; yy < 5; yy++) {
                #pragma unroll
                for (int x = 0; x < 6; x++) r1[x] = ip[(yy + 1) * 6 + x];
                #pragma unroll
                for (int x = 0; x < 5; x++)
                    acc[yy*5+x] += r0[x]*w.x + r0[x+1]*w.y + r1[x]*w.z + r1[x+1]*w.w;
                #pragma unroll
                for (int x = 0; x < 6; x++) r0[x] = r1[x];
            }
        }
        float bb = b3[oc];
        __syncthreads();
        #pragma unroll
        for (int p = 0; p < 25; p++) Bf[oc * 25 + p] = gelu_f(acc[p] + bb);
    }
    __syncthreads();

    // primary caps: 256x5x5 (Bf) -> 96x4x4 (A), no activation. t<192 active.
    if (t < 192) {
        const int g = t >> 1, half = t & 1, y0 = half * 2;
        float acc[8];
        #pragma unroll
        for (int p = 0; p < 8; p++) acc[p] = 0.f;
        for (int ic = 0; ic < 256; ic++) {
            float4 w = *(const float4*)(pw + g * 1024 + ic * 4);
            const float* ip = Bf + ic * 25 + y0 * 5;
            float r0[5], r1[5];
            #pragma unroll
            for (int x = 0; x < 5; x++) r0[x] = ip[x];
            #pragma unroll
            for (int yy = 0; yy < 2; yy++) {
                #pragma unroll
                for (int x = 0; x < 5; x++) r1[x] = ip[(yy + 1) * 5 + x];
                #pragma unroll
                for (int x = 0; x < 4; x++)
                    acc[yy*4+x] += r0[x]*w.x + r0[x+1]*w.y + r1[x]*w.z + r1[x+1]*w.w;
                #pragma unroll
                for (int x = 0; x < 5; x++) r0[x] = r1[x];
            }
        }
        float bb = pb[g];
        #pragma unroll
        for (int yy = 0; yy < 2; yy++)
            #pragma unroll
            for (int x = 0; x < 4; x++)
                A[g * 16 + (y0 + yy) * 4 + x] = acc[yy*4+x] + bb;
    }
    __syncthreads();

    // squash per capsule, store u
    if (t < 96) {
        float n2 = 0.f;
        #pragma unroll
        for (int d = 0; d < 16; d++) { float v = A[t * 16 + d]; n2 += v * v; }
        float n = sqrtf(n2);
        float sc = (1.0f - expf(-n)) / (n + 1e-8f);
        #pragma unroll
        for (int d = 0; d < 16; d++)
            d_u[b * 1536 + t * 16 + d] = A[t * 16 + d] * sc;
    }
}

// ---------------- 2) u_hat = einsum('oidk,bik->boid') --------------------------
__global__ void uhat_kernel(const float* __restrict__ capsW) {
    const int o = blockIdx.y, ic0 = blockIdx.x * 16;
    const int t = threadIdx.x, il = t >> 4, d = t & 15;
    float wr[16];
    const float* wp = capsW + (((size_t)o * 96 + ic0 + il) * 16 + d) * 16;
    #pragma unroll
    for (int k = 0; k < 16; k++) wr[k] = wp[k];

    __shared__ float us[4 * 256];
    for (int b0 = 0; b0 < BATCH; b0 += 4) {
        #pragma unroll
        for (int j = t; j < 1024; j += 256) {
            int bb = j >> 8, e = j & 255;
            us[j] = d_u[(b0 + bb) * 1536 + ic0 * 16 + e];
        }
        __syncthreads();
        #pragma unroll
        for (int bb = 0; bb < 4; bb++) {
            const float* ur = us + bb * 256 + il * 16;
            float acc = 0.f;
            #pragma unroll
            for (int k = 0; k < 16; k++) acc += wr[k] * ur[k];
            d_uhat[((size_t)(b0 + bb) * NUM_CAPS + o) * UHAT_TILE + ic0 * 16 + t] = acc;
        }
        __syncthreads();
    }
}

// ---------------- 3) routing ---------------------------------------------------
// iteration-1 logits are caps_b broadcast over b -> b-independent stats, 1 block.
__global__ void softmax_first_kernel(const float* __restrict__ caps_b) {
    extern __shared__ float sb[];            // 181*97 floats
    const int t = threadIdx.x;
    for (int e = t; e < OI; e += 256) sb[(e / 96) * 97 + (e % 96)] = caps_b[e];
    __syncthreads();
    const int wid = t >> 5, lane = t & 31;
    for (int i = wid; i < 96; i += 8) {
        float m = -1e30f;
        for (int o = lane; o < NUM_CAPS; o += 32) m = fmaxf(m, sb[o * 97 + i]);
        #pragma unroll
        for (int s = 16; s; s >>= 1) m = fmaxf(m, __shfl_xor_sync(0xffffffffu, m, s));
        float s = 0.f;
        for (int o = lane; o < NUM_CAPS; o += 32) s += expf(sb[o * 97 + i] - m);
        #pragma unroll
        for (int sh = 16; sh; sh >>= 1) s += __shfl_xor_sync(0xffffffffu, s, sh);
        if (lane == 0) d_ms[i] = make_float2(m, 1.0f / s);
    }
}

__global__ void softmax3_kernel() {
    extern __shared__ float sb[];            // 181*97 floats
    const int b = blockIdx.x, t = threadIdx.x;
    const float* blp = d_bl + (size_t)b * OI;
    for (int e = t; e < OI; e += 256) sb[(e / 96) * 97 + (e % 96)] = blp[e];
    __syncthreads();
    const int wid = t >> 5, lane = t & 31;
    for (int i = wid; i < 96; i += 8) {
        float m = -1e30f;
        for (int o = lane; o < NUM_CAPS; o += 32) m = fmaxf(m, sb[o * 97 + i]);
        #pragma unroll
        for (int s = 16; s; s >>= 1) m = fmaxf(m, __shfl_xor_sync(0xffffffffu, m, s));
        float s = 0.f;
        for (int o = lane; o < NUM_CAPS; o += 32) s += expf(sb[o * 97 + i] - m);
        #pragma unroll
        for (int sh = 16; sh; sh >>= 1) s += __shfl_xor_sync(0xffffffffu, s, sh);
        if (lane == 0) d_ms[b * 96 + i] = make_float2(m, 1.0f / s);
    }
}

// warp-per-(b,o) routing step, float4 everywhere.
// FIRST: logits come from caps_b (b-independent), stats from d_ms[0..95].
template<bool FIRST, bool LAST>
__global__ __launch_bounds__(256) void route3_kernel(const float* __restrict__ caps_b) {
    __shared__ float incsh[8][96];
    const int wid = threadIdx.x >> 5, lane = threadIdx.x & 31;
    const int w = blockIdx.x * 8 + wid;            // w = b*181 + o, exact grid
    const int b = w / NUM_CAPS;
    const float4* up = (const float4*)(d_uhat + (size_t)w * UHAT_TILE);
    float* blp = d_bl + (size_t)w * 96;

    float bl0, bl1, bl2;
    if (FIRST) {
        const int o = w - b * NUM_CAPS;
        const float* cbp = caps_b + o * 96;
        bl0 = cbp[lane]; bl1 = cbp[32 + lane]; bl2 = cbp[64 + lane];
    } else {
        bl0 = blp[lane]; bl1 = blp[32 + lane]; bl2 = blp[64 + lane];
    }
    const float2* msp = FIRST ? d_ms : (d_ms + b * 96);
    float2 ms0 = msp[lane], ms1 = msp[32 + lane], ms2 = msp[64 + lane];
    float c0 = expf(bl0 - ms0.x) * ms0.y;
    float c1 = expf(bl1 - ms1.x) * ms1.y;
    float c2 = expf(bl2 - ms2.x) * ms2.y;

    float4 uv[12];
    float4 acc = make_float4(0.f, 0.f, 0.f, 0.f);
    #pragma unroll
    for (int j = 0; j < 12; j++) {
        uv[j] = up[j * 32 + lane];
        float cr = (j < 4) ? c0 : (j < 8) ? c1 : c2;
        float cv = __shfl_sync(0xffffffffu, cr, ((j & 3) << 3) + (lane >> 2));
        acc.x += cv * uv[j].x; acc.y += cv * uv[j].y;
        acc.z += cv * uv[j].z; acc.w += cv * uv[j].w;
    }
    #pragma unroll
    for (int m = 4; m <= 16; m <<= 1) {
        acc.x += __shfl_xor_sync(0xffffffffu, acc.x, m);
        acc.y += __shfl_xor_sync(0xffffffffu, acc.y, m);
        acc.z += __shfl_xor_sync(0xffffffffu, acc.z, m);
        acc.w += __shfl_xor_sync(0xffffffffu, acc.w, m);
    }
    float sq = acc.x*acc.x + acc.y*acc.y + acc.z*acc.z + acc.w*acc.w;
    sq += __shfl_xor_sync(0xffffffffu, sq, 1);
    sq += __shfl_xor_sync(0xffffffffu, sq, 2);
    float n = sqrtf(sq);
    float sc = (1.0f - expf(-n)) / (n + 1e-8f);
    acc.x *= sc; acc.y *= sc; acc.z *= sc; acc.w *= sc;

    if (LAST) {
        if (lane < 4) ((float4*)(d_x + (size_t)w * 16))[lane] = acc;
    } else {
        #pragma unroll
        for (int j = 0; j < 12; j++) {
            float p = acc.x*uv[j].x + acc.y*uv[j].y + acc.z*uv[j].z + acc.w*uv[j].w;
            p += __shfl_xor_sync(0xffffffffu, p, 1);
            p += __shfl_xor_sync(0xffffffffu, p, 2);
            if ((lane & 3) == 0) incsh[wid][j * 8 + (lane >> 2)] = p;
        }
        __syncwarp();
        blp[lane]      = bl0 + incsh[wid][lane];
        blp[32 + lane] = bl1 + incsh[wid][32 + lane];
        blp[64 + lane] = bl2 + incsh[wid][64 + lane];
    }
}

// ---------------- 4) length, peaks, top-K, gather ------------------------------
__global__ void finalize_kernel(float* __restrict__ outL) {
    const int b = blockIdx.x, t = threadIdx.x; // 256 threads
    __shared__ float len[192], lnN[192], pk[192], red[256];
    float L = 0.f;
    if (t < NUM_CAPS) {
        const float* xp = d_x + ((size_t)b * NUM_CAPS + t) * 16;
        float n2 = 0.f;
        #pragma unroll
        for (int d = 0; d < 16; d++) { float v = xp[d]; n2 += v * v; }
        L = sqrtf(n2);
        len[t] = L;
    }
    red[t] = (t < NUM_CAPS) ? L : 0.f;
    __syncthreads();
    for (int s = 128; s > 0; s >>= 1) {
        if (t < s) red[t] += red[t + s];
        __syncthreads();
    }
    float tot = red[0];
    if (t < NUM_CAPS) {
        float ln = len[t] / (tot + 1e-8f);
        lnN[t] = ln;
        outL[b * NUM_CAPS + t] = ln;
    }
    __syncthreads();
    if (t < NUM_CAPS) {
        int lo = t - 5 > 0 ? t - 5 : 0;
        int hi = t + 5 < 180 ? t + 5 : 180;
        float m = -1e30f;
        for (int o = lo; o <= hi; o++) m = fmaxf(m, lnN[o]);
        pk[t] = (lnN[t] == m) ? lnN[t] : 0.f;
    }
    __syncthreads();
    if (t == 0) {
        int sel[KSEL];
        for (int k = 0; k < KSEL; k++) {
            int best = -1; float bv = -1e30f;
            for (int o = 0; o < NUM_CAPS; o++)
                if (pk[o] > bv) { bv = pk[o]; best = o; }
            sel[k] = best;
            pk[best] = -1e30f;
        }
        for (int a = 1; a < KSEL; a++) {
            int v = sel[a], j = a - 1;
            while (j >= 0 && sel[j] > v) { sel[j + 1] = sel[j]; j--; }
            sel[j + 1] = v;
        }
        for (int k = 0; k < KSEL; k++) {
            d_idx[b * KSEL + k] = sel[k];
            const float* xp = d_x + ((size_t)b * NUM_CAPS + sel[k]) * 16;
            float* gp = d_g + (b * KSEL + k) * 16;
            for (int d = 0; d < 16; d++) gp[d] = xp[d];
        }
    }
}

// ---------------- 5) MLP -------------------------------------------------------
__global__ void fc1_kernel(const float* __restrict__ w, const float* __restrict__ bias) {
    const int r = blockIdx.y;
    const int j = blockIdx.x * 256 + threadIdx.x;  // < 1024
    __shared__ float gr[16];
    __shared__ int base;
    if (threadIdx.x < 16) gr[threadIdx.x] = d_g[r * 16 + threadIdx.x];
    if (threadIdx.x == 0) base = d_idx[r] * 16;
    __syncthreads();
    float acc = bias[j];
    #pragma unroll
    for (int d = 0; d < 16; d++) acc += gr[d] * w[(size_t)(base + d) * 1024 + j];
    d_m0[r * 1024 + j] = gelu_f(acc);
}

__global__ void gemm_kernel(int asel, int csel, const float* __restrict__ W,
                            const float* __restrict__ bias, float* cout,
                            int Kd, int N, int act, int transOut) {
    const float* A = (asel == 0) ? d_m0 : d_m1;
    float* C = (csel == 0) ? d_m0 : (csel == 1) ? d_m1 : cout;
    __shared__ float As[16][64];
    __shared__ float Ws[16][68];
    const int bm = blockIdx.y * 64, bn = blockIdx.x * 64;
    const int t = threadIdx.x, tx = t & 15, ty = t >> 4;
    float acc[4][4];
    #pragma unroll
    for (int p = 0; p < 4; p++)
        #pragma unroll
        for (int q = 0; q < 4; q++) acc[p][q] = 0.f;

    for (int k0 = 0; k0 < Kd; k0 += 16) {
        {
            int r = t >> 2, cq = (t & 3) * 4;
            float4 a = *(const float4*)&A[(size_t)(bm + r) * Kd + k0 + cq];
            As[cq + 0][r] = a.x; As[cq + 1][r] = a.y;
            As[cq + 2][r] = a.z; As[cq + 3][r] = a.w;
        }
        {
            int r = t >> 4, c4 = (t & 15) * 4;
            *(float4*)&Ws[r][c4] = *(const float4*)&W[(size_t)(k0 + r) * N + bn + c4];
        }
        __syncthreads();
        #pragma unroll
        for (int kk = 0; kk < 16; kk++) {
            float4 a4 = *(const float4*)&As[kk][ty * 4];
            float4 b4 = *(const float4*)&Ws[kk][tx * 4];
            float a[4] = {a4.x, a4.y, a4.z, a4.w};
            float bb[4] = {b4.x, b4.y, b4.z, b4.w};
            #pragma unroll
            for (int p = 0; p < 4; p++)
                #pragma unroll
                for (int q = 0; q < 4; q++) acc[p][q] += a[p] * bb[q];
        }
        __syncthreads();
    }
    #pragma unroll
    for (int p = 0; p < 4; p++) {
        #pragma unroll
        for (int q = 0; q < 4; q++) {
            int m = bm + ty * 4 + p, n = bn + tx * 4 + q;
            float v = acc[p][q] + bias[n];
            if (act) v = gelu_f(v);
            if (!transOut) C[(size_t)m * N + n] = v;
            else C[(size_t)(m >> 2) * (N * 4) + n * 4 + (m & 3)] = v;
        }
    }
}

// ---------------- launch -------------------------------------------------------
extern "C" void kernel_launch(void* const* d_in, const int* in_sizes, int n_in,
                              void* d_out, int out_size) {
    const float* scm  = (const float*)d_in[0];
    const float* c1w = (const float*)d_in[2];  const float* c1b = (const float*)d_in[3];
    const float* c2w = (const float*)d_in[4];  const float* c2b = (const float*)d_in[5];
    const float* c3w = (const float*)d_in[6];  const float* c3b = (const float*)d_in[7];
    const float* pcw = (const float*)d_in[8];  const float* pcb = (const float*)d_in[9];
    const float* capsW = (const float*)d_in[10];
    const float* capsb = (const float*)d_in[11];
    const float* f1w = (const float*)d_in[12]; const float* f1b = (const float*)d_in[13];
    const float* f2w = (const float*)d_in[14]; const float* f2b = (const float*)d_in[15];
    const float* f3w = (const float*)d_in[16]; const float* f3b = (const float*)d_in[17];
    const float* f4w = (const float*)d_in[18]; const float* f4b = (const float*)d_in[19];
    const float* f5w = (const float*)d_in[20]; const float* f5b = (const float*)d_in[21];
    const float* hw  = (const float*)d_in[22]; const float* hb  = (const float*)d_in[23];

    float* outW = (float*)d_out;                       // [512, 128, 4]
    float* outL = outW + BATCH * 128 * KSEL;           // [512, 181]

    static int smem_set = 0;
    const int smax_smem = (NUM_CAPS * 97) * sizeof(float);  // ~70.2 KB
    if (!smem_set) {
        cudaFuncSetAttribute(softmax3_kernel,
                             cudaFuncAttributeMaxDynamicSharedMemorySize, smax_smem);
        cudaFuncSetAttribute(softmax_first_kernel,
                             cudaFuncAttributeMaxDynamicSharedMemorySize, smax_smem);
        smem_set = 1;
    }

    const int route_grid = BATCH * NUM_CAPS / 8;

    conv_stack_kernel<<<BATCH, 256>>>(scm, c1w, c1b, c2w, c2b, c3w, c3b, pcw, pcb); // 1
    uhat_kernel<<<dim3(6, NUM_CAPS), 256>>>(capsW);                                  // 2
    softmax_first_kernel<<<1, 256, smax_smem>>>(capsb);                              // 3
    route3_kernel<true,  false><<<route_grid, 256>>>(capsb);                         // 4
    softmax3_kernel<<<BATCH, 256, smax_smem>>>();                                    // 5
    route3_kernel<false, false><<<route_grid, 256>>>(capsb);                         // 6 (ncu)
    softmax3_kernel<<<BATCH, 256, smax_smem>>>();                                    // 7
    route3_kernel<false, true ><<<route_grid, 256>>>(capsb);                         // 8

    finalize_kernel<<<BATCH, 256>>>(outL);
    fc1_kernel<<<dim3(4, MLP_ROWS), 256>>>(f1w, f1b);
    gemm_kernel<<<dim3(12, 32), 256>>>(0, 1, f2w, f2b, nullptr, 1024, 768, 1, 0);
    gemm_kernel<<<dim3( 8, 32), 256>>>(1, 0, f3w, f3b, nullptr,  768, 512, 1, 0);
    gemm_kernel<<<dim3( 8, 32), 256>>>(0, 1, f4w, f4b, nullptr,  512, 512, 1, 0);
    gemm_kernel<<<dim3( 4, 32), 256>>>(1, 0, f5w, f5b, nullptr,  512, 256, 1, 0);
    gemm_kernel<<<dim3( 2, 32), 256>>>(0, 2, hw,  hb,  outW,     256, 128, 0, 1);
}

// round 5
// speedup vs baseline: 2.4959x; 1.1204x over previous
#include <cuda_runtime.h>
#include <cuda_fp16.h>
#include <math.h>

#define BATCH 512
#define NUM_CAPS 181
#define IN_CAPS 96
#define CAPS_DIM 16
#define KSEL 4
#define OI (NUM_CAPS * IN_CAPS)          // 17376
#define UHAT_TILE (IN_CAPS * CAPS_DIM)   // 1536
#define MLP_ROWS (BATCH * KSEL)          // 2048

// ---------------- scratch (device globals; no allocation allowed) -------------
__device__ float  d_u[BATCH * IN_CAPS * CAPS_DIM];                 // 3 MB
__device__ __half d_uhat[(size_t)BATCH * NUM_CAPS * IN_CAPS * CAPS_DIM]; // 285 MB
__device__ float  d_bl[BATCH * OI];                                // 35.6 MB
__device__ float2 d_ms[BATCH * IN_CAPS];                           // softmax stats
__device__ float  d_x[BATCH * NUM_CAPS * CAPS_DIM];                // 5.9 MB
__device__ int    d_idx[BATCH * KSEL];
__device__ float  d_g[MLP_ROWS * CAPS_DIM];
__device__ float  d_m0[MLP_ROWS * 1024];
__device__ float  d_m1[MLP_ROWS * 1024];

__device__ __forceinline__ float gelu_f(float x) {
    return 0.5f * x * (1.0f + erff(x * 0.70710678118654752f));
}

// ---------------- 1) fused conv stack + primary caps + squash ------------------
__global__ __launch_bounds__(256) void conv_stack_kernel(
        const float* __restrict__ scm,
        const float* __restrict__ w1, const float* __restrict__ b1,
        const float* __restrict__ w2, const float* __restrict__ b2,
        const float* __restrict__ w3, const float* __restrict__ b3,
        const float* __restrict__ pw, const float* __restrict__ pb) {
    __shared__ float A[4608];   // in(192) -> h2(128*36) -> u(1536)
    __shared__ float Bf[6400];  // h1(64*49) -> h3(256*25)
    const int b = blockIdx.x, t = threadIdx.x;

    const float* in = scm + b * 192;
    for (int i = t; i < 192; i += 256) A[i] = in[i];
    __syncthreads();

    // conv1: 3x8x8 -> 64x7x7 (Bf)
    for (int idx = t; idx < 64 * 49; idx += 256) {
        int oc = idx / 49, r = idx % 49, y = r / 7, x = r % 7;
        float acc = b1[oc];
        const float* wp = w1 + oc * 12;
        #pragma unroll
        for (int ic = 0; ic < 3; ic++) {
            const float* ip = A + ic * 64 + y * 8 + x;
            acc += ip[0]*wp[0] + ip[1]*wp[1] + ip[8]*wp[2] + ip[9]*wp[3];
            wp += 4;
        }
        Bf[idx] = gelu_f(acc);
    }
    __syncthreads();

    // conv2: 64x7x7 (Bf) -> 128x6x6 (A)
    {
        const int oc = t & 127, half = t >> 7, y0 = half * 3;
        float acc[18];
        #pragma unroll
        for (int p = 0; p < 18; p++) acc[p] = 0.f;
        for (int ic = 0; ic < 64; ic++) {
            float4 w = *(const float4*)(w2 + oc * 256 + ic * 4);
            const float* ip = Bf + ic * 49 + y0 * 7;
            float r0[7], r1[7];
            #pragma unroll
            for (int x = 0; x < 7; x++) r0[x] = ip[x];
            #pragma unroll
            for (int yy = 0; yy < 3; yy++) {
                #pragma unroll
                for (int x = 0; x < 7; x++) r1[x] = ip[(yy + 1) * 7 + x];
                #pragma unroll
                for (int x = 0; x < 6; x++)
                    acc[yy*6+x] += r0[x]*w.x + r0[x+1]*w.y + r1[x]*w.z + r1[x+1]*w.w;
                #pragma unroll
                for (int x = 0; x < 7; x++) r0[x] = r1[x];
            }
        }
        float bb = b2[oc];
        __syncthreads();
        #pragma unroll
        for (int yy = 0; yy < 3; yy++)
            #pragma unroll
            for (int x = 0; x < 6; x++)
                A[oc * 36 + (y0 + yy) * 6 + x] = gelu_f(acc[yy*6+x] + bb);
    }
    __syncthreads();

    // conv3: 128x6x6 (A) -> 256x5x5 (Bf)
    {
        const int oc = t;
        float acc[25];
        #pragma unroll
        for (int p = 0; p < 25; p++) acc[p] = 0.f;
        for (int ic = 0; ic < 128; ic++) {
            float4 w = *(const float4*)(w3 + oc * 512 + ic * 4);
            const float* ip = A + ic * 36;
            float r0[6], r1[6];
            #pragma unroll
            for (int x = 0; x < 6; x++) r0[x] = ip[x];
            #pragma unroll
            for (int yy = 0; yy < 5; yy++) {
                #pragma unroll
                for (int x = 0; x < 6; x++) r1[x] = ip[(yy + 1) * 6 + x];
                #pragma unroll
                for (int x = 0; x < 5; x++)
                    acc[yy*5+x] += r0[x]*w.x + r0[x+1]*w.y + r1[x]*w.z + r1[x+1]*w.w;
                #pragma unroll
                for (int x = 0; x < 6; x++) r0[x] = r1[x];
            }
        }
        float bb = b3[oc];
        __syncthreads();
        #pragma unroll
        for (int p = 0; p < 25; p++) Bf[oc * 25 + p] = gelu_f(acc[p] + bb);
    }
    __syncthreads();

    // primary caps: 256x5x5 (Bf) -> 96x4x4 (A)
    if (t < 192) {
        const int g = t >> 1, half = t & 1, y0 = half * 2;
        float acc[8];
        #pragma unroll
        for (int p = 0; p < 8; p++) acc[p] = 0.f;
        for (int ic = 0; ic < 256; ic++) {
            float4 w = *(const float4*)(pw + g * 1024 + ic * 4);
            const float* ip = Bf + ic * 25 + y0 * 5;
            float r0[5], r1[5];
            #pragma unroll
            for (int x = 0; x < 5; x++) r0[x] = ip[x];
            #pragma unroll
            for (int yy = 0; yy < 2; yy++) {
                #pragma unroll
                for (int x = 0; x < 5; x++) r1[x] = ip[(yy + 1) * 5 + x];
                #pragma unroll
                for (int x = 0; x < 4; x++)
                    acc[yy*4+x] += r0[x]*w.x + r0[x+1]*w.y + r1[x]*w.z + r1[x+1]*w.w;
                #pragma unroll
                for (int x = 0; x < 5; x++) r0[x] = r1[x];
            }
        }
        float bb = pb[g];
        #pragma unroll
        for (int yy = 0; yy < 2; yy++)
            #pragma unroll
            for (int x = 0; x < 4; x++)
                A[g * 16 + (y0 + yy) * 4 + x] = acc[yy*4+x] + bb;
    }
    __syncthreads();

    if (t < 96) {
        float n2 = 0.f;
        #pragma unroll
        for (int d = 0; d < 16; d++) { float v = A[t * 16 + d]; n2 += v * v; }
        float n = sqrtf(n2);
        float sc = (1.0f - expf(-n)) / (n + 1e-8f);
        #pragma unroll
        for (int d = 0; d < 16; d++)
            d_u[b * 1536 + t * 16 + d] = A[t * 16 + d] * sc;
    }
}

// ---------------- 2) u_hat = einsum('oidk,bik->boid'), fp16 output -------------
__global__ void uhat_kernel(const float* __restrict__ capsW) {
    const int o = blockIdx.y, ic0 = blockIdx.x * 16;
    const int t = threadIdx.x, il = t >> 4, d = t & 15;
    float wr[16];
    const float* wp = capsW + (((size_t)o * 96 + ic0 + il) * 16 + d) * 16;
    #pragma unroll
    for (int k = 0; k < 16; k++) wr[k] = wp[k];

    __shared__ float us[4 * 256];
    for (int b0 = 0; b0 < BATCH; b0 += 4) {
        #pragma unroll
        for (int j = t; j < 1024; j += 256) {
            int bb = j >> 8, e = j & 255;
            us[j] = d_u[(b0 + bb) * 1536 + ic0 * 16 + e];
        }
        __syncthreads();
        #pragma unroll
        for (int bb = 0; bb < 4; bb++) {
            const float* ur = us + bb * 256 + il * 16;
            float acc = 0.f;
            #pragma unroll
            for (int k = 0; k < 16; k++) acc += wr[k] * ur[k];
            d_uhat[((size_t)(b0 + bb) * NUM_CAPS + o) * UHAT_TILE + ic0 * 16 + t] =
                __float2half(acc);
        }
        __syncthreads();
    }
}

// ---------------- 3) routing ---------------------------------------------------
__global__ void softmax_first_kernel(const float* __restrict__ caps_b) {
    extern __shared__ float sb[];            // 181*97 floats
    const int t = threadIdx.x;
    for (int e = t; e < OI; e += 256) sb[(e / 96) * 97 + (e % 96)] = caps_b[e];
    __syncthreads();
    const int wid = t >> 5, lane = t & 31;
    for (int i = wid; i < 96; i += 8) {
        float m = -1e30f;
        for (int o = lane; o < NUM_CAPS; o += 32) m = fmaxf(m, sb[o * 97 + i]);
        #pragma unroll
        for (int s = 16; s; s >>= 1) m = fmaxf(m, __shfl_xor_sync(0xffffffffu, m, s));
        float s = 0.f;
        for (int o = lane; o < NUM_CAPS; o += 32) s += expf(sb[o * 97 + i] - m);
        #pragma unroll
        for (int sh = 16; sh; sh >>= 1) s += __shfl_xor_sync(0xffffffffu, s, sh);
        if (lane == 0) d_ms[i] = make_float2(m, 1.0f / s);
    }
}

__global__ void softmax3_kernel() {
    extern __shared__ float sb[];            // 181*97 floats
    const int b = blockIdx.x, t = threadIdx.x;
    const float* blp = d_bl + (size_t)b * OI;
    for (int e = t; e < OI; e += 256) sb[(e / 96) * 97 + (e % 96)] = blp[e];
    __syncthreads();
    const int wid = t >> 5, lane = t & 31;
    for (int i = wid; i < 96; i += 8) {
        float m = -1e30f;
        for (int o = lane; o < NUM_CAPS; o += 32) m = fmaxf(m, sb[o * 97 + i]);
        #pragma unroll
        for (int s = 16; s; s >>= 1) m = fmaxf(m, __shfl_xor_sync(0xffffffffu, m, s));
        float s = 0.f;
        for (int o = lane; o < NUM_CAPS; o += 32) s += expf(sb[o * 97 + i] - m);
        #pragma unroll
        for (int sh = 16; sh; sh >>= 1) s += __shfl_xor_sync(0xffffffffu, s, sh);
        if (lane == 0) d_ms[b * 96 + i] = make_float2(m, 1.0f / s);
    }
}

// warp-per-(b,o) routing step on fp16 u_hat.
// Lane l, iter j (0..5) loads 8 halves: i = j*16 + (l>>1), d-half = l&1.
template<bool FIRST, bool LAST>
__global__ __launch_bounds__(256) void route4_kernel(const float* __restrict__ caps_b) {
    __shared__ float incsh[8][96];
    const int wid = threadIdx.x >> 5, lane = threadIdx.x & 31;
    const int w = blockIdx.x * 8 + wid;            // w = b*181 + o
    const int b = w / NUM_CAPS;
    const uint4* up = (const uint4*)(d_uhat + (size_t)w * UHAT_TILE);
    float* blp = d_bl + (size_t)w * 96;

    float bl0, bl1, bl2;
    if (FIRST) {
        const int o = w - b * NUM_CAPS;
        const float* cbp = caps_b + o * 96;
        bl0 = cbp[lane]; bl1 = cbp[32 + lane]; bl2 = cbp[64 + lane];
    } else {
        bl0 = blp[lane]; bl1 = blp[32 + lane]; bl2 = blp[64 + lane];
    }
    const float2* msp = FIRST ? d_ms : (d_ms + b * 96);
    float2 ms0 = msp[lane], ms1 = msp[32 + lane], ms2 = msp[64 + lane];
    float c0 = expf(bl0 - ms0.x) * ms0.y;
    float c1 = expf(bl1 - ms1.x) * ms1.y;
    float c2 = expf(bl2 - ms2.x) * ms2.y;

    uint4 uv[6];
    float acc[8];
    #pragma unroll
    for (int q = 0; q < 8; q++) acc[q] = 0.f;
    #pragma unroll
    for (int j = 0; j < 6; j++) {
        uv[j] = up[j * 32 + lane];
        float cr = (j < 2) ? c0 : (j < 4) ? c1 : c2;
        float cv = __shfl_sync(0xffffffffu, cr, ((j & 1) << 4) + (lane >> 1));
        const __half2* h = (const __half2*)&uv[j];
        #pragma unroll
        for (int q = 0; q < 4; q++) {
            float2 f = __half22float2(h[q]);
            acc[2*q]   += cv * f.x;
            acc[2*q+1] += cv * f.y;
        }
    }
    // reduce over the 16 i-groups (lane bits 1..4)
    #pragma unroll
    for (int m = 2; m <= 16; m <<= 1)
        #pragma unroll
        for (int q = 0; q < 8; q++)
            acc[q] += __shfl_xor_sync(0xffffffffu, acc[q], m);
    // ||s||^2: this lane's 8 d's + the other d-half (lane^1)
    float sq = 0.f;
    #pragma unroll
    for (int q = 0; q < 8; q++) sq += acc[q] * acc[q];
    sq += __shfl_xor_sync(0xffffffffu, sq, 1);
    float n = sqrtf(sq);
    float sc = (1.0f - expf(-n)) / (n + 1e-8f);
    #pragma unroll
    for (int q = 0; q < 8; q++) acc[q] *= sc;

    if (LAST) {
        if (lane < 2) {
            float4* xp = (float4*)(d_x + (size_t)w * 16);
            xp[lane * 2 + 0] = make_float4(acc[0], acc[1], acc[2], acc[3]);
            xp[lane * 2 + 1] = make_float4(acc[4], acc[5], acc[6], acc[7]);
        }
    } else {
        #pragma unroll
        for (int j = 0; j < 6; j++) {
            const __half2* h = (const __half2*)&uv[j];
            float p = 0.f;
            #pragma unroll
            for (int q = 0; q < 4; q++) {
                float2 f = __half22float2(h[q]);
                p += acc[2*q] * f.x + acc[2*q+1] * f.y;
            }
            p += __shfl_xor_sync(0xffffffffu, p, 1);   // other d-half, same i
            if (!(lane & 1)) incsh[wid][j * 16 + (lane >> 1)] = p;
        }
        __syncwarp();
        blp[lane]      = bl0 + incsh[wid][lane];
        blp[32 + lane] = bl1 + incsh[wid][32 + lane];
        blp[64 + lane] = bl2 + incsh[wid][64 + lane];
    }
}

// ---------------- 4) length, peaks, top-K, gather ------------------------------
__global__ void finalize_kernel(float* __restrict__ outL) {
    const int b = blockIdx.x, t = threadIdx.x; // 256 threads
    __shared__ float len[192], lnN[192], pk[192], red[256];
    float L = 0.f;
    if (t < NUM_CAPS) {
        const float* xp = d_x + ((size_t)b * NUM_CAPS + t) * 16;
        float n2 = 0.f;
        #pragma unroll
        for (int d = 0; d < 16; d++) { float v = xp[d]; n2 += v * v; }
        L = sqrtf(n2);
        len[t] = L;
    }
    red[t] = (t < NUM_CAPS) ? L : 0.f;
    __syncthreads();
    for (int s = 128; s > 0; s >>= 1) {
        if (t < s) red[t] += red[t + s];
        __syncthreads();
    }
    float tot = red[0];
    if (t < NUM_CAPS) {
        float ln = len[t] / (tot + 1e-8f);
        lnN[t] = ln;
        outL[b * NUM_CAPS + t] = ln;
    }
    __syncthreads();
    if (t < NUM_CAPS) {
        int lo = t - 5 > 0 ? t - 5 : 0;
        int hi = t + 5 < 180 ? t + 5 : 180;
        float m = -1e30f;
        for (int o = lo; o <= hi; o++) m = fmaxf(m, lnN[o]);
        pk[t] = (lnN[t] == m) ? lnN[t] : 0.f;
    }
    __syncthreads();
    if (t == 0) {
        int sel[KSEL];
        for (int k = 0; k < KSEL; k++) {
            int best = -1; float bv = -1e30f;
            for (int o = 0; o < NUM_CAPS; o++)
                if (pk[o] > bv) { bv = pk[o]; best = o; }
            sel[k] = best;
            pk[best] = -1e30f;
        }
        for (int a = 1; a < KSEL; a++) {
            int v = sel[a], j = a - 1;
            while (j >= 0 && sel[j] > v) { sel[j + 1] = sel[j]; j--; }
            sel[j + 1] = v;
        }
        for (int k = 0; k < KSEL; k++) {
            d_idx[b * KSEL + k] = sel[k];
            const float* xp = d_x + ((size_t)b * NUM_CAPS + sel[k]) * 16;
            float* gp = d_g + (b * KSEL + k) * 16;
            for (int d = 0; d < 16; d++) gp[d] = xp[d];
        }
    }
}

// ---------------- 5) MLP -------------------------------------------------------
__global__ void fc1_kernel(const float* __restrict__ w, const float* __restrict__ bias) {
    const int r = blockIdx.y;
    const int j = blockIdx.x * 256 + threadIdx.x;  // < 1024
    __shared__ float gr[16];
    __shared__ int base;
    if (threadIdx.x < 16) gr[threadIdx.x] = d_g[r * 16 + threadIdx.x];
    if (threadIdx.x == 0) base = d_idx[r] * 16;
    __syncthreads();
    float acc = bias[j];
    #pragma unroll
    for (int d = 0; d < 16; d++) acc += gr[d] * w[(size_t)(base + d) * 1024 + j];
    d_m0[r * 1024 + j] = gelu_f(acc);
}

__global__ void gemm_kernel(int asel, int csel, const float* __restrict__ W,
                            const float* __restrict__ bias, float* cout,
                            int Kd, int N, int act, int transOut) {
    const float* A = (asel == 0) ? d_m0 : d_m1;
    float* C = (csel == 0) ? d_m0 : (csel == 1) ? d_m1 : cout;
    __shared__ float As[16][64];
    __shared__ float Ws[16][68];
    const int bm = blockIdx.y * 64, bn = blockIdx.x * 64;
    const int t = threadIdx.x, tx = t & 15, ty = t >> 4;
    float acc[4][4];
    #pragma unroll
    for (int p = 0; p < 4; p++)
        #pragma unroll
        for (int q = 0; q < 4; q++) acc[p][q] = 0.f;

    for (int k0 = 0; k0 < Kd; k0 += 16) {
        {
            int r = t >> 2, cq = (t & 3) * 4;
            float4 a = *(const float4*)&A[(size_t)(bm + r) * Kd + k0 + cq];
            As[cq + 0][r] = a.x; As[cq + 1][r] = a.y;
            As[cq + 2][r] = a.z; As[cq + 3][r] = a.w;
        }
        {
            int r = t >> 4, c4 = (t & 15) * 4;
            *(float4*)&Ws[r][c4] = *(const float4*)&W[(size_t)(k0 + r) * N + bn + c4];
        }
        __syncthreads();
        #pragma unroll
        for (int kk = 0; kk < 16; kk++) {
            float4 a4 = *(const float4*)&As[kk][ty * 4];
            float4 b4 = *(const float4*)&Ws[kk][tx * 4];
            float a[4] = {a4.x, a4.y, a4.z, a4.w};
            float bb[4] = {b4.x, b4.y, b4.z, b4.w};
            #pragma unroll
            for (int p = 0; p < 4; p++)
                #pragma unroll
                for (int q = 0; q < 4; q++) acc[p][q] += a[p] * bb[q];
        }
        __syncthreads();
    }
    #pragma unroll
    for (int p = 0; p < 4; p++) {
        #pragma unroll
        for (int q = 0; q < 4; q++) {
            int m = bm + ty * 4 + p, n = bn + tx * 4 + q;
            float v = acc[p][q] + bias[n];
            if (act) v = gelu_f(v);
            if (!transOut) C[(size_t)m * N + n] = v;
            else C[(size_t)(m >> 2) * (N * 4) + n * 4 + (m & 3)] = v;
        }
    }
}

// ---------------- launch -------------------------------------------------------
extern "C" void kernel_launch(void* const* d_in, const int* in_sizes, int n_in,
                              void* d_out, int out_size) {
    const float* scm  = (const float*)d_in[0];
    const float* c1w = (const float*)d_in[2];  const float* c1b = (const float*)d_in[3];
    const float* c2w = (const float*)d_in[4];  const float* c2b = (const float*)d_in[5];
    const float* c3w = (const float*)d_in[6];  const float* c3b = (const float*)d_in[7];
    const float* pcw = (const float*)d_in[8];  const float* pcb = (const float*)d_in[9];
    const float* capsW = (const float*)d_in[10];
    const float* capsb = (const float*)d_in[11];
    const float* f1w = (const float*)d_in[12]; const float* f1b = (const float*)d_in[13];
    const float* f2w = (const float*)d_in[14]; const float* f2b = (const float*)d_in[15];
    const float* f3w = (const float*)d_in[16]; const float* f3b = (const float*)d_in[17];
    const float* f4w = (const float*)d_in[18]; const float* f4b = (const float*)d_in[19];
    const float* f5w = (const float*)d_in[20]; const float* f5b = (const float*)d_in[21];
    const float* hw  = (const float*)d_in[22]; const float* hb  = (const float*)d_in[23];

    float* outW = (float*)d_out;                       // [512, 128, 4]
    float* outL = outW + BATCH * 128 * KSEL;           // [512, 181]

    static int smem_set = 0;
    const int smax_smem = (NUM_CAPS * 97) * sizeof(float);  // ~70.2 KB
    if (!smem_set) {
        cudaFuncSetAttribute(softmax3_kernel,
                             cudaFuncAttributeMaxDynamicSharedMemorySize, smax_smem);
        cudaFuncSetAttribute(softmax_first_kernel,
                             cudaFuncAttributeMaxDynamicSharedMemorySize, smax_smem);
        smem_set = 1;
    }

    const int route_grid = BATCH * NUM_CAPS / 8;

    conv_stack_kernel<<<BATCH, 256>>>(scm, c1w, c1b, c2w, c2b, c3w, c3b, pcw, pcb); // 1
    uhat_kernel<<<dim3(6, NUM_CAPS), 256>>>(capsW);                                  // 2
    softmax_first_kernel<<<1, 256, smax_smem>>>(capsb);                              // 3
    route4_kernel<true,  false><<<route_grid, 256>>>(capsb);                         // 4
    softmax3_kernel<<<BATCH, 256, smax_smem>>>();                                    // 5
    route4_kernel<false, false><<<route_grid, 256>>>(capsb);                         // 6 (ncu)
    softmax3_kernel<<<BATCH, 256, smax_smem>>>();                                    // 7
    route4_kernel<false, true ><<<route_grid, 256>>>(capsb);                         // 8

    finalize_kernel<<<BATCH, 256>>>(outL);
    fc1_kernel<<<dim3(4, MLP_ROWS), 256>>>(f1w, f1b);
    gemm_kernel<<<dim3(12, 32), 256>>>(0, 1, f2w, f2b, nullptr, 1024, 768, 1, 0);
    gemm_kernel<<<dim3( 8, 32), 256>>>(1, 0, f3w, f3b, nullptr,  768, 512, 1, 0);
    gemm_kernel<<<dim3( 8, 32), 256>>>(0, 1, f4w, f4b, nullptr,  512, 512, 1, 0);
    gemm_kernel<<<dim3( 4, 32), 256>>>(1, 0, f5w, f5b, nullptr,  512, 256, 1, 0);
    gemm_kernel<<<dim3( 2, 32), 256>>>(0, 2, hw,  hb,  outW,     256, 128, 0, 1);
}

// round 6
// speedup vs baseline: 2.9103x; 1.1660x over previous
#include <cuda_runtime.h>
#include <cuda_fp16.h>
#include <math.h>

#define BATCH 512
#define NUM_CAPS 181
#define IN_CAPS 96
#define CAPS_DIM 16
#define KSEL 4
#define OI (NUM_CAPS * IN_CAPS)          // 17376
#define UHAT_TILE (IN_CAPS * CAPS_DIM)   // 1536
#define MLP_ROWS (BATCH * KSEL)          // 2048
#define NTOT (NUM_CAPS * CAPS_DIM)       // 2896

// ---------------- scratch (device globals; no allocation allowed) -------------
__device__ __half d_uh[IN_CAPS * BATCH * CAPS_DIM];                // u fp16, [i][b][k]
__device__ __half d_vh[(size_t)IN_CAPS * NTOT * CAPS_DIM];         // W repack, [i][n][k]
__device__ __half d_uhat[(size_t)BATCH * NUM_CAPS * IN_CAPS * CAPS_DIM]; // 285 MB
__device__ float  d_bl[BATCH * OI];                                // 35.6 MB
__device__ float2 d_ms[BATCH * IN_CAPS];                           // softmax stats
__device__ float  d_x[BATCH * NUM_CAPS * CAPS_DIM];                // 5.9 MB
__device__ int    d_idx[BATCH * KSEL];
__device__ float  d_g[MLP_ROWS * CAPS_DIM];
__device__ float  d_m0[MLP_ROWS * 1024];
__device__ float  d_m1[MLP_ROWS * 1024];

__device__ __forceinline__ float gelu_f(float x) {
    return 0.5f * x * (1.0f + erff(x * 0.70710678118654752f));
}

// ---------------- 0) W repack: capsW[o][i][d][k] -> d_vh[i][o*16+d][k] fp16 ----
__global__ void wrepack_kernel(const float* __restrict__ capsW, int o0, int cnt) {
    int idx = blockIdx.x * 256 + threadIdx.x;      // (o-o0)*1536 + i*16 + d
    if (idx >= cnt * 1536) return;
    int o = o0 + idx / 1536, r = idx % 1536, i = r >> 4, d = r & 15;
    const float* src = capsW + ((size_t)(o * 96 + i) * 16 + d) * 16;
    __half* dst = d_vh + ((size_t)i * NTOT + o * 16 + d) * 16;
    #pragma unroll
    for (int k = 0; k < 16; k++) dst[k] = __float2half(src[k]);
}

// ---------------- 1) fused conv stack + primary caps + squash ------------------
__global__ __launch_bounds__(256) void conv_stack_kernel(
        const float* __restrict__ scm,
        const float* __restrict__ w1, const float* __restrict__ b1,
        const float* __restrict__ w2, const float* __restrict__ b2,
        const float* __restrict__ w3, const float* __restrict__ b3,
        const float* __restrict__ pw, const float* __restrict__ pb) {
    __shared__ float A[4608];   // in(192) -> h2(128*36) -> u(1536)
    __shared__ float Bf[6400];  // h1(64*49) -> h3(256*25)
    const int b = blockIdx.x, t = threadIdx.x;

    const float* in = scm + b * 192;
    for (int i = t; i < 192; i += 256) A[i] = in[i];
    __syncthreads();

    // conv1: 3x8x8 -> 64x7x7 (Bf)
    for (int idx = t; idx < 64 * 49; idx += 256) {
        int oc = idx / 49, r = idx % 49, y = r / 7, x = r % 7;
        float acc = b1[oc];
        const float* wp = w1 + oc * 12;
        #pragma unroll
        for (int ic = 0; ic < 3; ic++) {
            const float* ip = A + ic * 64 + y * 8 + x;
            acc += ip[0]*wp[0] + ip[1]*wp[1] + ip[8]*wp[2] + ip[9]*wp[3];
            wp += 4;
        }
        Bf[idx] = gelu_f(acc);
    }
    __syncthreads();

    // conv2: 64x7x7 (Bf) -> 128x6x6 (A)
    {
        const int oc = t & 127, half = t >> 7, y0 = half * 3;
        float acc[18];
        #pragma unroll
        for (int p = 0; p < 18; p++) acc[p] = 0.f;
        for (int ic = 0; ic < 64; ic++) {
            float4 w = *(const float4*)(w2 + oc * 256 + ic * 4);
            const float* ip = Bf + ic * 49 + y0 * 7;
            float r0[7], r1[7];
            #pragma unroll
            for (int x = 0; x < 7; x++) r0[x] = ip[x];
            #pragma unroll
            for (int yy = 0; yy < 3; yy++) {
                #pragma unroll
                for (int x = 0; x < 7; x++) r1[x] = ip[(yy + 1) * 7 + x];
                #pragma unroll
                for (int x = 0; x < 6; x++)
                    acc[yy*6+x] += r0[x]*w.x + r0[x+1]*w.y + r1[x]*w.z + r1[x+1]*w.w;
                #pragma unroll
                for (int x = 0; x < 7; x++) r0[x] = r1[x];
            }
        }
        float bb = b2[oc];
        __syncthreads();
        #pragma unroll
        for (int yy = 0; yy < 3; yy++)
            #pragma unroll
            for (int x = 0; x < 6; x++)
                A[oc * 36 + (y0 + yy) * 6 + x] = gelu_f(acc[yy*6+x] + bb);
    }
    __syncthreads();

    // conv3: 128x6x6 (A) -> 256x5x5 (Bf)
    {
        const int oc = t;
        float acc[25];
        #pragma unroll
        for (int p = 0; p < 25; p++) acc[p] = 0.f;
        for (int ic = 0; ic < 128; ic++) {
            float4 w = *(const float4*)(w3 + oc * 512 + ic * 4);
            const float* ip = A + ic * 36;
            float r0[6], r1[6];
            #pragma unroll
            for (int x = 0; x < 6; x++) r0[x] = ip[x];
            #pragma unroll
            for (int yy = 0; yy < 5; yy++) {
                #pragma unroll
                for (int x = 0; x < 6; x++) r1[x] = ip[(yy + 1) * 6 + x];
                #pragma unroll
                for (int x = 0; x < 5; x++)
                    acc[yy*5+x] += r0[x]*w.x + r0[x+1]*w.y + r1[x]*w.z + r1[x+1]*w.w;
                #pragma unroll
                for (int x = 0; x < 6; x++) r0[x] = r1[x];
            }
        }
        float bb = b3[oc];
        __syncthreads();
        #pragma unroll
        for (int p = 0; p < 25; p++) Bf[oc * 25 + p] = gelu_f(acc[p] + bb);
    }
    __syncthreads();

    // primary caps: 256x5x5 (Bf) -> 96x4x4 (A)
    if (t < 192) {
        const int g = t >> 1, half = t & 1, y0 = half * 2;
        float acc[8];
        #pragma unroll
        for (int p = 0; p < 8; p++) acc[p] = 0.f;
        for (int ic = 0; ic < 256; ic++) {
            float4 w = *(const float4*)(pw + g * 1024 + ic * 4);
            const float* ip = Bf + ic * 25 + y0 * 5;
            float r0[5], r1[5];
            #pragma unroll
            for (int x = 0; x < 5; x++) r0[x] = ip[x];
            #pragma unroll
            for (int yy = 0; yy < 2; yy++) {
                #pragma unroll
                for (int x = 0; x < 5; x++) r1[x] = ip[(yy + 1) * 5 + x];
                #pragma unroll
                for (int x = 0; x < 4; x++)
                    acc[yy*4+x] += r0[x]*w.x + r0[x+1]*w.y + r1[x]*w.z + r1[x+1]*w.w;
                #pragma unroll
                for (int x = 0; x < 5; x++) r0[x] = r1[x];
            }
        }
        float bb = pb[g];
        #pragma unroll
        for (int yy = 0; yy < 2; yy++)
            #pragma unroll
            for (int x = 0; x < 4; x++)
                A[g * 16 + (y0 + yy) * 4 + x] = acc[yy*4+x] + bb;
    }
    __syncthreads();

    // squash per capsule; store fp16 u as [i][b][k]
    if (t < 96) {
        float n2 = 0.f;
        #pragma unroll
        for (int d = 0; d < 16; d++) { float v = A[t * 16 + d]; n2 += v * v; }
        float n = sqrtf(n2);
        float sc = (1.0f - expf(-n)) / (n + 1e-8f);
        __half2* up = (__half2*)(d_uh + ((size_t)t * BATCH + b) * 16);
        #pragma unroll
        for (int q = 0; q < 8; q++)
            up[q] = __floats2half2_rn(A[t*16 + 2*q] * sc, A[t*16 + 2*q + 1] * sc);
    }
}

// ---------------- 2) u_hat via tensor cores ------------------------------------
// Per i: C[512 x 2896] = U_i[512x16] @ V_i[16x2896], one m16n8k16 step (K=16).
__global__ __launch_bounds__(256) void uhat_mma_kernel() {
    const int i = blockIdx.y;
    const int n0 = blockIdx.x * 128;
    const int warp = threadIdx.x >> 5, lane = threadIdx.x & 31;
    __shared__ __half As[512 * 16];   // A_i[b][k], 16KB

    {   // cooperative load of A_i (coalesced uint4)
        const uint4* src = (const uint4*)(d_uh + (size_t)i * BATCH * 16);
        uint4* dst = (uint4*)As;
        for (int t2 = threadIdx.x; t2 < 1024; t2 += 256) dst[t2] = src[t2];
    }
    __syncthreads();

    const int nrem = NTOT - n0;                    // 128 or 80 (last chunk)
    const __half* Vb = d_vh + (size_t)i * NTOT * 16;

    // B fragments, register-resident (fully unrolled, predicated)
    unsigned bf0[16], bf1[16];
    #pragma unroll
    for (int tn = 0; tn < 16; tn++) {
        if (tn * 8 < nrem) {
            int n = n0 + tn * 8 + (lane >> 2);
            const __half* p = Vb + n * 16 + (lane & 3) * 2;
            bf0[tn] = *(const unsigned*)(p);       // k, k+1
            bf1[tn] = *(const unsigned*)(p + 8);   // k+8, k+9
        } else { bf0[tn] = 0u; bf1[tn] = 0u; }
    }

    #pragma unroll
    for (int mt = 0; mt < 4; mt++) {
        const int m0 = warp * 64 + mt * 16;
        const __half* ap = As + (m0 + (lane >> 2)) * 16 + (lane & 3) * 2;
        unsigned a0 = *(const unsigned*)(ap);
        unsigned a1 = *(const unsigned*)(ap + 8 * 16);
        unsigned a2 = *(const unsigned*)(ap + 8);
        unsigned a3 = *(const unsigned*)(ap + 8 * 16 + 8);
        const int brow = m0 + (lane >> 2);
        #pragma unroll
        for (int tn = 0; tn < 16; tn++) {
            if (tn * 8 < nrem) {
                float e0, e1, e2, e3;
                asm volatile(
                    "mma.sync.aligned.m16n8k16.row.col.f32.f16.f16.f32 "
                    "{%0,%1,%2,%3}, {%4,%5,%6,%7}, {%8,%9}, {%10,%11,%12,%13};"
                    : "=f"(e0), "=f"(e1), "=f"(e2), "=f"(e3)
                    : "r"(a0), "r"(a1), "r"(a2), "r"(a3),
                      "r"(bf0[tn]), "r"(bf1[tn]),
                      "f"(0.f), "f"(0.f), "f"(0.f), "f"(0.f));
                int n = n0 + tn * 8 + 2 * (lane & 3);
                int o = n >> 4, dd = n & 15;
                __half2 h01 = __floats2half2_rn(e0, e1);
                __half2 h23 = __floats2half2_rn(e2, e3);
                *(__half2*)(d_uhat + ((size_t)(brow * NUM_CAPS + o) * 96 + i) * 16 + dd) = h01;
                *(__half2*)(d_uhat + ((size_t)((brow + 8) * NUM_CAPS + o) * 96 + i) * 16 + dd) = h23;
            }
        }
    }
}

// ---------------- 3) routing ---------------------------------------------------
__global__ void softmax_first_kernel(const float* __restrict__ caps_b) {
    extern __shared__ float sb[];            // 181*97 floats
    const int t = threadIdx.x;
    for (int e = t; e < OI; e += 256) sb[(e / 96) * 97 + (e % 96)] = caps_b[e];
    __syncthreads();
    const int wid = t >> 5, lane = t & 31;
    for (int i = wid; i < 96; i += 8) {
        float m = -1e30f;
        for (int o = lane; o < NUM_CAPS; o += 32) m = fmaxf(m, sb[o * 97 + i]);
        #pragma unroll
        for (int s = 16; s; s >>= 1) m = fmaxf(m, __shfl_xor_sync(0xffffffffu, m, s));
        float s = 0.f;
        for (int o = lane; o < NUM_CAPS; o += 32) s += expf(sb[o * 97 + i] - m);
        #pragma unroll
        for (int sh = 16; sh; sh >>= 1) s += __shfl_xor_sync(0xffffffffu, s, sh);
        if (lane == 0) d_ms[i] = make_float2(m, 1.0f / s);
    }
}

__global__ void softmax3_kernel() {
    extern __shared__ float sb[];            // 181*97 floats
    const int b = blockIdx.x, t = threadIdx.x;
    const float* blp = d_bl + (size_t)b * OI;
    for (int e = t; e < OI; e += 256) sb[(e / 96) * 97 + (e % 96)] = blp[e];
    __syncthreads();
    const int wid = t >> 5, lane = t & 31;
    for (int i = wid; i < 96; i += 8) {
        float m = -1e30f;
        for (int o = lane; o < NUM_CAPS; o += 32) m = fmaxf(m, sb[o * 97 + i]);
        #pragma unroll
        for (int s = 16; s; s >>= 1) m = fmaxf(m, __shfl_xor_sync(0xffffffffu, m, s));
        float s = 0.f;
        for (int o = lane; o < NUM_CAPS; o += 32) s += expf(sb[o * 97 + i] - m);
        #pragma unroll
        for (int sh = 16; sh; sh >>= 1) s += __shfl_xor_sync(0xffffffffu, s, sh);
        if (lane == 0) d_ms[b * 96 + i] = make_float2(m, 1.0f / s);
    }
}

// warp-per-(b,o) routing step on fp16 u_hat.
template<bool FIRST, bool LAST>
__global__ __launch_bounds__(256) void route4_kernel(const float* __restrict__ caps_b) {
    __shared__ float incsh[8][96];
    const int wid = threadIdx.x >> 5, lane = threadIdx.x & 31;
    const int w = blockIdx.x * 8 + wid;            // w = b*181 + o
    const int b = w / NUM_CAPS;
    const uint4* up = (const uint4*)(d_uhat + (size_t)w * UHAT_TILE);
    float* blp = d_bl + (size_t)w * 96;

    float bl0, bl1, bl2;
    if (FIRST) {
        const int o = w - b * NUM_CAPS;
        const float* cbp = caps_b + o * 96;
        bl0 = cbp[lane]; bl1 = cbp[32 + lane]; bl2 = cbp[64 + lane];
    } else {
        bl0 = blp[lane]; bl1 = blp[32 + lane]; bl2 = blp[64 + lane];
    }
    const float2* msp = FIRST ? d_ms : (d_ms + b * 96);
    float2 ms0 = msp[lane], ms1 = msp[32 + lane], ms2 = msp[64 + lane];
    float c0 = expf(bl0 - ms0.x) * ms0.y;
    float c1 = expf(bl1 - ms1.x) * ms1.y;
    float c2 = expf(bl2 - ms2.x) * ms2.y;

    uint4 uv[6];
    float acc[8];
    #pragma unroll
    for (int q = 0; q < 8; q++) acc[q] = 0.f;
    #pragma unroll
    for (int j = 0; j < 6; j++) {
        uv[j] = up[j * 32 + lane];
        float cr = (j < 2) ? c0 : (j < 4) ? c1 : c2;
        float cv = __shfl_sync(0xffffffffu, cr, ((j & 1) << 4) + (lane >> 1));
        const __half2* h = (const __half2*)&uv[j];
        #pragma unroll
        for (int q = 0; q < 4; q++) {
            float2 f = __half22float2(h[q]);
            acc[2*q]   += cv * f.x;
            acc[2*q+1] += cv * f.y;
        }
    }
    #pragma unroll
    for (int m = 2; m <= 16; m <<= 1)
        #pragma unroll
        for (int q = 0; q < 8; q++)
            acc[q] += __shfl_xor_sync(0xffffffffu, acc[q], m);
    float sq = 0.f;
    #pragma unroll
    for (int q = 0; q < 8; q++) sq += acc[q] * acc[q];
    sq += __shfl_xor_sync(0xffffffffu, sq, 1);
    float n = sqrtf(sq);
    float sc = (1.0f - expf(-n)) / (n + 1e-8f);
    #pragma unroll
    for (int q = 0; q < 8; q++) acc[q] *= sc;

    if (LAST) {
        if (lane < 2) {
            float4* xp = (float4*)(d_x + (size_t)w * 16);
            xp[lane * 2 + 0] = make_float4(acc[0], acc[1], acc[2], acc[3]);
            xp[lane * 2 + 1] = make_float4(acc[4], acc[5], acc[6], acc[7]);
        }
    } else {
        #pragma unroll
        for (int j = 0; j < 6; j++) {
            const __half2* h = (const __half2*)&uv[j];
            float p = 0.f;
            #pragma unroll
            for (int q = 0; q < 4; q++) {
                float2 f = __half22float2(h[q]);
                p += acc[2*q] * f.x + acc[2*q+1] * f.y;
            }
            p += __shfl_xor_sync(0xffffffffu, p, 1);
            if (!(lane & 1)) incsh[wid][j * 16 + (lane >> 1)] = p;
        }
        __syncwarp();
        blp[lane]      = bl0 + incsh[wid][lane];
        blp[32 + lane] = bl1 + incsh[wid][32 + lane];
        blp[64 + lane] = bl2 + incsh[wid][64 + lane];
    }
}

// ---------------- 4) length, peaks, top-K, gather ------------------------------
__global__ void finalize_kernel(float* __restrict__ outL) {
    const int b = blockIdx.x, t = threadIdx.x; // 256 threads
    __shared__ float len[192], lnN[192], pk[192], red[256];
    float L = 0.f;
    if (t < NUM_CAPS) {
        const float* xp = d_x + ((size_t)b * NUM_CAPS + t) * 16;
        float n2 = 0.f;
        #pragma unroll
        for (int d = 0; d < 16; d++) { float v = xp[d]; n2 += v * v; }
        L = sqrtf(n2);
        len[t] = L;
    }
    red[t] = (t < NUM_CAPS) ? L : 0.f;
    __syncthreads();
    for (int s = 128; s > 0; s >>= 1) {
        if (t < s) red[t] += red[t + s];
        __syncthreads();
    }
    float tot = red[0];
    if (t < NUM_CAPS) {
        float ln = len[t] / (tot + 1e-8f);
        lnN[t] = ln;
        outL[b * NUM_CAPS + t] = ln;
    }
    __syncthreads();
    if (t < NUM_CAPS) {
        int lo = t - 5 > 0 ? t - 5 : 0;
        int hi = t + 5 < 180 ? t + 5 : 180;
        float m = -1e30f;
        for (int o = lo; o <= hi; o++) m = fmaxf(m, lnN[o]);
        pk[t] = (lnN[t] == m) ? lnN[t] : 0.f;
    }
    __syncthreads();
    if (t == 0) {
        int sel[KSEL];
        for (int k = 0; k < KSEL; k++) {
            int best = -1; float bv = -1e30f;
            for (int o = 0; o < NUM_CAPS; o++)
                if (pk[o] > bv) { bv = pk[o]; best = o; }
            sel[k] = best;
            pk[best] = -1e30f;
        }
        for (int a = 1; a < KSEL; a++) {
            int v = sel[a], j = a - 1;
            while (j >= 0 && sel[j] > v) { sel[j + 1] = sel[j]; j--; }
            sel[j + 1] = v;
        }
        for (int k = 0; k < KSEL; k++) {
            d_idx[b * KSEL + k] = sel[k];
            const float* xp = d_x + ((size_t)b * NUM_CAPS + sel[k]) * 16;
            float* gp = d_g + (b * KSEL + k) * 16;
            for (int d = 0; d < 16; d++) gp[d] = xp[d];
        }
    }
}

// ---------------- 5) MLP -------------------------------------------------------
__global__ void fc1_kernel(const float* __restrict__ w, const float* __restrict__ bias) {
    const int r = blockIdx.y;
    const int j = blockIdx.x * 256 + threadIdx.x;  // < 1024
    __shared__ float gr[16];
    __shared__ int base;
    if (threadIdx.x < 16) gr[threadIdx.x] = d_g[r * 16 + threadIdx.x];
    if (threadIdx.x == 0) base = d_idx[r] * 16;
    __syncthreads();
    float acc = bias[j];
    #pragma unroll
    for (int d = 0; d < 16; d++) acc += gr[d] * w[(size_t)(base + d) * 1024 + j];
    d_m0[r * 1024 + j] = gelu_f(acc);
}

__global__ void gemm_kernel(int asel, int csel, const float* __restrict__ W,
                            const float* __restrict__ bias, float* cout,
                            int Kd, int N, int act, int transOut) {
    const float* A = (asel == 0) ? d_m0 : d_m1;
    float* C = (csel == 0) ? d_m0 : (csel == 1) ? d_m1 : cout;
    __shared__ float As[16][64];
    __shared__ float Ws[16][68];
    const int bm = blockIdx.y * 64, bn = blockIdx.x * 64;
    const int t = threadIdx.x, tx = t & 15, ty = t >> 4;
    float acc[4][4];
    #pragma unroll
    for (int p = 0; p < 4; p++)
        #pragma unroll
        for (int q = 0; q < 4; q++) acc[p][q] = 0.f;

    for (int k0 = 0; k0 < Kd; k0 += 16) {
        {
            int r = t >> 2, cq = (t & 3) * 4;
            float4 a = *(const float4*)&A[(size_t)(bm + r) * Kd + k0 + cq];
            As[cq + 0][r] = a.x; As[cq + 1][r] = a.y;
            As[cq + 2][r] = a.z; As[cq + 3][r] = a.w;
        }
        {
            int r = t >> 4, c4 = (t & 15) * 4;
            *(float4*)&Ws[r][c4] = *(const float4*)&W[(size_t)(k0 + r) * N + bn + c4];
        }
        __syncthreads();
        #pragma unroll
        for (int kk = 0; kk < 16; kk++) {
            float4 a4 = *(const float4*)&As[kk][ty * 4];
            float4 b4 = *(const float4*)&Ws[kk][tx * 4];
            float a[4] = {a4.x, a4.y, a4.z, a4.w};
            float bb[4] = {b4.x, b4.y, b4.z, b4.w};
            #pragma unroll
            for (int p = 0; p < 4; p++)
                #pragma unroll
                for (int q = 0; q < 4; q++) acc[p][q] += a[p] * bb[q];
        }
        __syncthreads();
    }
    #pragma unroll
    for (int p = 0; p < 4; p++) {
        #pragma unroll
        for (int q = 0; q < 4; q++) {
            int m = bm + ty * 4 + p, n = bn + tx * 4 + q;
            float v = acc[p][q] + bias[n];
            if (act) v = gelu_f(v);
            if (!transOut) C[(size_t)m * N + n] = v;
            else C[(size_t)(m >> 2) * (N * 4) + n * 4 + (m & 3)] = v;
        }
    }
}

// ---------------- launch -------------------------------------------------------
extern "C" void kernel_launch(void* const* d_in, const int* in_sizes, int n_in,
                              void* d_out, int out_size) {
    const float* scm  = (const float*)d_in[0];
    const float* c1w = (const float*)d_in[2];  const float* c1b = (const float*)d_in[3];
    const float* c2w = (const float*)d_in[4];  const float* c2b = (const float*)d_in[5];
    const float* c3w = (const float*)d_in[6];  const float* c3b = (const float*)d_in[7];
    const float* pcw = (const float*)d_in[8];  const float* pcb = (const float*)d_in[9];
    const float* capsW = (const float*)d_in[10];
    const float* capsb = (const float*)d_in[11];
    const float* f1w = (const float*)d_in[12]; const float* f1b = (const float*)d_in[13];
    const float* f2w = (const float*)d_in[14]; const float* f2b = (const float*)d_in[15];
    const float* f3w = (const float*)d_in[16]; const float* f3b = (const float*)d_in[17];
    const float* f4w = (const float*)d_in[18]; const float* f4b = (const float*)d_in[19];
    const float* f5w = (const float*)d_in[20]; const float* f5b = (const float*)d_in[21];
    const float* hw  = (const float*)d_in[22]; const float* hb  = (const float*)d_in[23];

    float* outW = (float*)d_out;                       // [512, 128, 4]
    float* outL = outW + BATCH * 128 * KSEL;           // [512, 181]

    static int smem_set = 0;
    const int smax_smem = (NUM_CAPS * 97) * sizeof(float);  // ~70.2 KB
    if (!smem_set) {
        cudaFuncSetAttribute(softmax3_kernel,
                             cudaFuncAttributeMaxDynamicSharedMemorySize, smax_smem);
        cudaFuncSetAttribute(softmax_first_kernel,
                             cudaFuncAttributeMaxDynamicSharedMemorySize, smax_smem);
        smem_set = 1;
    }

    const int route_grid = BATCH * NUM_CAPS / 8;

    // launches 1-3 are independent of conv so conv lands at #4 (ncu window)
    wrepack_kernel<<<(91 * 1536 + 255) / 256, 256>>>(capsW, 0, 91);                  // 1
    softmax_first_kernel<<<1, 256, smax_smem>>>(capsb);                              // 2
    wrepack_kernel<<<(90 * 1536 + 255) / 256, 256>>>(capsW, 91, 90);                 // 3
    conv_stack_kernel<<<BATCH, 256>>>(scm, c1w, c1b, c2w, c2b, c3w, c3b, pcw, pcb); // 4 (ncu)
    uhat_mma_kernel<<<dim3(23, 96), 256>>>();                                        // 5
    route4_kernel<true,  false><<<route_grid, 256>>>(capsb);                         // 6
    softmax3_kernel<<<BATCH, 256, smax_smem>>>();                                    // 7
    route4_kernel<false, false><<<route_grid, 256>>>(capsb);                         // 8
    softmax3_kernel<<<BATCH, 256, smax_smem>>>();                                    // 9
    route4_kernel<false, true ><<<route_grid, 256>>>(capsb);                         // 10

    finalize_kernel<<<BATCH, 256>>>(outL);
    fc1_kernel<<<dim3(4, MLP_ROWS), 256>>>(f1w, f1b);
    gemm_kernel<<<dim3(12, 32), 256>>>(0, 1, f2w, f2b, nullptr, 1024, 768, 1, 0);
    gemm_kernel<<<dim3( 8, 32), 256>>>(1, 0, f3w, f3b, nullptr,  768, 512, 1, 0);
    gemm_kernel<<<dim3( 8, 32), 256>>>(0, 1, f4w, f4b, nullptr,  512, 512, 1, 0);
    gemm_kernel<<<dim3( 4, 32), 256>>>(1, 0, f5w, f5b, nullptr,  512, 256, 1, 0);
    gemm_kernel<<<dim3( 2, 32), 256>>>(0, 2, hw,  hb,  outW,     256, 128, 0, 1);
}

// round 7
// speedup vs baseline: 3.0089x; 1.0339x over previous
#include <cuda_runtime.h>
#include <cuda_fp16.h>
#include <math.h>

#define BATCH 512
#define NUM_CAPS 181
#define IN_CAPS 96
#define CAPS_DIM 16
#define KSEL 4
#define OI (NUM_CAPS * IN_CAPS)          // 17376
#define UHAT_TILE (IN_CAPS * CAPS_DIM)   // 1536
#define MLP_ROWS (BATCH * KSEL)          // 2048
#define NTOT (NUM_CAPS * CAPS_DIM)       // 2896

// ---------------- scratch (device globals; no allocation allowed) -------------
__device__ __half d_uh[IN_CAPS * BATCH * CAPS_DIM];                // u fp16, [i][b][k]
__device__ __half d_vh[(size_t)IN_CAPS * NTOT * CAPS_DIM];         // W repack, [i][n][k]
__device__ __half d_uhat[(size_t)BATCH * NUM_CAPS * IN_CAPS * CAPS_DIM]; // 285 MB
__device__ float  d_bl[BATCH * OI];                                // 35.6 MB
__device__ float2 d_ms[BATCH * IN_CAPS];                           // softmax stats
__device__ float  d_x[BATCH * NUM_CAPS * CAPS_DIM];                // 5.9 MB
__device__ int    d_idx[BATCH * KSEL];
__device__ float  d_g[MLP_ROWS * CAPS_DIM];
__device__ float  d_m0[MLP_ROWS * 1024];
__device__ float  d_m1[MLP_ROWS * 1024];

__device__ __forceinline__ float gelu_f(float x) {
    return 0.5f * x * (1.0f + erff(x * 0.70710678118654752f));
}

// ---------------- 0) W repack: capsW[o][i][d][k] -> d_vh[i][o*16+d][k] fp16 ----
__global__ void wrepack_kernel(const float* __restrict__ capsW) {
    int idx = blockIdx.x * 256 + threadIdx.x;      // o*1536 + i*16 + d
    if (idx >= NUM_CAPS * 1536) return;
    int o = idx / 1536, r = idx % 1536, i = r >> 4, d = r & 15;
    const float* src = capsW + ((size_t)(o * 96 + i) * 16 + d) * 16;
    __half* dst = d_vh + ((size_t)i * NTOT + o * 16 + d) * 16;
    #pragma unroll
    for (int k = 0; k < 16; k++) dst[k] = __float2half(src[k]);
}

// ---------------- 1) fused conv stack + primary caps + squash ------------------
// Padded row layouts (stride 8, 16B-aligned) + LDS.128 rolling-row windows.
// smem: s_in[192] | Y[6144] (c2 out, later u) | X[6400] (c1 out padded, later c3)
#define LD8(dst, ptr) do { \
    float4 _a = *(const float4*)(ptr); \
    float4 _b = *(const float4*)((ptr) + 4); \
    dst[0]=_a.x; dst[1]=_a.y; dst[2]=_a.z; dst[3]=_a.w; \
    dst[4]=_b.x; dst[5]=_b.y; dst[6]=_b.z; dst[7]=_b.w; } while (0)

#define CROW(top, bot, acc, yy, W) do { \
    _Pragma("unroll") \
    for (int _x = 0; _x < (W); _x++) \
        acc[(yy)*(W)+_x] += top[_x]*w.x + top[_x+1]*w.y + bot[_x]*w.z + bot[_x+1]*w.w; \
    } while (0)

__global__ __launch_bounds__(256, 4) void conv_stack_kernel(
        const float* __restrict__ scm,
        const float* __restrict__ w1, const float* __restrict__ b1,
        const float* __restrict__ w2, const float* __restrict__ b2,
        const float* __restrict__ w3, const float* __restrict__ b3,
        const float* __restrict__ pw, const float* __restrict__ pb) {
    extern __shared__ float smem[];
    float* s_in = smem;            // 192
    float* Y    = smem + 192;      // 6144: c2 out [128][6][8]; later u[1536]
    float* X    = smem + 6336;     // 6400: c1 out [64][7][8]; later c3 [256][25]
    const int b = blockIdx.x, t = threadIdx.x;

    const float* in = scm + b * 192;
    for (int i = t; i < 192; i += 256) s_in[i] = in[i];
    __syncthreads();

    // conv1: 3x8x8 -> 64x[7][8] padded (Bf->X)
    for (int idx = t; idx < 64 * 49; idx += 256) {
        int oc = idx / 49, r = idx % 49, y = r / 7, x = r % 7;
        float acc = b1[oc];
        const float* wp = w1 + oc * 12;
        #pragma unroll
        for (int ic = 0; ic < 3; ic++) {
            const float* ip = s_in + ic * 64 + y * 8 + x;
            acc += ip[0]*wp[0] + ip[1]*wp[1] + ip[8]*wp[2] + ip[9]*wp[3];
            wp += 4;
        }
        X[oc * 56 + y * 8 + x] = gelu_f(acc);
    }
    __syncthreads();

    // conv2: 64x7x7 (X) -> 128x[6][8] (Y). thread: oc = t&127, half rows
    {
        const int oc = t & 127, half = t >> 7, y0 = half * 3;
        float acc[18];
        #pragma unroll
        for (int p = 0; p < 18; p++) acc[p] = 0.f;
        for (int ic = 0; ic < 64; ic++) {
            float4 w = *(const float4*)(w2 + oc * 256 + ic * 4);
            const float* Xc = X + ic * 56 + y0 * 8;
            float r0[8], r1[8];
            LD8(r0, Xc);
            LD8(r1, Xc + 8);
            CROW(r0, r1, acc, 0, 6);
            LD8(r0, Xc + 16);
            CROW(r1, r0, acc, 1, 6);
            LD8(r1, Xc + 24);
            CROW(r0, r1, acc, 2, 6);
        }
        float bb = b2[oc];
        #pragma unroll
        for (int yy = 0; yy < 3; yy++)
            #pragma unroll
            for (int x = 0; x < 6; x++)
                Y[oc * 48 + (y0 + yy) * 8 + x] = gelu_f(acc[yy*6+x] + bb);
    }
    __syncthreads();

    // conv3: 128x[6][8] (Y) -> 256x25 compact (X). thread: oc = t
    {
        const int oc = t;
        float acc[25];
        #pragma unroll
        for (int p = 0; p < 25; p++) acc[p] = 0.f;
        for (int ic = 0; ic < 128; ic++) {
            float4 w = *(const float4*)(w3 + oc * 512 + ic * 4);
            const float* Yc = Y + ic * 48;
            float r0[8], r1[8];
            LD8(r0, Yc);
            LD8(r1, Yc + 8);
            CROW(r0, r1, acc, 0, 5);
            LD8(r0, Yc + 16);
            CROW(r1, r0, acc, 1, 5);
            LD8(r1, Yc + 24);
            CROW(r0, r1, acc, 2, 5);
            LD8(r0, Yc + 32);
            CROW(r1, r0, acc, 3, 5);
            LD8(r1, Yc + 40);
            CROW(r0, r1, acc, 4, 5);
        }
        float bb = b3[oc];
        __syncthreads();   // Y(c2) reads done block-wide; X(c1) dead
        #pragma unroll
        for (int p = 0; p < 25; p++) X[oc * 25 + p] = gelu_f(acc[p] + bb);
    }
    __syncthreads();

    // primary caps: 256x25 (X) -> 96x4x4 -> Y[0..1536)
    if (t < 192) {
        const int g = t >> 1, half = t & 1, y0 = half * 2;
        float acc[8];
        #pragma unroll
        for (int p = 0; p < 8; p++) acc[p] = 0.f;
        for (int ic = 0; ic < 256; ic++) {
            float4 w = *(const float4*)(pw + g * 1024 + ic * 4);
            const float* ip = X + ic * 25 + y0 * 5;
            float r0[5], r1[5];
            #pragma unroll
            for (int x = 0; x < 5; x++) r0[x] = ip[x];
            #pragma unroll
            for (int x = 0; x < 5; x++) r1[x] = ip[5 + x];
            CROW(r0, r1, acc, 0, 4);
            #pragma unroll
            for (int x = 0; x < 5; x++) r0[x] = ip[10 + x];
            CROW(r1, r0, acc, 1, 4);
        }
        float bb = pb[g];
        #pragma unroll
        for (int yy = 0; yy < 2; yy++)
            #pragma unroll
            for (int x = 0; x < 4; x++)
                Y[g * 16 + (y0 + yy) * 4 + x] = acc[yy*4+x] + bb;
    }
    __syncthreads();

    // squash per capsule; store fp16 u as [i][b][k]
    if (t < 96) {
        float n2 = 0.f;
        #pragma unroll
        for (int d = 0; d < 16; d++) { float v = Y[t * 16 + d]; n2 += v * v; }
        float n = sqrtf(n2);
        float sc = (1.0f - expf(-n)) / (n + 1e-8f);
        __half2* up = (__half2*)(d_uh + ((size_t)t * BATCH + b) * 16);
        #pragma unroll
        for (int q = 0; q < 8; q++)
            up[q] = __floats2half2_rn(Y[t*16 + 2*q] * sc, Y[t*16 + 2*q + 1] * sc);
    }
}

// ---------------- 2) u_hat via tensor cores ------------------------------------
__global__ __launch_bounds__(256) void uhat_mma_kernel() {
    const int i = blockIdx.y;
    const int n0 = blockIdx.x * 128;
    const int warp = threadIdx.x >> 5, lane = threadIdx.x & 31;
    __shared__ __half As[512 * 16];   // A_i[b][k], 16KB

    {
        const uint4* src = (const uint4*)(d_uh + (size_t)i * BATCH * 16);
        uint4* dst = (uint4*)As;
        for (int t2 = threadIdx.x; t2 < 1024; t2 += 256) dst[t2] = src[t2];
    }
    __syncthreads();

    const int nrem = NTOT - n0;
    const __half* Vb = d_vh + (size_t)i * NTOT * 16;

    unsigned bf0[16], bf1[16];
    #pragma unroll
    for (int tn = 0; tn < 16; tn++) {
        if (tn * 8 < nrem) {
            int n = n0 + tn * 8 + (lane >> 2);
            const __half* p = Vb + n * 16 + (lane & 3) * 2;
            bf0[tn] = *(const unsigned*)(p);
            bf1[tn] = *(const unsigned*)(p + 8);
        } else { bf0[tn] = 0u; bf1[tn] = 0u; }
    }

    #pragma unroll
    for (int mt = 0; mt < 4; mt++) {
        const int m0 = warp * 64 + mt * 16;
        const __half* ap = As + (m0 + (lane >> 2)) * 16 + (lane & 3) * 2;
        unsigned a0 = *(const unsigned*)(ap);
        unsigned a1 = *(const unsigned*)(ap + 8 * 16);
        unsigned a2 = *(const unsigned*)(ap + 8);
        unsigned a3 = *(const unsigned*)(ap + 8 * 16 + 8);
        const int brow = m0 + (lane >> 2);
        #pragma unroll
        for (int tn = 0; tn < 16; tn++) {
            if (tn * 8 < nrem) {
                float e0, e1, e2, e3;
                asm volatile(
                    "mma.sync.aligned.m16n8k16.row.col.f32.f16.f16.f32 "
                    "{%0,%1,%2,%3}, {%4,%5,%6,%7}, {%8,%9}, {%10,%11,%12,%13};"
                    : "=f"(e0), "=f"(e1), "=f"(e2), "=f"(e3)
                    : "r"(a0), "r"(a1), "r"(a2), "r"(a3),
                      "r"(bf0[tn]), "r"(bf1[tn]),
                      "f"(0.f), "f"(0.f), "f"(0.f), "f"(0.f));
                int n = n0 + tn * 8 + 2 * (lane & 3);
                int o = n >> 4, dd = n & 15;
                __half2 h01 = __floats2half2_rn(e0, e1);
                __half2 h23 = __floats2half2_rn(e2, e3);
                *(__half2*)(d_uhat + ((size_t)(brow * NUM_CAPS + o) * 96 + i) * 16 + dd) = h01;
                *(__half2*)(d_uhat + ((size_t)((brow + 8) * NUM_CAPS + o) * 96 + i) * 16 + dd) = h23;
            }
        }
    }
}

// ---------------- 3) routing ---------------------------------------------------
__global__ void softmax_first_kernel(const float* __restrict__ caps_b) {
    extern __shared__ float sb[];            // 181*97 floats
    const int t = threadIdx.x;
    for (int e = t; e < OI; e += 256) sb[(e / 96) * 97 + (e % 96)] = caps_b[e];
    __syncthreads();
    const int wid = t >> 5, lane = t & 31;
    for (int i = wid; i < 96; i += 8) {
        float m = -1e30f;
        for (int o = lane; o < NUM_CAPS; o += 32) m = fmaxf(m, sb[o * 97 + i]);
        #pragma unroll
        for (int s = 16; s; s >>= 1) m = fmaxf(m, __shfl_xor_sync(0xffffffffu, m, s));
        float s = 0.f;
        for (int o = lane; o < NUM_CAPS; o += 32) s += expf(sb[o * 97 + i] - m);
        #pragma unroll
        for (int sh = 16; sh; sh >>= 1) s += __shfl_xor_sync(0xffffffffu, s, sh);
        if (lane == 0) d_ms[i] = make_float2(m, 1.0f / s);
    }
}

__global__ void softmax3_kernel() {
    extern __shared__ float sb[];            // 181*97 floats
    const int b = blockIdx.x, t = threadIdx.x;
    const float* blp = d_bl + (size_t)b * OI;
    for (int e = t; e < OI; e += 256) sb[(e / 96) * 97 + (e % 96)] = blp[e];
    __syncthreads();
    const int wid = t >> 5, lane = t & 31;
    for (int i = wid; i < 96; i += 8) {
        float m = -1e30f;
        for (int o = lane; o < NUM_CAPS; o += 32) m = fmaxf(m, sb[o * 97 + i]);
        #pragma unroll
        for (int s = 16; s; s >>= 1) m = fmaxf(m, __shfl_xor_sync(0xffffffffu, m, s));
        float s = 0.f;
        for (int o = lane; o < NUM_CAPS; o += 32) s += expf(sb[o * 97 + i] - m);
        #pragma unroll
        for (int sh = 16; sh; sh >>= 1) s += __shfl_xor_sync(0xffffffffu, s, sh);
        if (lane == 0) d_ms[b * 96 + i] = make_float2(m, 1.0f / s);
    }
}

template<bool FIRST, bool LAST>
__global__ __launch_bounds__(256) void route4_kernel(const float* __restrict__ caps_b) {
    __shared__ float incsh[8][96];
    const int wid = threadIdx.x >> 5, lane = threadIdx.x & 31;
    const int w = blockIdx.x * 8 + wid;            // w = b*181 + o
    const int b = w / NUM_CAPS;
    const uint4* up = (const uint4*)(d_uhat + (size_t)w * UHAT_TILE);
    float* blp = d_bl + (size_t)w * 96;

    float bl0, bl1, bl2;
    if (FIRST) {
        const int o = w - b * NUM_CAPS;
        const float* cbp = caps_b + o * 96;
        bl0 = cbp[lane]; bl1 = cbp[32 + lane]; bl2 = cbp[64 + lane];
    } else {
        bl0 = blp[lane]; bl1 = blp[32 + lane]; bl2 = blp[64 + lane];
    }
    const float2* msp = FIRST ? d_ms : (d_ms + b * 96);
    float2 ms0 = msp[lane], ms1 = msp[32 + lane], ms2 = msp[64 + lane];
    float c0 = expf(bl0 - ms0.x) * ms0.y;
    float c1 = expf(bl1 - ms1.x) * ms1.y;
    float c2 = expf(bl2 - ms2.x) * ms2.y;

    uint4 uv[6];
    float acc[8];
    #pragma unroll
    for (int q = 0; q < 8; q++) acc[q] = 0.f;
    #pragma unroll
    for (int j = 0; j < 6; j++) {
        uv[j] = up[j * 32 + lane];
        float cr = (j < 2) ? c0 : (j < 4) ? c1 : c2;
        float cv = __shfl_sync(0xffffffffu, cr, ((j & 1) << 4) + (lane >> 1));
        const __half2* h = (const __half2*)&uv[j];
        #pragma unroll
        for (int q = 0; q < 4; q++) {
            float2 f = __half22float2(h[q]);
            acc[2*q]   += cv * f.x;
            acc[2*q+1] += cv * f.y;
        }
    }
    #pragma unroll
    for (int m = 2; m <= 16; m <<= 1)
        #pragma unroll
        for (int q = 0; q < 8; q++)
            acc[q] += __shfl_xor_sync(0xffffffffu, acc[q], m);
    float sq = 0.f;
    #pragma unroll
    for (int q = 0; q < 8; q++) sq += acc[q] * acc[q];
    sq += __shfl_xor_sync(0xffffffffu, sq, 1);
    float n = sqrtf(sq);
    float sc = (1.0f - expf(-n)) / (n + 1e-8f);
    #pragma unroll
    for (int q = 0; q < 8; q++) acc[q] *= sc;

    if (LAST) {
        if (lane < 2) {
            float4* xp = (float4*)(d_x + (size_t)w * 16);
            xp[lane * 2 + 0] = make_float4(acc[0], acc[1], acc[2], acc[3]);
            xp[lane * 2 + 1] = make_float4(acc[4], acc[5], acc[6], acc[7]);
        }
    } else {
        #pragma unroll
        for (int j = 0; j < 6; j++) {
            const __half2* h = (const __half2*)&uv[j];
            float p = 0.f;
            #pragma unroll
            for (int q = 0; q < 4; q++) {
                float2 f = __half22float2(h[q]);
                p += acc[2*q] * f.x + acc[2*q+1] * f.y;
            }
            p += __shfl_xor_sync(0xffffffffu, p, 1);
            if (!(lane & 1)) incsh[wid][j * 16 + (lane >> 1)] = p;
        }
        __syncwarp();
        blp[lane]      = bl0 + incsh[wid][lane];
        blp[32 + lane] = bl1 + incsh[wid][32 + lane];
        blp[64 + lane] = bl2 + incsh[wid][64 + lane];
    }
}

// ---------------- 4) length, peaks, top-K, gather ------------------------------
__global__ void finalize_kernel(float* __restrict__ outL) {
    const int b = blockIdx.x, t = threadIdx.x; // 256 threads
    __shared__ float len[192], lnN[192], pk[192], red[256];
    float L = 0.f;
    if (t < NUM_CAPS) {
        const float* xp = d_x + ((size_t)b * NUM_CAPS + t) * 16;
        float n2 = 0.f;
        #pragma unroll
        for (int d = 0; d < 16; d++) { float v = xp[d]; n2 += v * v; }
        L = sqrtf(n2);
        len[t] = L;
    }
    red[t] = (t < NUM_CAPS) ? L : 0.f;
    __syncthreads();
    for (int s = 128; s > 0; s >>= 1) {
        if (t < s) red[t] += red[t + s];
        __syncthreads();
    }
    float tot = red[0];
    if (t < NUM_CAPS) {
        float ln = len[t] / (tot + 1e-8f);
        lnN[t] = ln;
        outL[b * NUM_CAPS + t] = ln;
    }
    __syncthreads();
    if (t < NUM_CAPS) {
        int lo = t - 5 > 0 ? t - 5 : 0;
        int hi = t + 5 < 180 ? t + 5 : 180;
        float m = -1e30f;
        for (int o = lo; o <= hi; o++) m = fmaxf(m, lnN[o]);
        pk[t] = (lnN[t] == m) ? lnN[t] : 0.f;
    }
    __syncthreads();
    if (t == 0) {
        int sel[KSEL];
        for (int k = 0; k < KSEL; k++) {
            int best = -1; float bv = -1e30f;
            for (int o = 0; o < NUM_CAPS; o++)
                if (pk[o] > bv) { bv = pk[o]; best = o; }
            sel[k] = best;
            pk[best] = -1e30f;
        }
        for (int a = 1; a < KSEL; a++) {
            int v = sel[a], j = a - 1;
            while (j >= 0 && sel[j] > v) { sel[j + 1] = sel[j]; j--; }
            sel[j + 1] = v;
        }
        for (int k = 0; k < KSEL; k++) {
            d_idx[b * KSEL + k] = sel[k];
            const float* xp = d_x + ((size_t)b * NUM_CAPS + sel[k]) * 16;
            float* gp = d_g + (b * KSEL + k) * 16;
            for (int d = 0; d < 16; d++) gp[d] = xp[d];
        }
    }
}

// ---------------- 5) MLP -------------------------------------------------------
__global__ void fc1_kernel(const float* __restrict__ w, const float* __restrict__ bias) {
    const int r = blockIdx.y;
    const int j = blockIdx.x * 256 + threadIdx.x;  // < 1024
    __shared__ float gr[16];
    __shared__ int base;
    if (threadIdx.x < 16) gr[threadIdx.x] = d_g[r * 16 + threadIdx.x];
    if (threadIdx.x == 0) base = d_idx[r] * 16;
    __syncthreads();
    float acc = bias[j];
    #pragma unroll
    for (int d = 0; d < 16; d++) acc += gr[d] * w[(size_t)(base + d) * 1024 + j];
    d_m0[r * 1024 + j] = gelu_f(acc);
}

__global__ void gemm_kernel(int asel, int csel, const float* __restrict__ W,
                            const float* __restrict__ bias, float* cout,
                            int Kd, int N, int act, int transOut) {
    const float* A = (asel == 0) ? d_m0 : d_m1;
    float* C = (csel == 0) ? d_m0 : (csel == 1) ? d_m1 : cout;
    __shared__ float As[16][64];
    __shared__ float Ws[16][68];
    const int bm = blockIdx.y * 64, bn = blockIdx.x * 64;
    const int t = threadIdx.x, tx = t & 15, ty = t >> 4;
    float acc[4][4];
    #pragma unroll
    for (int p = 0; p < 4; p++)
        #pragma unroll
        for (int q = 0; q < 4; q++) acc[p][q] = 0.f;

    for (int k0 = 0; k0 < Kd; k0 += 16) {
        {
            int r = t >> 2, cq = (t & 3) * 4;
            float4 a = *(const float4*)&A[(size_t)(bm + r) * Kd + k0 + cq];
            As[cq + 0][r] = a.x; As[cq + 1][r] = a.y;
            As[cq + 2][r] = a.z; As[cq + 3][r] = a.w;
        }
        {
            int r = t >> 4, c4 = (t & 15) * 4;
            *(float4*)&Ws[r][c4] = *(const float4*)&W[(size_t)(k0 + r) * N + bn + c4];
        }
        __syncthreads();
        #pragma unroll
        for (int kk = 0; kk < 16; kk++) {
            float4 a4 = *(const float4*)&As[kk][ty * 4];
            float4 b4 = *(const float4*)&Ws[kk][tx * 4];
            float a[4] = {a4.x, a4.y, a4.z, a4.w};
            float bb[4] = {b4.x, b4.y, b4.z, b4.w};
            #pragma unroll
            for (int p = 0; p < 4; p++)
                #pragma unroll
                for (int q = 0; q < 4; q++) acc[p][q] += a[p] * bb[q];
        }
        __syncthreads();
    }
    #pragma unroll
    for (int p = 0; p < 4; p++) {
        #pragma unroll
        for (int q = 0; q < 4; q++) {
            int m = bm + ty * 4 + p, n = bn + tx * 4 + q;
            float v = acc[p][q] + bias[n];
            if (act) v = gelu_f(v);
            if (!transOut) C[(size_t)m * N + n] = v;
            else C[(size_t)(m >> 2) * (N * 4) + n * 4 + (m & 3)] = v;
        }
    }
}

// ---------------- launch -------------------------------------------------------
extern "C" void kernel_launch(void* const* d_in, const int* in_sizes, int n_in,
                              void* d_out, int out_size) {
    const float* scm  = (const float*)d_in[0];
    const float* c1w = (const float*)d_in[2];  const float* c1b = (const float*)d_in[3];
    const float* c2w = (const float*)d_in[4];  const float* c2b = (const float*)d_in[5];
    const float* c3w = (const float*)d_in[6];  const float* c3b = (const float*)d_in[7];
    const float* pcw = (const float*)d_in[8];  const float* pcb = (const float*)d_in[9];
    const float* capsW = (const float*)d_in[10];
    const float* capsb = (const float*)d_in[11];
    const float* f1w = (const float*)d_in[12]; const float* f1b = (const float*)d_in[13];
    const float* f2w = (const float*)d_in[14]; const float* f2b = (const float*)d_in[15];
    const float* f3w = (const float*)d_in[16]; const float* f3b = (const float*)d_in[17];
    const float* f4w = (const float*)d_in[18]; const float* f4b = (const float*)d_in[19];
    const float* f5w = (const float*)d_in[20]; const float* f5b = (const float*)d_in[21];
    const float* hw  = (const float*)d_in[22]; const float* hb  = (const float*)d_in[23];

    float* outW = (float*)d_out;                       // [512, 128, 4]
    float* outL = outW + BATCH * 128 * KSEL;           // [512, 181]

    static int smem_set = 0;
    const int smax_smem = (NUM_CAPS * 97) * sizeof(float);     // ~70.2 KB
    const int conv_smem = (192 + 6144 + 6400) * sizeof(float); // 50944 B
    if (!smem_set) {
        cudaFuncSetAttribute(softmax3_kernel,
                             cudaFuncAttributeMaxDynamicSharedMemorySize, smax_smem);
        cudaFuncSetAttribute(softmax_first_kernel,
                             cudaFuncAttributeMaxDynamicSharedMemorySize, smax_smem);
        cudaFuncSetAttribute(conv_stack_kernel,
                             cudaFuncAttributeMaxDynamicSharedMemorySize, conv_smem);
        smem_set = 1;
    }

    const int route_grid = BATCH * NUM_CAPS / 8;

    wrepack_kernel<<<(NUM_CAPS * 1536 + 255) / 256, 256>>>(capsW);                   // 1
    conv_stack_kernel<<<BATCH, 256, conv_smem>>>(scm, c1w, c1b, c2w, c2b, c3w, c3b,
                                                 pcw, pcb);                          // 2
    softmax_first_kernel<<<1, 256, smax_smem>>>(capsb);                              // 3
    uhat_mma_kernel<<<dim3(23, 96), 256>>>();                                        // 4
    route4_kernel<true,  false><<<route_grid, 256>>>(capsb);                         // 5
    softmax3_kernel<<<BATCH, 256, smax_smem>>>();                                    // 6
    route4_kernel<false, false><<<route_grid, 256>>>(capsb);                         // 7
    softmax3_kernel<<<BATCH, 256, smax_smem>>>();                                    // 8
    route4_kernel<false, true ><<<route_grid, 256>>>(capsb);                         // 9

    finalize_kernel<<<BATCH, 256>>>(outL);
    fc1_kernel<<<dim3(4, MLP_ROWS), 256>>>(f1w, f1b);
    gemm_kernel<<<dim3(12, 32), 256>>>(0, 1, f2w, f2b, nullptr, 1024, 768, 1, 0);
    gemm_kernel<<<dim3( 8, 32), 256>>>(1, 0, f3w, f3b, nullptr,  768, 512, 1, 0);
    gemm_kernel<<<dim3( 8, 32), 256>>>(0, 1, f4w, f4b, nullptr,  512, 512, 1, 0);
    gemm_kernel<<<dim3( 4, 32), 256>>>(1, 0, f5w, f5b, nullptr,  512, 256, 1, 0);
    gemm_kernel<<<dim3( 2, 32), 256>>>(0, 2, hw,  hb,  outW,     256, 128, 0, 1);
}

// round 9
// speedup vs baseline: 3.3812x; 1.1237x over previous
#include <cuda_runtime.h>
#include <cuda_fp16.h>
#include <math.h>

#define BATCH 512
#define NUM_CAPS 181
#define IN_CAPS 96
#define CAPS_DIM 16
#define KSEL 4
#define OI (NUM_CAPS * IN_CAPS)          // 17376
#define UHAT_TILE (IN_CAPS * CAPS_DIM)   // 1536
#define MLP_ROWS (BATCH * KSEL)          // 2048
#define NTOT (NUM_CAPS * CAPS_DIM)       // 2896

// ---------------- scratch (device globals; no allocation allowed) -------------
__device__ __half d_uh[IN_CAPS * BATCH * CAPS_DIM];                // u fp16, [i][b][k]
__device__ __half d_vh[(size_t)IN_CAPS * NTOT * CAPS_DIM];         // W repack, [i][n][k]
__device__ __half d_uhat[(size_t)BATCH * NUM_CAPS * IN_CAPS * CAPS_DIM]; // 285 MB
__device__ float  d_bl[BATCH * OI];                                // 35.6 MB
__device__ float2 d_ms[BATCH * IN_CAPS];                           // softmax stats
__device__ float  d_x[BATCH * NUM_CAPS * CAPS_DIM];                // 5.9 MB
__device__ int    d_idx[BATCH * KSEL];
__device__ float  d_g[MLP_ROWS * CAPS_DIM];
__device__ float  d_m0[MLP_ROWS * 1024];
__device__ float  d_m1[MLP_ROWS * 1024];

__device__ __forceinline__ float gelu_f(float x) {
    return 0.5f * x * (1.0f + erff(x * 0.70710678118654752f));
}

// ---------------- 0) W repack: capsW[o][i][d][k] -> d_vh[i][o*16+d][k] fp16 ----
__global__ void wrepack_kernel(const float* __restrict__ capsW) {
    int idx = blockIdx.x * 256 + threadIdx.x;      // o*1536 + i*16 + d
    if (idx >= NUM_CAPS * 1536) return;
    int o = idx / 1536, r = idx % 1536, i = r >> 4, d = r & 15;
    const float* src = capsW + ((size_t)(o * 96 + i) * 16 + d) * 16;
    __half* dst = d_vh + ((size_t)i * NTOT + o * 16 + d) * 16;
    #pragma unroll
    for (int k = 0; k < 16; k++) dst[k] = __float2half(src[k]);
}

// ---------------- 1) fused conv stack + primary caps + squash ------------------
#define LD8(dst, ptr) do { \
    float4 _a = *(const float4*)(ptr); \
    float4 _b = *(const float4*)((ptr) + 4); \
    dst[0]=_a.x; dst[1]=_a.y; dst[2]=_a.z; dst[3]=_a.w; \
    dst[4]=_b.x; dst[5]=_b.y; dst[6]=_b.z; dst[7]=_b.w; } while (0)

#define CROW(top, bot, acc, yy, W) do { \
    _Pragma("unroll") \
    for (int _x = 0; _x < (W); _x++) \
        acc[(yy)*(W)+_x] += top[_x]*w.x + top[_x+1]*w.y + bot[_x]*w.z + bot[_x+1]*w.w; \
    } while (0)

__global__ __launch_bounds__(256, 4) void conv_stack_kernel(
        const float* __restrict__ scm,
        const float* __restrict__ w1, const float* __restrict__ b1,
        const float* __restrict__ w2, const float* __restrict__ b2,
        const float* __restrict__ w3, const float* __restrict__ b3,
        const float* __restrict__ pw, const float* __restrict__ pb) {
    extern __shared__ float smem[];
    float* s_in = smem;            // 192
    float* Y    = smem + 192;      // 6144: c2 out [128][6][8]; later u[1536]
    float* X    = smem + 6336;     // 6400: c1 out [64][7][8]; later c3 [256][25]
    const int b = blockIdx.x, t = threadIdx.x;

    const float* in = scm + b * 192;
    for (int i = t; i < 192; i += 256) s_in[i] = in[i];
    __syncthreads();

    // conv1: 3x8x8 -> 64x[7][8] padded
    for (int idx = t; idx < 64 * 49; idx += 256) {
        int oc = idx / 49, r = idx % 49, y = r / 7, x = r % 7;
        float acc = b1[oc];
        const float* wp = w1 + oc * 12;
        #pragma unroll
        for (int ic = 0; ic < 3; ic++) {
            const float* ip = s_in + ic * 64 + y * 8 + x;
            acc += ip[0]*wp[0] + ip[1]*wp[1] + ip[8]*wp[2] + ip[9]*wp[3];
            wp += 4;
        }
        X[oc * 56 + y * 8 + x] = gelu_f(acc);
    }
    __syncthreads();

    // conv2: 64x7x7 (X) -> 128x[6][8] (Y)
    {
        const int oc = t & 127, half = t >> 7, y0 = half * 3;
        float acc[18];
        #pragma unroll
        for (int p = 0; p < 18; p++) acc[p] = 0.f;
        for (int ic = 0; ic < 64; ic++) {
            float4 w = *(const float4*)(w2 + oc * 256 + ic * 4);
            const float* Xc = X + ic * 56 + y0 * 8;
            float r0[8], r1[8];
            LD8(r0, Xc);
            LD8(r1, Xc + 8);
            CROW(r0, r1, acc, 0, 6);
            LD8(r0, Xc + 16);
            CROW(r1, r0, acc, 1, 6);
            LD8(r1, Xc + 24);
            CROW(r0, r1, acc, 2, 6);
        }
        float bb = b2[oc];
        #pragma unroll
        for (int yy = 0; yy < 3; yy++)
            #pragma unroll
            for (int x = 0; x < 6; x++)
                Y[oc * 48 + (y0 + yy) * 8 + x] = gelu_f(acc[yy*6+x] + bb);
    }
    __syncthreads();

    // conv3: 128x[6][8] (Y) -> 256x25 compact (X)
    {
        const int oc = t;
        float acc[25];
        #pragma unroll
        for (int p = 0; p < 25; p++) acc[p] = 0.f;
        for (int ic = 0; ic < 128; ic++) {
            float4 w = *(const float4*)(w3 + oc * 512 + ic * 4);
            const float* Yc = Y + ic * 48;
            float r0[8], r1[8];
            LD8(r0, Yc);
            LD8(r1, Yc + 8);
            CROW(r0, r1, acc, 0, 5);
            LD8(r0, Yc + 16);
            CROW(r1, r0, acc, 1, 5);
            LD8(r1, Yc + 24);
            CROW(r0, r1, acc, 2, 5);
            LD8(r0, Yc + 32);
            CROW(r1, r0, acc, 3, 5);
            LD8(r1, Yc + 40);
            CROW(r0, r1, acc, 4, 5);
        }
        float bb = b3[oc];
        __syncthreads();
        #pragma unroll
        for (int p = 0; p < 25; p++) X[oc * 25 + p] = gelu_f(acc[p] + bb);
    }
    __syncthreads();

    // primary caps: 256x25 (X) -> 96x4x4 -> Y[0..1536)
    if (t < 192) {
        const int g = t >> 1, half = t & 1, y0 = half * 2;
        float acc[8];
        #pragma unroll
        for (int p = 0; p < 8; p++) acc[p] = 0.f;
        for (int ic = 0; ic < 256; ic++) {
            float4 w = *(const float4*)(pw + g * 1024 + ic * 4);
            const float* ip = X + ic * 25 + y0 * 5;
            float r0[5], r1[5];
            #pragma unroll
            for (int x = 0; x < 5; x++) r0[x] = ip[x];
            #pragma unroll
            for (int x = 0; x < 5; x++) r1[x] = ip[5 + x];
            CROW(r0, r1, acc, 0, 4);
            #pragma unroll
            for (int x = 0; x < 5; x++) r0[x] = ip[10 + x];
            CROW(r1, r0, acc, 1, 4);
        }
        float bb = pb[g];
        #pragma unroll
        for (int yy = 0; yy < 2; yy++)
            #pragma unroll
            for (int x = 0; x < 4; x++)
                Y[g * 16 + (y0 + yy) * 4 + x] = acc[yy*4+x] + bb;
    }
    __syncthreads();

    // squash per capsule; store fp16 u as [i][b][k]
    if (t < 96) {
        float n2 = 0.f;
        #pragma unroll
        for (int d = 0; d < 16; d++) { float v = Y[t * 16 + d]; n2 += v * v; }
        float n = sqrtf(n2);
        float sc = (1.0f - expf(-n)) / (n + 1e-8f);
        __half2* up = (__half2*)(d_uh + ((size_t)t * BATCH + b) * 16);
        #pragma unroll
        for (int q = 0; q < 8; q++)
            up[q] = __floats2half2_rn(Y[t*16 + 2*q] * sc, Y[t*16 + 2*q + 1] * sc);
    }
}

// ---------------- 2) u_hat via tensor cores, smem-staged coalesced stores ------
// Dynamic smem: As (512x16 halves, 16KB) + 8 per-warp staging tiles
// (16 x 136 halves each, 4.25KB) = 51200 B total.
#define STG_STRIDE 136
#define UHAT_SMEM (512 * 16 * 2 + 8 * 16 * STG_STRIDE * 2)
__global__ __launch_bounds__(256) void uhat_mma_kernel() {
    extern __shared__ __half hsmem[];
    __half* As = hsmem;                              // 512*16
    const int i = blockIdx.y;
    const int n0 = blockIdx.x * 128;
    const int warp = threadIdx.x >> 5, lane = threadIdx.x & 31;
    __half* st = hsmem + 512 * 16 + warp * (16 * STG_STRIDE);

    {
        const uint4* src = (const uint4*)(d_uh + (size_t)i * BATCH * 16);
        uint4* dst = (uint4*)As;
        for (int t2 = threadIdx.x; t2 < 1024; t2 += 256) dst[t2] = src[t2];
    }
    __syncthreads();

    const int nrem = NTOT - n0;
    const int no = nrem >> 4;                        // o-count in chunk: 8 or 5
    const int obase = n0 >> 4;
    const __half* Vb = d_vh + (size_t)i * NTOT * 16;

    unsigned bf0[16], bf1[16];
    #pragma unroll
    for (int tn = 0; tn < 16; tn++) {
        if (tn * 8 < nrem) {
            int n = n0 + tn * 8 + (lane >> 2);
            const __half* p = Vb + n * 16 + (lane & 3) * 2;
            bf0[tn] = *(const unsigned*)(p);
            bf1[tn] = *(const unsigned*)(p + 8);
        } else { bf0[tn] = 0u; bf1[tn] = 0u; }
    }

    #pragma unroll
    for (int mt = 0; mt < 4; mt++) {
        const int m0 = warp * 64 + mt * 16;          // warp in [0,8): rows 0..511
        const __half* ap = As + (m0 + (lane >> 2)) * 16 + (lane & 3) * 2;
        unsigned a0 = *(const unsigned*)(ap);
        unsigned a1 = *(const unsigned*)(ap + 8 * 16);
        unsigned a2 = *(const unsigned*)(ap + 8);
        unsigned a3 = *(const unsigned*)(ap + 8 * 16 + 8);
        const int rb = lane >> 2, col = 2 * (lane & 3);
        #pragma unroll
        for (int tn = 0; tn < 16; tn++) {
            if (tn * 8 < nrem) {
                float e0, e1, e2, e3;
                asm volatile(
                    "mma.sync.aligned.m16n8k16.row.col.f32.f16.f16.f32 "
                    "{%0,%1,%2,%3}, {%4,%5,%6,%7}, {%8,%9}, {%10,%11,%12,%13};"
                    : "=f"(e0), "=f"(e1), "=f"(e2), "=f"(e3)
                    : "r"(a0), "r"(a1), "r"(a2), "r"(a3),
                      "r"(bf0[tn]), "r"(bf1[tn]),
                      "f"(0.f), "f"(0.f), "f"(0.f), "f"(0.f));
                int c = tn * 8 + col;
                *(__half2*)&st[rb * STG_STRIDE + c]       = __floats2half2_rn(e0, e1);
                *(__half2*)&st[(rb + 8) * STG_STRIDE + c] = __floats2half2_rn(e2, e3);
            }
        }
        __syncwarp();
        // coalesced flush: lane pairs cover one 32B gmem row (b,o fixed, 16 d)
        #pragma unroll
        for (int q = 0; q < 8; q++) {
            int v = q * 32 + lane;               // [0, 256)
            int gr = v >> 1;                     // [0, 128): rb2 = gr&15, ol = gr>>4
            int rb2 = gr & 15, ol = gr >> 4, h = v & 1;
            if (ol < no) {
                uint4 val = *(const uint4*)&st[rb2 * STG_STRIDE + ol * 16 + h * 8];
                *(uint4*)(d_uhat + ((size_t)((m0 + rb2) * NUM_CAPS + obase + ol) * 96
                                    + i) * 16 + h * 8) = val;
            }
        }
        __syncwarp();
    }
}

// ---------------- 3) routing ---------------------------------------------------
__global__ void softmax_first_kernel(const float* __restrict__ caps_b) {
    extern __shared__ float sb[];            // 181*97 floats
    const int t = threadIdx.x;
    for (int e = t; e < OI; e += 256) sb[(e / 96) * 97 + (e % 96)] = caps_b[e];
    __syncthreads();
    const int wid = t >> 5, lane = t & 31;
    for (int i = wid; i < 96; i += 8) {
        float m = -1e30f;
        for (int o = lane; o < NUM_CAPS; o += 32) m = fmaxf(m, sb[o * 97 + i]);
        #pragma unroll
        for (int s = 16; s; s >>= 1) m = fmaxf(m, __shfl_xor_sync(0xffffffffu, m, s));
        float s = 0.f;
        for (int o = lane; o < NUM_CAPS; o += 32) s += expf(sb[o * 97 + i] - m);
        #pragma unroll
        for (int sh = 16; sh; sh >>= 1) s += __shfl_xor_sync(0xffffffffu, s, sh);
        if (lane == 0) d_ms[i] = make_float2(m, 1.0f / s);
    }
}

__global__ void softmax3_kernel() {
    extern __shared__ float sb[];            // 181*97 floats
    const int b = blockIdx.x, t = threadIdx.x;
    const float* blp = d_bl + (size_t)b * OI;
    for (int e = t; e < OI; e += 256) sb[(e / 96) * 97 + (e % 96)] = blp[e];
    __syncthreads();
    const int wid = t >> 5, lane = t & 31;
    for (int i = wid; i < 96; i += 8) {
        float m = -1e30f;
        for (int o = lane; o < NUM_CAPS; o += 32) m = fmaxf(m, sb[o * 97 + i]);
        #pragma unroll
        for (int s = 16; s; s >>= 1) m = fmaxf(m, __shfl_xor_sync(0xffffffffu, m, s));
        float s = 0.f;
        for (int o = lane; o < NUM_CAPS; o += 32) s += expf(sb[o * 97 + i] - m);
        #pragma unroll
        for (int sh = 16; sh; sh >>= 1) s += __shfl_xor_sync(0xffffffffu, s, sh);
        if (lane == 0) d_ms[b * 96 + i] = make_float2(m, 1.0f / s);
    }
}

template<bool FIRST, bool LAST>
__global__ __launch_bounds__(256) void route4_kernel(const float* __restrict__ caps_b) {
    __shared__ float incsh[8][96];
    const int wid = threadIdx.x >> 5, lane = threadIdx.x & 31;
    const int w = blockIdx.x * 8 + wid;            // w = b*181 + o
    const int b = w / NUM_CAPS;
    const uint4* up = (const uint4*)(d_uhat + (size_t)w * UHAT_TILE);
    float* blp = d_bl + (size_t)w * 96;

    float bl0, bl1, bl2;
    if (FIRST) {
        const int o = w - b * NUM_CAPS;
        const float* cbp = caps_b + o * 96;
        bl0 = cbp[lane]; bl1 = cbp[32 + lane]; bl2 = cbp[64 + lane];
    } else {
        bl0 = blp[lane]; bl1 = blp[32 + lane]; bl2 = blp[64 + lane];
    }
    const float2* msp = FIRST ? d_ms : (d_ms + b * 96);
    float2 ms0 = msp[lane], ms1 = msp[32 + lane], ms2 = msp[64 + lane];
    float c0 = expf(bl0 - ms0.x) * ms0.y;
    float c1 = expf(bl1 - ms1.x) * ms1.y;
    float c2 = expf(bl2 - ms2.x) * ms2.y;

    uint4 uv[6];
    float acc[8];
    #pragma unroll
    for (int q = 0; q < 8; q++) acc[q] = 0.f;
    #pragma unroll
    for (int j = 0; j < 6; j++) {
        uv[j] = up[j * 32 + lane];
        float cr = (j < 2) ? c0 : (j < 4) ? c1 : c2;
        float cv = __shfl_sync(0xffffffffu, cr, ((j & 1) << 4) + (lane >> 1));
        const __half2* h = (const __half2*)&uv[j];
        #pragma unroll
        for (int q = 0; q < 4; q++) {
            float2 f = __half22float2(h[q]);
            acc[2*q]   += cv * f.x;
            acc[2*q+1] += cv * f.y;
        }
    }
    #pragma unroll
    for (int m = 2; m <= 16; m <<= 1)
        #pragma unroll
        for (int q = 0; q < 8; q++)
            acc[q] += __shfl_xor_sync(0xffffffffu, acc[q], m);
    float sq = 0.f;
    #pragma unroll
    for (int q = 0; q < 8; q++) sq += acc[q] * acc[q];
    sq += __shfl_xor_sync(0xffffffffu, sq, 1);
    float n = sqrtf(sq);
    float sc = (1.0f - expf(-n)) / (n + 1e-8f);
    #pragma unroll
    for (int q = 0; q < 8; q++) acc[q] *= sc;

    if (LAST) {
        if (lane < 2) {
            float4* xp = (float4*)(d_x + (size_t)w * 16);
            xp[lane * 2 + 0] = make_float4(acc[0], acc[1], acc[2], acc[3]);
            xp[lane * 2 + 1] = make_float4(acc[4], acc[5], acc[6], acc[7]);
        }
    } else {
        #pragma unroll
        for (int j = 0; j < 6; j++) {
            const __half2* h = (const __half2*)&uv[j];
            float p = 0.f;
            #pragma unroll
            for (int q = 0; q < 4; q++) {
                float2 f = __half22float2(h[q]);
                p += acc[2*q] * f.x + acc[2*q+1] * f.y;
            }
            p += __shfl_xor_sync(0xffffffffu, p, 1);
            if (!(lane & 1)) incsh[wid][j * 16 + (lane >> 1)] = p;
        }
        __syncwarp();
        blp[lane]      = bl0 + incsh[wid][lane];
        blp[32 + lane] = bl1 + incsh[wid][32 + lane];
        blp[64 + lane] = bl2 + incsh[wid][64 + lane];
    }
}

// ---------------- 4) length, peaks, top-K, gather ------------------------------
__global__ void finalize_kernel(float* __restrict__ outL) {
    const int b = blockIdx.x, t = threadIdx.x; // 256 threads
    __shared__ float len[192], lnN[192], pk[192], red[256];
    float L = 0.f;
    if (t < NUM_CAPS) {
        const float* xp = d_x + ((size_t)b * NUM_CAPS + t) * 16;
        float n2 = 0.f;
        #pragma unroll
        for (int d = 0; d < 16; d++) { float v = xp[d]; n2 += v * v; }
        L = sqrtf(n2);
        len[t] = L;
    }
    red[t] = (t < NUM_CAPS) ? L : 0.f;
    __syncthreads();
    for (int s = 128; s > 0; s >>= 1) {
        if (t < s) red[t] += red[t + s];
        __syncthreads();
    }
    float tot = red[0];
    if (t < NUM_CAPS) {
        float ln = len[t] / (tot + 1e-8f);
        lnN[t] = ln;
        outL[b * NUM_CAPS + t] = ln;
    }
    __syncthreads();
    if (t < NUM_CAPS) {
        int lo = t - 5 > 0 ? t - 5 : 0;
        int hi = t + 5 < 180 ? t + 5 : 180;
        float m = -1e30f;
        for (int o = lo; o <= hi; o++) m = fmaxf(m, lnN[o]);
        pk[t] = (lnN[t] == m) ? lnN[t] : 0.f;
    }
    __syncthreads();
    if (t == 0) {
        int sel[KSEL];
        for (int k = 0; k < KSEL; k++) {
            int best = -1; float bv = -1e30f;
            for (int o = 0; o < NUM_CAPS; o++)
                if (pk[o] > bv) { bv = pk[o]; best = o; }
            sel[k] = best;
            pk[best] = -1e30f;
        }
        for (int a = 1; a < KSEL; a++) {
            int v = sel[a], j = a - 1;
            while (j >= 0 && sel[j] > v) { sel[j + 1] = sel[j]; j--; }
            sel[j + 1] = v;
        }
        for (int k = 0; k < KSEL; k++) {
            d_idx[b * KSEL + k] = sel[k];
            const float* xp = d_x + ((size_t)b * NUM_CAPS + sel[k]) * 16;
            float* gp = d_g + (b * KSEL + k) * 16;
            for (int d = 0; d < 16; d++) gp[d] = xp[d];
        }
    }
}

// ---------------- 5) MLP -------------------------------------------------------
__global__ void fc1_kernel(const float* __restrict__ w, const float* __restrict__ bias) {
    const int r = blockIdx.y;
    const int j = blockIdx.x * 256 + threadIdx.x;  // < 1024
    __shared__ float gr[16];
    __shared__ int base;
    if (threadIdx.x < 16) gr[threadIdx.x] = d_g[r * 16 + threadIdx.x];
    if (threadIdx.x == 0) base = d_idx[r] * 16;
    __syncthreads();
    float acc = bias[j];
    #pragma unroll
    for (int d = 0; d < 16; d++) acc += gr[d] * w[(size_t)(base + d) * 1024 + j];
    d_m0[r * 1024 + j] = gelu_f(acc);
}

__global__ void gemm_kernel(int asel, int csel, const float* __restrict__ W,
                            const float* __restrict__ bias, float* cout,
                            int Kd, int N, int act, int transOut) {
    const float* A = (asel == 0) ? d_m0 : d_m1;
    float* C = (csel == 0) ? d_m0 : (csel == 1) ? d_m1 : cout;
    __shared__ float As[16][64];
    __shared__ float Ws[16][68];
    const int bm = blockIdx.y * 64, bn = blockIdx.x * 64;
    const int t = threadIdx.x, tx = t & 15, ty = t >> 4;
    float acc[4][4];
    #pragma unroll
    for (int p = 0; p < 4; p++)
        #pragma unroll
        for (int q = 0; q < 4; q++) acc[p][q] = 0.f;

    for (int k0 = 0; k0 < Kd; k0 += 16) {
        {
            int r = t >> 2, cq = (t & 3) * 4;
            float4 a = *(const float4*)&A[(size_t)(bm + r) * Kd + k0 + cq];
            As[cq + 0][r] = a.x; As[cq + 1][r] = a.y;
            As[cq + 2][r] = a.z; As[cq + 3][r] = a.w;
        }
        {
            int r = t >> 4, c4 = (t & 15) * 4;
            *(float4*)&Ws[r][c4] = *(const float4*)&W[(size_t)(k0 + r) * N + bn + c4];
        }
        __syncthreads();
        #pragma unroll
        for (int kk = 0; kk < 16; kk++) {
            float4 a4 = *(const float4*)&As[kk][ty * 4];
            float4 b4 = *(const float4*)&Ws[kk][tx * 4];
            float a[4] = {a4.x, a4.y, a4.z, a4.w};
            float bb[4] = {b4.x, b4.y, b4.z, b4.w};
            #pragma unroll
            for (int p = 0; p < 4; p++)
                #pragma unroll
                for (int q = 0; q < 4; q++) acc[p][q] += a[p] * bb[q];
        }
        __syncthreads();
    }
    #pragma unroll
    for (int p = 0; p < 4; p++) {
        #pragma unroll
        for (int q = 0; q < 4; q++) {
            int m = bm + ty * 4 + p, n = bn + tx * 4 + q;
            float v = acc[p][q] + bias[n];
            if (act) v = gelu_f(v);
            if (!transOut) C[(size_t)m * N + n] = v;
            else C[(size_t)(m >> 2) * (N * 4) + n * 4 + (m & 3)] = v;
        }
    }
}

// ---------------- launch -------------------------------------------------------
extern "C" void kernel_launch(void* const* d_in, const int* in_sizes, int n_in,
                              void* d_out, int out_size) {
    const float* scm  = (const float*)d_in[0];
    const float* c1w = (const float*)d_in[2];  const float* c1b = (const float*)d_in[3];
    const float* c2w = (const float*)d_in[4];  const float* c2b = (const float*)d_in[5];
    const float* c3w = (const float*)d_in[6];  const float* c3b = (const float*)d_in[7];
    const float* pcw = (const float*)d_in[8];  const float* pcb = (const float*)d_in[9];
    const float* capsW = (const float*)d_in[10];
    const float* capsb = (const float*)d_in[11];
    const float* f1w = (const float*)d_in[12]; const float* f1b = (const float*)d_in[13];
    const float* f2w = (const float*)d_in[14]; const float* f2b = (const float*)d_in[15];
    const float* f3w = (const float*)d_in[16]; const float* f3b = (const float*)d_in[17];
    const float* f4w = (const float*)d_in[18]; const float* f4b = (const float*)d_in[19];
    const float* f5w = (const float*)d_in[20]; const float* f5b = (const float*)d_in[21];
    const float* hw  = (const float*)d_in[22]; const float* hb  = (const float*)d_in[23];

    float* outW = (float*)d_out;                       // [512, 128, 4]
    float* outL = outW + BATCH * 128 * KSEL;           // [512, 181]

    static int smem_set = 0;
    const int smax_smem = (NUM_CAPS * 97) * sizeof(float);     // ~70.2 KB
    const int conv_smem = (192 + 6144 + 6400) * sizeof(float); // 50944 B
    if (!smem_set) {
        cudaFuncSetAttribute(softmax3_kernel,
                             cudaFuncAttributeMaxDynamicSharedMemorySize, smax_smem);
        cudaFuncSetAttribute(softmax_first_kernel,
                             cudaFuncAttributeMaxDynamicSharedMemorySize, smax_smem);
        cudaFuncSetAttribute(conv_stack_kernel,
                             cudaFuncAttributeMaxDynamicSharedMemorySize, conv_smem);
        cudaFuncSetAttribute(uhat_mma_kernel,
                             cudaFuncAttributeMaxDynamicSharedMemorySize, UHAT_SMEM);
        smem_set = 1;
    }

    const int route_grid = BATCH * NUM_CAPS / 8;

    wrepack_kernel<<<(NUM_CAPS * 1536 + 255) / 256, 256>>>(capsW);                   // 1
    conv_stack_kernel<<<BATCH, 256, conv_smem>>>(scm, c1w, c1b, c2w, c2b, c3w, c3b,
                                                 pcw, pcb);                          // 2
    softmax_first_kernel<<<1, 256, smax_smem>>>(capsb);                              // 3
    uhat_mma_kernel<<<dim3(23, 96), 256, UHAT_SMEM>>>();                             // 4 (ncu)
    route4_kernel<true,  false><<<route_grid, 256>>>(capsb);                         // 5
    softmax3_kernel<<<BATCH, 256, smax_smem>>>();                                    // 6
    route4_kernel<false, false><<<route_grid, 256>>>(capsb);                         // 7
    softmax3_kernel<<<BATCH, 256, smax_smem>>>();                                    // 8
    route4_kernel<false, true ><<<route_grid, 256>>>(capsb);                         // 9

    finalize_kernel<<<BATCH, 256>>>(outL);
    fc1_kernel<<<dim3(4, MLP_ROWS), 256>>>(f1w, f1b);
    gemm_kernel<<<dim3(12, 32), 256>>>(0, 1, f2w, f2b, nullptr, 1024, 768, 1, 0);
    gemm_kernel<<<dim3( 8, 32), 256>>>(1, 0, f3w, f3b, nullptr,  768, 512, 1, 0);
    gemm_kernel<<<dim3( 8, 32), 256>>>(0, 1, f4w, f4b, nullptr,  512, 512, 1, 0);
    gemm_kernel<<<dim3( 4, 32), 256>>>(1, 0, f5w, f5b, nullptr,  512, 256, 1, 0);
    gemm_kernel<<<dim3( 2, 32), 256>>>(0, 2, hw,  hb,  outW,     256, 128, 0, 1);
}

// round 13
// speedup vs baseline: 4.0759x; 1.2055x over previous
#include <cuda_runtime.h>
#include <cuda_fp16.h>
#include <math.h>

#define BATCH 512
#define NUM_CAPS 181
#define IN_CAPS 96
#define CAPS_DIM 16
#define KSEL 4
#define OI (NUM_CAPS * IN_CAPS)          // 17376
#define UHAT_TILE (IN_CAPS * CAPS_DIM)   // 1536
#define MLP_ROWS (BATCH * KSEL)          // 2048
#define NTOT (NUM_CAPS * CAPS_DIM)       // 2896

// transposed fp16 MLP weight offsets inside d_wt
#define OFF2 0                       // fc2: 768 x 1024
#define OFF3 786432                  // fc3: 512 x 768
#define OFF4 1179648                 // fc4: 512 x 512
#define OFF5 1441792                 // fc5: 256 x 512
#define OFFH 1572864                 // head: 128 x 256
#define WT_TOTAL 1605632

// ---------------- scratch (device globals; no allocation allowed) -------------
__device__ __half d_uh[IN_CAPS * BATCH * CAPS_DIM];                // u fp16, [i][b][k]
__device__ __half d_vh[(size_t)IN_CAPS * NTOT * CAPS_DIM];         // W repack, [i][n][k]
__device__ __half d_uhat[(size_t)BATCH * NUM_CAPS * IN_CAPS * CAPS_DIM]; // 285 MB
__device__ float  d_bl[BATCH * OI];                                // 35.6 MB
__device__ float2 d_ms[BATCH * IN_CAPS];                           // softmax stats
__device__ float  d_x[BATCH * NUM_CAPS * CAPS_DIM];                // 5.9 MB
__device__ int    d_idx[BATCH * KSEL];
__device__ float  d_g[MLP_ROWS * CAPS_DIM];
__device__ __half d_m0h[MLP_ROWS * 1024];
__device__ __half d_m1h[MLP_ROWS * 1024];
__device__ __half d_wt[WT_TOTAL];

__device__ __forceinline__ float gelu_f(float x) {
    return 0.5f * x * (1.0f + erff(x * 0.70710678118654752f));
}

// ---------------- 0) W repack: capsW[o][i][d][k] -> d_vh[i][o*16+d][k] fp16 ----
__global__ void wrepack_kernel(const float* __restrict__ capsW) {
    int idx = blockIdx.x * 256 + threadIdx.x;      // o*1536 + i*16 + d
    if (idx >= NUM_CAPS * 1536) return;
    int o = idx / 1536, r = idx % 1536, i = r >> 4, d = r & 15;
    const float* src = capsW + ((size_t)(o * 96 + i) * 16 + d) * 16;
    __half* dst = d_vh + ((size_t)i * NTOT + o * 16 + d) * 16;
    #pragma unroll
    for (int k = 0; k < 16; k++) dst[k] = __float2half(src[k]);
}

// ---------------- 0b) MLP weight transpose repack: W[k][n] f32 -> Wt[n][k] f16 -
__global__ void wtrepack_kernel(const float* __restrict__ src, int Kd, int N, int off) {
    int idx = blockIdx.x * 256 + threadIdx.x;      // n*Kd + k (write-coalesced)
    if (idx >= Kd * N) return;
    int n = idx / Kd, k = idx % Kd;
    d_wt[off + idx] = __float2half(src[(size_t)k * N + n]);
}

// ---------------- 1) fused conv stack + primary caps + squash ------------------
#define LD8(dst, ptr) do { \
    float4 _a = *(const float4*)(ptr); \
    float4 _b = *(const float4*)((ptr) + 4); \
    dst[0]=_a.x; dst[1]=_a.y; dst[2]=_a.z; dst[3]=_a.w; \
    dst[4]=_b.x; dst[5]=_b.y; dst[6]=_b.z; dst[7]=_b.w; } while (0)

#define CROW(top, bot, acc, yy, W) do { \
    _Pragma("unroll") \
    for (int _x = 0; _x < (W); _x++) \
        acc[(yy)*(W)+_x] += top[_x]*w.x + top[_x+1]*w.y + bot[_x]*w.z + bot[_x+1]*w.w; \
    } while (0)

__global__ __launch_bounds__(256, 4) void conv_stack_kernel(
        const float* __restrict__ scm,
        const float* __restrict__ w1, const float* __restrict__ b1,
        const float* __restrict__ w2, const float* __restrict__ b2,
        const float* __restrict__ w3, const float* __restrict__ b3,
        const float* __restrict__ pw, const float* __restrict__ pb) {
    extern __shared__ float smem[];
    float* s_in = smem;            // 192
    float* Y    = smem + 192;      // 6144: c2 out [128][6][8]; later u[1536]
    float* X    = smem + 6336;     // 6400: c1 out [64][7][8]; later c3 [256][25]
    const int b = blockIdx.x, t = threadIdx.x;

    const float* in = scm + b * 192;
    for (int i = t; i < 192; i += 256) s_in[i] = in[i];
    __syncthreads();

    // conv1: 3x8x8 -> 64x[7][8] padded
    for (int idx = t; idx < 64 * 49; idx += 256) {
        int oc = idx / 49, r = idx % 49, y = r / 7, x = r % 7;
        float acc = b1[oc];
        const float* wp = w1 + oc * 12;
        #pragma unroll
        for (int ic = 0; ic < 3; ic++) {
            const float* ip = s_in + ic * 64 + y * 8 + x;
            acc += ip[0]*wp[0] + ip[1]*wp[1] + ip[8]*wp[2] + ip[9]*wp[3];
            wp += 4;
        }
        X[oc * 56 + y * 8 + x] = gelu_f(acc);
    }
    __syncthreads();

    // conv2: 64x7x7 (X) -> 128x[6][8] (Y)
    {
        const int oc = t & 127, half = t >> 7, y0 = half * 3;
        float acc[18];
        #pragma unroll
        for (int p = 0; p < 18; p++) acc[p] = 0.f;
        for (int ic = 0; ic < 64; ic++) {
            float4 w = *(const float4*)(w2 + oc * 256 + ic * 4);
            const float* Xc = X + ic * 56 + y0 * 8;
            float r0[8], r1[8];
            LD8(r0, Xc);
            LD8(r1, Xc + 8);
            CROW(r0, r1, acc, 0, 6);
            LD8(r0, Xc + 16);
            CROW(r1, r0, acc, 1, 6);
            LD8(r1, Xc + 24);
            CROW(r0, r1, acc, 2, 6);
        }
        float bb = b2[oc];
        #pragma unroll
        for (int yy = 0; yy < 3; yy++)
            #pragma unroll
            for (int x = 0; x < 6; x++)
                Y[oc * 48 + (y0 + yy) * 8 + x] = gelu_f(acc[yy*6+x] + bb);
    }
    __syncthreads();

    // conv3: 128x[6][8] (Y) -> 256x25 compact (X)
    {
        const int oc = t;
        float acc[25];
        #pragma unroll
        for (int p = 0; p < 25; p++) acc[p] = 0.f;
        for (int ic = 0; ic < 128; ic++) {
            float4 w = *(const float4*)(w3 + oc * 512 + ic * 4);
            const float* Yc = Y + ic * 48;
            float r0[8], r1[8];
            LD8(r0, Yc);
            LD8(r1, Yc + 8);
            CROW(r0, r1, acc, 0, 5);
            LD8(r0, Yc + 16);
            CROW(r1, r0, acc, 1, 5);
            LD8(r1, Yc + 24);
            CROW(r0, r1, acc, 2, 5);
            LD8(r0, Yc + 32);
            CROW(r1, r0, acc, 3, 5);
            LD8(r1, Yc + 40);
            CROW(r0, r1, acc, 4, 5);
        }
        float bb = b3[oc];
        __syncthreads();
        #pragma unroll
        for (int p = 0; p < 25; p++) X[oc * 25 + p] = gelu_f(acc[p] + bb);
    }
    __syncthreads();

    // primary caps: 256x25 (X) -> 96x4x4 -> Y[0..1536)
    if (t < 192) {
        const int g = t >> 1, half = t & 1, y0 = half * 2;
        float acc[8];
        #pragma unroll
        for (int p = 0; p < 8; p++) acc[p] = 0.f;
        for (int ic = 0; ic < 256; ic++) {
            float4 w = *(const float4*)(pw + g * 1024 + ic * 4);
            const float* ip = X + ic * 25 + y0 * 5;
            float r0[5], r1[5];
            #pragma unroll
            for (int x = 0; x < 5; x++) r0[x] = ip[x];
            #pragma unroll
            for (int x = 0; x < 5; x++) r1[x] = ip[5 + x];
            CROW(r0, r1, acc, 0, 4);
            #pragma unroll
            for (int x = 0; x < 5; x++) r0[x] = ip[10 + x];
            CROW(r1, r0, acc, 1, 4);
        }
        float bb = pb[g];
        #pragma unroll
        for (int yy = 0; yy < 2; yy++)
            #pragma unroll
            for (int x = 0; x < 4; x++)
                Y[g * 16 + (y0 + yy) * 4 + x] = acc[yy*4+x] + bb;
    }
    __syncthreads();

    // squash per capsule; store fp16 u as [i][b][k]
    if (t < 96) {
        float n2 = 0.f;
        #pragma unroll
        for (int d = 0; d < 16; d++) { float v = Y[t * 16 + d]; n2 += v * v; }
        float n = sqrtf(n2);
        float sc = (1.0f - expf(-n)) / (n + 1e-8f);
        __half2* up = (__half2*)(d_uh + ((size_t)t * BATCH + b) * 16);
        #pragma unroll
        for (int q = 0; q < 8; q++)
            up[q] = __floats2half2_rn(Y[t*16 + 2*q] * sc, Y[t*16 + 2*q + 1] * sc);
    }
}

// ---------------- 2) u_hat via tensor cores, smem-staged coalesced stores ------
#define STG_STRIDE 136
#define UHAT_SMEM (512 * 16 * 2 + 8 * 16 * STG_STRIDE * 2)
__global__ __launch_bounds__(256) void uhat_mma_kernel() {
    extern __shared__ __half hsmem[];
    __half* As = hsmem;                              // 512*16
    const int i = blockIdx.y;
    const int n0 = blockIdx.x * 128;
    const int warp = threadIdx.x >> 5, lane = threadIdx.x & 31;
    __half* st = hsmem + 512 * 16 + warp * (16 * STG_STRIDE);

    {
        const uint4* src = (const uint4*)(d_uh + (size_t)i * BATCH * 16);
        uint4* dst = (uint4*)As;
        for (int t2 = threadIdx.x; t2 < 1024; t2 += 256) dst[t2] = src[t2];
    }
    __syncthreads();

    const int nrem = NTOT - n0;
    const int no = nrem >> 4;
    const int obase = n0 >> 4;
    const __half* Vb = d_vh + (size_t)i * NTOT * 16;

    unsigned bf0[16], bf1[16];
    #pragma unroll
    for (int tn = 0; tn < 16; tn++) {
        if (tn * 8 < nrem) {
            int n = n0 + tn * 8 + (lane >> 2);
            const __half* p = Vb + n * 16 + (lane & 3) * 2;
            bf0[tn] = *(const unsigned*)(p);
            bf1[tn] = *(const unsigned*)(p + 8);
        } else { bf0[tn] = 0u; bf1[tn] = 0u; }
    }

    #pragma unroll
    for (int mt = 0; mt < 4; mt++) {
        const int m0 = warp * 64 + mt * 16;
        const __half* ap = As + (m0 + (lane >> 2)) * 16 + (lane & 3) * 2;
        unsigned a0 = *(const unsigned*)(ap);
        unsigned a1 = *(const unsigned*)(ap + 8 * 16);
        unsigned a2 = *(const unsigned*)(ap + 8);
        unsigned a3 = *(const unsigned*)(ap + 8 * 16 + 8);
        const int rb = lane >> 2, col = 2 * (lane & 3);
        #pragma unroll
        for (int tn = 0; tn < 16; tn++) {
            if (tn * 8 < nrem) {
                float e0, e1, e2, e3;
                asm volatile(
                    "mma.sync.aligned.m16n8k16.row.col.f32.f16.f16.f32 "
                    "{%0,%1,%2,%3}, {%4,%5,%6,%7}, {%8,%9}, {%10,%11,%12,%13};"
                    : "=f"(e0), "=f"(e1), "=f"(e2), "=f"(e3)
                    : "r"(a0), "r"(a1), "r"(a2), "r"(a3),
                      "r"(bf0[tn]), "r"(bf1[tn]),
                      "f"(0.f), "f"(0.f), "f"(0.f), "f"(0.f));
                int c = tn * 8 + col;
                *(__half2*)&st[rb * STG_STRIDE + c]       = __floats2half2_rn(e0, e1);
                *(__half2*)&st[(rb + 8) * STG_STRIDE + c] = __floats2half2_rn(e2, e3);
            }
        }
        __syncwarp();
        #pragma unroll
        for (int q = 0; q < 8; q++) {
            int v = q * 32 + lane;
            int gr = v >> 1;
            int rb2 = gr & 15, ol = gr >> 4, h = v & 1;
            if (ol < no) {
                uint4 val = *(const uint4*)&st[rb2 * STG_STRIDE + ol * 16 + h * 8];
                *(uint4*)(d_uhat + ((size_t)((m0 + rb2) * NUM_CAPS + obase + ol) * 96
                                    + i) * 16 + h * 8) = val;
            }
        }
        __syncwarp();
    }
}

// ---------------- 3) routing ---------------------------------------------------
__global__ void softmax_first_kernel(const float* __restrict__ caps_b) {
    extern __shared__ float sb[];
    const int t = threadIdx.x;
    for (int e = t; e < OI; e += 256) sb[(e / 96) * 97 + (e % 96)] = caps_b[e];
    __syncthreads();
    const int wid = t >> 5, lane = t & 31;
    for (int i = wid; i < 96; i += 8) {
        float m = -1e30f;
        for (int o = lane; o < NUM_CAPS; o += 32) m = fmaxf(m, sb[o * 97 + i]);
        #pragma unroll
        for (int s = 16; s; s >>= 1) m = fmaxf(m, __shfl_xor_sync(0xffffffffu, m, s));
        float s = 0.f;
        for (int o = lane; o < NUM_CAPS; o += 32) s += expf(sb[o * 97 + i] - m);
        #pragma unroll
        for (int sh = 16; sh; sh >>= 1) s += __shfl_xor_sync(0xffffffffu, s, sh);
        if (lane == 0) d_ms[i] = make_float2(m, 1.0f / s);
    }
}

__global__ void softmax3_kernel() {
    extern __shared__ float sb[];
    const int b = blockIdx.x, t = threadIdx.x;
    const float* blp = d_bl + (size_t)b * OI;
    for (int e = t; e < OI; e += 256) sb[(e / 96) * 97 + (e % 96)] = blp[e];
    __syncthreads();
    const int wid = t >> 5, lane = t & 31;
    for (int i = wid; i < 96; i += 8) {
        float m = -1e30f;
        for (int o = lane; o < NUM_CAPS; o += 32) m = fmaxf(m, sb[o * 97 + i]);
        #pragma unroll
        for (int s = 16; s; s >>= 1) m = fmaxf(m, __shfl_xor_sync(0xffffffffu, m, s));
        float s = 0.f;
        for (int o = lane; o < NUM_CAPS; o += 32) s += expf(sb[o * 97 + i] - m);
        #pragma unroll
        for (int sh = 16; sh; sh >>= 1) s += __shfl_xor_sync(0xffffffffu, s, sh);
        if (lane == 0) d_ms[b * 96 + i] = make_float2(m, 1.0f / s);
    }
}

template<bool FIRST, bool LAST>
__global__ __launch_bounds__(256) void route4_kernel(const float* __restrict__ caps_b) {
    __shared__ float incsh[8][96];
    const int wid = threadIdx.x >> 5, lane = threadIdx.x & 31;
    const int w = blockIdx.x * 8 + wid;            // w = b*181 + o
    const int b = w / NUM_CAPS;
    const uint4* up = (const uint4*)(d_uhat + (size_t)w * UHAT_TILE);
    float* blp = d_bl + (size_t)w * 96;

    float bl0, bl1, bl2;
    if (FIRST) {
        const int o = w - b * NUM_CAPS;
        const float* cbp = caps_b + o * 96;
        bl0 = cbp[lane]; bl1 = cbp[32 + lane]; bl2 = cbp[64 + lane];
    } else {
        bl0 = blp[lane]; bl1 = blp[32 + lane]; bl2 = blp[64 + lane];
    }
    const float2* msp = FIRST ? d_ms : (d_ms + b * 96);
    float2 ms0 = msp[lane], ms1 = msp[32 + lane], ms2 = msp[64 + lane];
    float c0 = expf(bl0 - ms0.x) * ms0.y;
    float c1 = expf(bl1 - ms1.x) * ms1.y;
    float c2 = expf(bl2 - ms2.x) * ms2.y;

    uint4 uv[6];
    float acc[8];
    #pragma unroll
    for (int q = 0; q < 8; q++) acc[q] = 0.f;
    #pragma unroll
    for (int j = 0; j < 6; j++) {
        uv[j] = up[j * 32 + lane];
        float cr = (j < 2) ? c0 : (j < 4) ? c1 : c2;
        float cv = __shfl_sync(0xffffffffu, cr, ((j & 1) << 4) + (lane >> 1));
        const __half2* h = (const __half2*)&uv[j];
        #pragma unroll
        for (int q = 0; q < 4; q++) {
            float2 f = __half22float2(h[q]);
            acc[2*q]   += cv * f.x;
            acc[2*q+1] += cv * f.y;
        }
    }
    #pragma unroll
    for (int m = 2; m <= 16; m <<= 1)
        #pragma unroll
        for (int q = 0; q < 8; q++)
            acc[q] += __shfl_xor_sync(0xffffffffu, acc[q], m);
    float sq = 0.f;
    #pragma unroll
    for (int q = 0; q < 8; q++) sq += acc[q] * acc[q];
    sq += __shfl_xor_sync(0xffffffffu, sq, 1);
    float n = sqrtf(sq);
    float sc = (1.0f - expf(-n)) / (n + 1e-8f);
    #pragma unroll
    for (int q = 0; q < 8; q++) acc[q] *= sc;

    if (LAST) {
        if (lane < 2) {
            float4* xp = (float4*)(d_x + (size_t)w * 16);
            xp[lane * 2 + 0] = make_float4(acc[0], acc[1], acc[2], acc[3]);
            xp[lane * 2 + 1] = make_float4(acc[4], acc[5], acc[6], acc[7]);
        }
    } else {
        #pragma unroll
        for (int j = 0; j < 6; j++) {
            const __half2* h = (const __half2*)&uv[j];
            float p = 0.f;
            #pragma unroll
            for (int q = 0; q < 4; q++) {
                float2 f = __half22float2(h[q]);
                p += acc[2*q] * f.x + acc[2*q+1] * f.y;
            }
            p += __shfl_xor_sync(0xffffffffu, p, 1);
            if (!(lane & 1)) incsh[wid][j * 16 + (lane >> 1)] = p;
        }
        __syncwarp();
        blp[lane]      = bl0 + incsh[wid][lane];
        blp[32 + lane] = bl1 + incsh[wid][32 + lane];
        blp[64 + lane] = bl2 + incsh[wid][64 + lane];
    }
}

// ---------------- 4) length, peaks, top-K, gather ------------------------------
__global__ void finalize_kernel(float* __restrict__ outL) {
    const int b = blockIdx.x, t = threadIdx.x; // 256 threads
    __shared__ float len[192], lnN[192], pk[192], red[256];
    float L = 0.f;
    if (t < NUM_CAPS) {
        const float* xp = d_x + ((size_t)b * NUM_CAPS + t) * 16;
        float n2 = 0.f;
        #pragma unroll
        for (int d = 0; d < 16; d++) { float v = xp[d]; n2 += v * v; }
        L = sqrtf(n2);
        len[t] = L;
    }
    red[t] = (t < NUM_CAPS) ? L : 0.f;
    __syncthreads();
    for (int s = 128; s > 0; s >>= 1) {
        if (t < s) red[t] += red[t + s];
        __syncthreads();
    }
    float tot = red[0];
    if (t < NUM_CAPS) {
        float ln = len[t] / (tot + 1e-8f);
        lnN[t] = ln;
        outL[b * NUM_CAPS + t] = ln;
    }
    __syncthreads();
    if (t < NUM_CAPS) {
        int lo = t - 5 > 0 ? t - 5 : 0;
        int hi = t + 5 < 180 ? t + 5 : 180;
        float m = -1e30f;
        for (int o = lo; o <= hi; o++) m = fmaxf(m, lnN[o]);
        pk[t] = (lnN[t] == m) ? lnN[t] : 0.f;
    }
    __syncthreads();
    if (t == 0) {
        int s0, s1, s2, s3;
        {
            int b0 = -1; float v0 = -1e30f;
            for (int o = 0; o < NUM_CAPS; o++)
                if (pk[o] > v0) { v0 = pk[o]; b0 = o; }
            pk[b0] = -1e30f; s0 = b0;
            int b1 = -1; float v1 = -1e30f;
            for (int o = 0; o < NUM_CAPS; o++)
                if (pk[o] > v1) { v1 = pk[o]; b1 = o; }
            pk[b1] = -1e30f; s1 = b1;
            int b2 = -1; float v2 = -1e30f;
            for (int o = 0; o < NUM_CAPS; o++)
                if (pk[o] > v2) { v2 = pk[o]; b2 = o; }
            pk[b2] = -1e30f; s2 = b2;
            int b3 = -1; float v3 = -1e30f;
            for (int o = 0; o < NUM_CAPS; o++)
                if (pk[o] > v3) { v3 = pk[o]; b3 = o; }
            s3 = b3;
        }
        int tmp;
        if (s0 > s1) { tmp = s0; s0 = s1; s1 = tmp; }
        if (s2 > s3) { tmp = s2; s2 = s3; s3 = tmp; }
        if (s0 > s2) { tmp = s0; s0 = s2; s2 = tmp; }
        if (s1 > s3) { tmp = s1; s1 = s3; s3 = tmp; }
        if (s1 > s2) { tmp = s1; s1 = s2; s2 = tmp; }
        pk[184] = __int_as_float(s0); pk[185] = __int_as_float(s1);
        pk[186] = __int_as_float(s2); pk[187] = __int_as_float(s3);
    }
    __syncthreads();
    if (t < 4 * 16) {
        int k = t >> 4, d = t & 15;
        int sel = __float_as_int(pk[184 + k]);
        if (d == 0) d_idx[b * KSEL + k] = sel;
        d_g[(b * KSEL + k) * 16 + d] = d_x[((size_t)b * NUM_CAPS + sel) * 16 + d];
    }
}

// ---------------- 5) MLP -------------------------------------------------------
__global__ void fc1_kernel(const float* __restrict__ w, const float* __restrict__ bias) {
    const int r = blockIdx.y;
    const int j = blockIdx.x * 256 + threadIdx.x;  // < 1024
    __shared__ float gr[16];
    __shared__ int base;
    if (threadIdx.x < 16) gr[threadIdx.x] = d_g[r * 16 + threadIdx.x];
    if (threadIdx.x == 0) base = d_idx[r] * 16;
    __syncthreads();
    float acc = bias[j];
    #pragma unroll
    for (int d = 0; d < 16; d++) acc += gr[d] * w[(size_t)(base + d) * 1024 + j];
    d_m0h[r * 1024 + j] = __float2half(gelu_f(acc));
}

#define MMA_ACC(CC, A0, A1, A2, A3, B0, B1) \
    asm volatile( \
        "mma.sync.aligned.m16n8k16.row.col.f32.f16.f16.f32 " \
        "{%0,%1,%2,%3}, {%4,%5,%6,%7}, {%8,%9}, {%10,%11,%12,%13};" \
        : "=f"(CC.x), "=f"(CC.y), "=f"(CC.z), "=f"(CC.w) \
        : "r"(A0), "r"(A1), "r"(A2), "r"(A3), "r"(B0), "r"(B1), \
          "f"(CC.x), "f"(CC.y), "f"(CC.z), "f"(CC.w))

#define DO_NT(NT, CLO, CHI) do { \
    const __half* _bp = &Bs[(warp & 3) * 32 + (NT) * 8 + (lane >> 2)][kk + (lane & 3) * 2]; \
    unsigned _b0 = *(const unsigned*)_bp; \
    unsigned _b1 = *(const unsigned*)(_bp + 8); \
    MMA_ACC(CLO, a00, a01, a02, a03, _b0, _b1); \
    MMA_ACC(CHI, a10, a11, a12, a13, _b0, _b1); \
} while (0)

#define EPI(CC, MT, NT) do { \
    int _n0 = bn + (warp & 3) * 32 + (NT) * 8 + (lane & 3) * 2; \
    float _b0v = bias[_n0], _b1v = bias[_n0 + 1]; \
    int _m1 = bm + (warp >> 2) * 32 + (MT) * 16 + (lane >> 2), _m2 = _m1 + 8; \
    float _v0 = CC.x + _b0v, _v1 = CC.y + _b1v, _v2 = CC.z + _b0v, _v3 = CC.w + _b1v; \
    if (ACT) { _v0 = gelu_f(_v0); _v1 = gelu_f(_v1); _v2 = gelu_f(_v2); _v3 = gelu_f(_v3); } \
    if (!TRANS) { \
        *(__half2*)&Ch[(size_t)_m1 * N + _n0] = __floats2half2_rn(_v0, _v1); \
        *(__half2*)&Ch[(size_t)_m2 * N + _n0] = __floats2half2_rn(_v2, _v3); \
    } else { \
        Cf[(size_t)(_m1 >> 2) * (N * 4) + _n0 * 4 + (_m1 & 3)]       = _v0; \
        Cf[(size_t)(_m1 >> 2) * (N * 4) + (_n0 + 1) * 4 + (_m1 & 3)] = _v1; \
        Cf[(size_t)(_m2 >> 2) * (N * 4) + _n0 * 4 + (_m2 & 3)]       = _v2; \
        Cf[(size_t)(_m2 >> 2) * (N * 4) + (_n0 + 1) * 4 + (_m2 & 3)] = _v3; \
    } \
} while (0)

// tensor-core MLP layer. Buffers selected IN DEVICE CODE via template params
// (SRC/DST pick d_m0h/d_m1h; WOFF indexes d_wt). Host passes only harness ptrs.
template<int ACT, int TRANS, int SRC, int DST, int WOFF>
__global__ __launch_bounds__(256) void mlp_mma_kernel(
        const float* __restrict__ bias, float* __restrict__ Cf, int Kd, int N) {
    const __half* __restrict__ A  = SRC ? d_m1h : d_m0h;
    const __half* __restrict__ Wt = d_wt + WOFF;
    __half* __restrict__ Ch       = DST ? d_m1h : d_m0h;
    __shared__ __half As[64][40];
    __shared__ __half Bs[128][40];
    const int bm = blockIdx.y * 64, bn = blockIdx.x * 128;
    const int t = threadIdx.x, warp = t >> 5, lane = t & 31;
    float4 c0 = make_float4(0.f, 0.f, 0.f, 0.f), c1 = c0, c2 = c0, c3 = c0;
    float4 c4 = c0, c5 = c0, c6 = c0, c7 = c0;

    for (int k0 = 0; k0 < Kd; k0 += 32) {
        {
            int r = t >> 2, q = t & 3;
            *(uint4*)&As[r][q * 8] =
                *(const uint4*)&A[(size_t)(bm + r) * Kd + k0 + q * 8];
        }
        #pragma unroll
        for (int it = 0; it < 2; it++) {
            int l = t + it * 256;
            int r = l >> 2, q = l & 3;
            *(uint4*)&Bs[r][q * 8] =
                *(const uint4*)&Wt[(size_t)(bn + r) * Kd + k0 + q * 8];
        }
        __syncthreads();
        #pragma unroll
        for (int ks = 0; ks < 2; ks++) {
            const int kk = ks * 16;
            const __half* ap = &As[(warp >> 2) * 32 + (lane >> 2)][kk + (lane & 3) * 2];
            unsigned a00 = *(const unsigned*)ap;
            unsigned a01 = *(const unsigned*)(ap + 8 * 40);
            unsigned a02 = *(const unsigned*)(ap + 8);
            unsigned a03 = *(const unsigned*)(ap + 8 * 40 + 8);
            const __half* ap1 = ap + 16 * 40;
            unsigned a10 = *(const unsigned*)ap1;
            unsigned a11 = *(const unsigned*)(ap1 + 8 * 40);
            unsigned a12 = *(const unsigned*)(ap1 + 8);
            unsigned a13 = *(const unsigned*)(ap1 + 8 * 40 + 8);
            DO_NT(0, c0, c4);
            DO_NT(1, c1, c5);
            DO_NT(2, c2, c6);
            DO_NT(3, c3, c7);
        }
        __syncthreads();
    }

    EPI(c0, 0, 0); EPI(c1, 0, 1); EPI(c2, 0, 2); EPI(c3, 0, 3);
    EPI(c4, 1, 0); EPI(c5, 1, 1); EPI(c6, 1, 2); EPI(c7, 1, 3);
}

// ---------------- launch -------------------------------------------------------
extern "C" void kernel_launch(void* const* d_in, const int* in_sizes, int n_in,
                              void* d_out, int out_size) {
    const float* scm  = (const float*)d_in[0];
    const float* c1w = (const float*)d_in[2];  const float* c1b = (const float*)d_in[3];
    const float* c2w = (const float*)d_in[4];  const float* c2b = (const float*)d_in[5];
    const float* c3w = (const float*)d_in[6];  const float* c3b = (const float*)d_in[7];
    const float* pcw = (const float*)d_in[8];  const float* pcb = (const float*)d_in[9];
    const float* capsW = (const float*)d_in[10];
    const float* capsb = (const float*)d_in[11];
    const float* f1w = (const float*)d_in[12]; const float* f1b = (const float*)d_in[13];
    const float* f2w = (const float*)d_in[14]; const float* f2b = (const float*)d_in[15];
    const float* f3w = (const float*)d_in[16]; const float* f3b = (const float*)d_in[17];
    const float* f4w = (const float*)d_in[18]; const float* f4b = (const float*)d_in[19];
    const float* f5w = (const float*)d_in[20]; const float* f5b = (const float*)d_in[21];
    const float* hw  = (const float*)d_in[22]; const float* hb  = (const float*)d_in[23];

    float* outW = (float*)d_out;                       // [512, 128, 4]
    float* outL = outW + BATCH * 128 * KSEL;           // [512, 181]

    static int smem_set = 0;
    const int smax_smem = (NUM_CAPS * 97) * sizeof(float);     // ~70.2 KB
    const int conv_smem = (192 + 6144 + 6400) * sizeof(float); // 50944 B
    if (!smem_set) {
        cudaFuncSetAttribute(softmax3_kernel,
                             cudaFuncAttributeMaxDynamicSharedMemorySize, smax_smem);
        cudaFuncSetAttribute(softmax_first_kernel,
                             cudaFuncAttributeMaxDynamicSharedMemorySize, smax_smem);
        cudaFuncSetAttribute(conv_stack_kernel,
                             cudaFuncAttributeMaxDynamicSharedMemorySize, conv_smem);
        cudaFuncSetAttribute(uhat_mma_kernel,
                             cudaFuncAttributeMaxDynamicSharedMemorySize, UHAT_SMEM);
        smem_set = 1;
    }

    const int route_grid = BATCH * NUM_CAPS / 8;

    wrepack_kernel<<<(NUM_CAPS * 1536 + 255) / 256, 256>>>(capsW);                   // 1
    conv_stack_kernel<<<BATCH, 256, conv_smem>>>(scm, c1w, c1b, c2w, c2b, c3w, c3b,
                                                 pcw, pcb);                          // 2
    softmax_first_kernel<<<1, 256, smax_smem>>>(capsb);                              // 3
    uhat_mma_kernel<<<dim3(23, 96), 256, UHAT_SMEM>>>();                             // 4 (ncu)
    // MLP weight transposes (independent; hide behind routing path)
    wtrepack_kernel<<<(1024 * 768 + 255) / 256, 256>>>(f2w, 1024, 768, OFF2);
    wtrepack_kernel<<<( 768 * 512 + 255) / 256, 256>>>(f3w,  768, 512, OFF3);
    wtrepack_kernel<<<( 512 * 512 + 255) / 256, 256>>>(f4w,  512, 512, OFF4);
    wtrepack_kernel<<<( 512 * 256 + 255) / 256, 256>>>(f5w,  512, 256, OFF5);
    wtrepack_kernel<<<( 256 * 128 + 255) / 256, 256>>>(hw,   256, 128, OFFH);
    route4_kernel<true,  false><<<route_grid, 256>>>(capsb);
    softmax3_kernel<<<BATCH, 256, smax_smem>>>();
    route4_kernel<false, false><<<route_grid, 256>>>(capsb);
    softmax3_kernel<<<BATCH, 256, smax_smem>>>();
    route4_kernel<false, true ><<<route_grid, 256>>>(capsb);

    finalize_kernel<<<BATCH, 256>>>(outL);
    fc1_kernel<<<dim3(4, MLP_ROWS), 256>>>(f1w, f1b);
    mlp_mma_kernel<1, 0, 0, 1, OFF2><<<dim3(6, 32), 256>>>(f2b, nullptr, 1024, 768);
    mlp_mma_kernel<1, 0, 1, 0, OFF3><<<dim3(4, 32), 256>>>(f3b, nullptr,  768, 512);
    mlp_mma_kernel<1, 0, 0, 1, OFF4><<<dim3(4, 32), 256>>>(f4b, nullptr,  512, 512);
    mlp_mma_kernel<1, 0, 1, 0, OFF5><<<dim3(2, 32), 256>>>(f5b, nullptr,  512, 256);
    mlp_mma_kernel<0, 1, 0, 1, OFFH><<<dim3(1, 32), 256>>>(hb,  outW,     256, 128);
}

// round 15
// speedup vs baseline: 4.6294x; 1.1358x over previous
#include <cuda_runtime.h>
#include <cuda_fp16.h>
#include <math.h>

#define BATCH 512
#define NUM_CAPS 181
#define IN_CAPS 96
#define CAPS_DIM 16
#define KSEL 4
#define OI (NUM_CAPS * IN_CAPS)          // 17376
#define UHAT_TILE (IN_CAPS * CAPS_DIM)   // 1536
#define MLP_ROWS (BATCH * KSEL)          // 2048
#define NTOT (NUM_CAPS * CAPS_DIM)       // 2896

// transposed fp16 MLP weight offsets inside d_wt
#define OFF2 0
#define OFF3 786432
#define OFF4 1179648
#define OFF5 1441792
#define OFFH 1572864
#define WT_TOTAL 1605632

typedef unsigned long long ull;

// ---------------- scratch (device globals; no allocation allowed) -------------
__device__ __half d_uh[IN_CAPS * BATCH * CAPS_DIM];                // u fp16, [i][b][k]
__device__ __half d_vh[(size_t)IN_CAPS * NTOT * CAPS_DIM];         // W repack, [i][n][k]
__device__ __half d_uhat[(size_t)BATCH * NUM_CAPS * IN_CAPS * CAPS_DIM]; // 285 MB
__device__ float  d_bl[BATCH * OI];
__device__ float2 d_ms[BATCH * IN_CAPS];
__device__ float  d_x[BATCH * NUM_CAPS * CAPS_DIM];
__device__ int    d_idx[BATCH * KSEL];
__device__ float  d_g[MLP_ROWS * CAPS_DIM];
__device__ __half d_m0h[MLP_ROWS * 1024];
__device__ __half d_m1h[MLP_ROWS * 1024];
__device__ __half d_wt[WT_TOTAL];

__device__ __forceinline__ float gelu_f(float x) {
    return 0.5f * x * (1.0f + erff(x * 0.70710678118654752f));
}

// ---------------- f32x2 packed helpers ----------------------------------------
__device__ __forceinline__ ull pk2(float v) {
    ull r; asm("mov.b64 %0, {%1, %1};" : "=l"(r) : "f"(v)); return r;
}
__device__ __forceinline__ ull pkf(float lo, float hi) {
    ull r; asm("mov.b64 %0, {%1, %2};" : "=l"(r) : "f"(lo), "f"(hi)); return r;
}
#define UPK(V, LO, HI) asm("mov.b64 {%0, %1}, %2;" : "=f"(LO), "=f"(HI) : "l"(V))
#define FMA2(ACC, A, B) asm("fma.rn.f32x2 %0, %1, %2, %0;" : "+l"(ACC) : "l"(A), "l"(B))

// ---------------- 0) W repack ---------------------------------------------------
__global__ void wrepack_kernel(const float* __restrict__ capsW) {
    int idx = blockIdx.x * 256 + threadIdx.x;
    if (idx >= NUM_CAPS * 1536) return;
    int o = idx / 1536, r = idx % 1536, i = r >> 4, d = r & 15;
    const float* src = capsW + ((size_t)(o * 96 + i) * 16 + d) * 16;
    __half* dst = d_vh + ((size_t)i * NTOT + o * 16 + d) * 16;
    #pragma unroll
    for (int k = 0; k < 16; k++) dst[k] = __float2half(src[k]);
}

__global__ void wtrepack_kernel(const float* __restrict__ src, int Kd, int N, int off) {
    int idx = blockIdx.x * 256 + threadIdx.x;
    if (idx >= Kd * N) return;
    int n = idx / Kd, k = idx % Kd;
    d_wt[off + idx] = __float2half(src[(size_t)k * N + n]);
}

// ---------------- 1) conv stack: 2 images/block, f32x2 packed -------------------
// smem floats: s_in[384] | Y[12800] (c2 out stride-100/oc; later pc out stride-34)
//              | X[12800] (c1 out [oc][7][8]x2; later c3 out [oc][25]x2)
#define CONV_SMEM ((384 + 12800 + 12800) * 4)

#define LDP8(d, p) do{ \
    ulonglong2 _a = *(const ulonglong2*)(p);        ulonglong2 _b = *(const ulonglong2*)((p)+4); \
    ulonglong2 _c = *(const ulonglong2*)((p)+8);    ulonglong2 _e = *(const ulonglong2*)((p)+12); \
    d[0]=_a.x; d[1]=_a.y; d[2]=_b.x; d[3]=_b.y; d[4]=_c.x; d[5]=_c.y; d[6]=_e.x; d[7]=_e.y; }while(0)

#define LDP6(d, p) do{ \
    ulonglong2 _a = *(const ulonglong2*)(p);        ulonglong2 _b = *(const ulonglong2*)((p)+4); \
    ulonglong2 _c = *(const ulonglong2*)((p)+8); \
    d[0]=_a.x; d[1]=_a.y; d[2]=_b.x; d[3]=_b.y; d[4]=_c.x; d[5]=_c.y; }while(0)

#define LDP5(d, p) do{ \
    d[0]=*(const ull*)(p);     d[1]=*(const ull*)((p)+2); d[2]=*(const ull*)((p)+4); \
    d[3]=*(const ull*)((p)+6); d[4]=*(const ull*)((p)+8); }while(0)

#define CROW2(top, bot, acc, yy, W) do{ \
    _Pragma("unroll") \
    for (int _x = 0; _x < (W); _x++){ \
        FMA2(acc[(yy)*(W)+_x], top[_x],     wxx); \
        FMA2(acc[(yy)*(W)+_x], top[_x + 1], wyy); \
        FMA2(acc[(yy)*(W)+_x], bot[_x],     wzz); \
        FMA2(acc[(yy)*(W)+_x], bot[_x + 1], www); } }while(0)

__global__ __launch_bounds__(256, 2) void conv_stack_kernel(
        const float* __restrict__ scm,
        const float* __restrict__ w1, const float* __restrict__ b1,
        const float* __restrict__ w2, const float* __restrict__ b2,
        const float* __restrict__ w3, const float* __restrict__ b3,
        const float* __restrict__ pw, const float* __restrict__ pb) {
    extern __shared__ float smem[];
    float* s_in = smem;            // 384
    float* Y    = smem + 384;      // 12800
    float* X    = smem + 13184;    // 12800
    const int t = threadIdx.x, b0 = blockIdx.x * 2;

    // load 2 images interleaved: s_in[j*2+img]
    for (int i = t; i < 384; i += 256)
        s_in[i] = scm[(size_t)(b0 + (i & 1)) * 192 + (i >> 1)];
    __syncthreads();

    // conv1 (scalar): 3x8x8 -> 64x[7][8]x2 (X)
    for (int idx = t; idx < 64 * 49 * 2; idx += 256) {
        int img = idx & 1, q = idx >> 1;
        int oc = q / 49, r = q % 49, y = r / 7, x = r % 7;
        float acc = b1[oc];
        const float* wp = w1 + oc * 12;
        #pragma unroll
        for (int ic = 0; ic < 3; ic++) {
            const float* ip = s_in + (ic * 64 + y * 8 + x) * 2 + img;
            acc += ip[0]*wp[0] + ip[2]*wp[1] + ip[16]*wp[2] + ip[18]*wp[3];
            wp += 4;
        }
        X[(oc * 56 + y * 8 + x) * 2 + img] = gelu_f(acc);
    }
    __syncthreads();

    // conv2: 64x7x7 -> 128x[6][8]x2 (Y, oc-stride 100). f32x2.
    {
        const int oc = t & 127, half = t >> 7, y0 = half * 3;
        ull acc[18];
        #pragma unroll
        for (int p = 0; p < 18; p++) acc[p] = 0ULL;
        for (int ic = 0; ic < 64; ic++) {
            float4 w = *(const float4*)(w2 + oc * 256 + ic * 4);
            ull wxx = pk2(w.x), wyy = pk2(w.y), wzz = pk2(w.z), www = pk2(w.w);
            const float* Xc = X + (ic * 56 + y0 * 8) * 2;   // rows of 16 floats
            ull r0[8], r1[8];
            LDP8(r0, Xc);
            LDP8(r1, Xc + 16);
            CROW2(r0, r1, acc, 0, 6);
            LDP8(r0, Xc + 32);
            CROW2(r1, r0, acc, 1, 6);
            LDP8(r1, Xc + 48);
            CROW2(r0, r1, acc, 2, 6);
        }
        float bb = b2[oc];
        #pragma unroll
        for (int yy = 0; yy < 3; yy++)
            #pragma unroll
            for (int x = 0; x < 6; x++) {
                float lo, hi; UPK(acc[yy*6+x], lo, hi);
                *(ull*)&Y[oc * 100 + (y0 + yy) * 16 + 2 * x] =
                    pkf(gelu_f(lo + bb), gelu_f(hi + bb));
            }
    }
    __syncthreads();

    // conv3: 128x[6][8]x2 (Y) -> 256x[25]x2 (X). f32x2.
    {
        const int oc = t;
        ull acc[25];
        #pragma unroll
        for (int p = 0; p < 25; p++) acc[p] = 0ULL;
        for (int ic = 0; ic < 128; ic++) {
            float4 w = *(const float4*)(w3 + oc * 512 + ic * 4);
            ull wxx = pk2(w.x), wyy = pk2(w.y), wzz = pk2(w.z), www = pk2(w.w);
            const float* Yc = Y + ic * 100;                 // rows of 16 floats
            ull r0[6], r1[6];
            LDP6(r0, Yc);
            LDP6(r1, Yc + 16);
            CROW2(r0, r1, acc, 0, 5);
            LDP6(r0, Yc + 32);
            CROW2(r1, r0, acc, 1, 5);
            LDP6(r1, Yc + 48);
            CROW2(r0, r1, acc, 2, 5);
            LDP6(r0, Yc + 64);
            CROW2(r1, r0, acc, 3, 5);
            LDP6(r1, Yc + 80);
            CROW2(r0, r1, acc, 4, 5);
        }
        float bb = b3[oc];
        __syncthreads();   // all Y (c2) reads done
        #pragma unroll
        for (int p = 0; p < 25; p++) {
            float lo, hi; UPK(acc[p], lo, hi);
            *(ull*)&X[(oc * 25 + p) * 2] = pkf(gelu_f(lo + bb), gelu_f(hi + bb));
        }
    }
    __syncthreads();

    // primary caps: 256x[25]x2 (X) -> 96x[16]x2 (Y, g-stride 34). f32x2.
    if (t < 192) {
        const int g = t >> 1, half = t & 1, y0 = half * 2;
        ull acc[8];
        #pragma unroll
        for (int p = 0; p < 8; p++) acc[p] = 0ULL;
        for (int ic = 0; ic < 256; ic++) {
            float4 w = *(const float4*)(pw + g * 1024 + ic * 4);
            ull wxx = pk2(w.x), wyy = pk2(w.y), wzz = pk2(w.z), www = pk2(w.w);
            const float* Xc = X + ic * 50 + y0 * 10;        // rows of 10 floats
            ull r0[5], r1[5];
            LDP5(r0, Xc);
            LDP5(r1, Xc + 10);
            CROW2(r0, r1, acc, 0, 4);
            LDP5(r0, Xc + 20);
            CROW2(r1, r0, acc, 1, 4);
        }
        float bb = pb[g];
        #pragma unroll
        for (int yy = 0; yy < 2; yy++)
            #pragma unroll
            for (int x = 0; x < 4; x++) {
                float lo, hi; UPK(acc[yy*4+x], lo, hi);
                *(ull*)&Y[g * 34 + ((y0 + yy) * 4 + x) * 2] = pkf(lo + bb, hi + bb);
            }
    }
    __syncthreads();

    // squash per (capsule, img); store fp16 u as [i][b][k]
    if (t < 192) {
        const int c = t >> 1, img = t & 1, b = b0 + img;
        const float* yp = Y + c * 34 + img;
        float n2 = 0.f;
        #pragma unroll
        for (int d = 0; d < 16; d++) { float v = yp[d * 2]; n2 += v * v; }
        float n = sqrtf(n2);
        float sc = (1.0f - expf(-n)) / (n + 1e-8f);
        __half2* up = (__half2*)(d_uh + ((size_t)c * BATCH + b) * 16);
        #pragma unroll
        for (int q = 0; q < 8; q++)
            up[q] = __floats2half2_rn(yp[4*q] * sc, yp[4*q + 2] * sc);
    }
}

// ---------------- 2) u_hat via tensor cores, smem-staged coalesced stores ------
#define STG_STRIDE 136
#define UHAT_SMEM (512 * 16 * 2 + 8 * 16 * STG_STRIDE * 2)
__global__ __launch_bounds__(256) void uhat_mma_kernel() {
    extern __shared__ __half hsmem[];
    __half* As = hsmem;
    const int i = blockIdx.y;
    const int n0 = blockIdx.x * 128;
    const int warp = threadIdx.x >> 5, lane = threadIdx.x & 31;
    __half* st = hsmem + 512 * 16 + warp * (16 * STG_STRIDE);

    {
        const uint4* src = (const uint4*)(d_uh + (size_t)i * BATCH * 16);
        uint4* dst = (uint4*)As;
        for (int t2 = threadIdx.x; t2 < 1024; t2 += 256) dst[t2] = src[t2];
    }
    __syncthreads();

    const int nrem = NTOT - n0;
    const int no = nrem >> 4;
    const int obase = n0 >> 4;
    const __half* Vb = d_vh + (size_t)i * NTOT * 16;

    unsigned bf0[16], bf1[16];
    #pragma unroll
    for (int tn = 0; tn < 16; tn++) {
        if (tn * 8 < nrem) {
            int n = n0 + tn * 8 + (lane >> 2);
            const __half* p = Vb + n * 16 + (lane & 3) * 2;
            bf0[tn] = *(const unsigned*)(p);
            bf1[tn] = *(const unsigned*)(p + 8);
        } else { bf0[tn] = 0u; bf1[tn] = 0u; }
    }

    #pragma unroll
    for (int mt = 0; mt < 4; mt++) {
        const int m0 = warp * 64 + mt * 16;
        const __half* ap = As + (m0 + (lane >> 2)) * 16 + (lane & 3) * 2;
        unsigned a0 = *(const unsigned*)(ap);
        unsigned a1 = *(const unsigned*)(ap + 8 * 16);
        unsigned a2 = *(const unsigned*)(ap + 8);
        unsigned a3 = *(const unsigned*)(ap + 8 * 16 + 8);
        const int rb = lane >> 2, col = 2 * (lane & 3);
        #pragma unroll
        for (int tn = 0; tn < 16; tn++) {
            if (tn * 8 < nrem) {
                float e0, e1, e2, e3;
                asm volatile(
                    "mma.sync.aligned.m16n8k16.row.col.f32.f16.f16.f32 "
                    "{%0,%1,%2,%3}, {%4,%5,%6,%7}, {%8,%9}, {%10,%11,%12,%13};"
                    : "=f"(e0), "=f"(e1), "=f"(e2), "=f"(e3)
                    : "r"(a0), "r"(a1), "r"(a2), "r"(a3),
                      "r"(bf0[tn]), "r"(bf1[tn]),
                      "f"(0.f), "f"(0.f), "f"(0.f), "f"(0.f));
                int c = tn * 8 + col;
                *(__half2*)&st[rb * STG_STRIDE + c]       = __floats2half2_rn(e0, e1);
                *(__half2*)&st[(rb + 8) * STG_STRIDE + c] = __floats2half2_rn(e2, e3);
            }
        }
        __syncwarp();
        #pragma unroll
        for (int q = 0; q < 8; q++) {
            int v = q * 32 + lane;
            int gr = v >> 1;
            int rb2 = gr & 15, ol = gr >> 4, h = v & 1;
            if (ol < no) {
                uint4 val = *(const uint4*)&st[rb2 * STG_STRIDE + ol * 16 + h * 8];
                *(uint4*)(d_uhat + ((size_t)((m0 + rb2) * NUM_CAPS + obase + ol) * 96
                                    + i) * 16 + h * 8) = val;
            }
        }
        __syncwarp();
    }
}

// ---------------- 3) routing ---------------------------------------------------
__global__ void softmax_first_kernel(const float* __restrict__ caps_b) {
    extern __shared__ float sb[];
    const int t = threadIdx.x;
    for (int e = t; e < OI; e += 256) sb[(e / 96) * 97 + (e % 96)] = caps_b[e];
    __syncthreads();
    const int wid = t >> 5, lane = t & 31;
    for (int i = wid; i < 96; i += 8) {
        float m = -1e30f;
        for (int o = lane; o < NUM_CAPS; o += 32) m = fmaxf(m, sb[o * 97 + i]);
        #pragma unroll
        for (int s = 16; s; s >>= 1) m = fmaxf(m, __shfl_xor_sync(0xffffffffu, m, s));
        float s = 0.f;
        for (int o = lane; o < NUM_CAPS; o += 32) s += expf(sb[o * 97 + i] - m);
        #pragma unroll
        for (int sh = 16; sh; sh >>= 1) s += __shfl_xor_sync(0xffffffffu, s, sh);
        if (lane == 0) d_ms[i] = make_float2(m, 1.0f / s);
    }
}

__global__ void softmax3_kernel() {
    extern __shared__ float sb[];
    const int b = blockIdx.x, t = threadIdx.x;
    const float* blp = d_bl + (size_t)b * OI;
    for (int e = t; e < OI; e += 256) sb[(e / 96) * 97 + (e % 96)] = blp[e];
    __syncthreads();
    const int wid = t >> 5, lane = t & 31;
    for (int i = wid; i < 96; i += 8) {
        float m = -1e30f;
        for (int o = lane; o < NUM_CAPS; o += 32) m = fmaxf(m, sb[o * 97 + i]);
        #pragma unroll
        for (int s = 16; s; s >>= 1) m = fmaxf(m, __shfl_xor_sync(0xffffffffu, m, s));
        float s = 0.f;
        for (int o = lane; o < NUM_CAPS; o += 32) s += expf(sb[o * 97 + i] - m);
        #pragma unroll
        for (int sh = 16; sh; sh >>= 1) s += __shfl_xor_sync(0xffffffffu, s, sh);
        if (lane == 0) d_ms[b * 96 + i] = make_float2(m, 1.0f / s);
    }
}

template<bool FIRST, bool LAST>
__global__ __launch_bounds__(256) void route4_kernel(const float* __restrict__ caps_b) {
    __shared__ float incsh[8][96];
    const int wid = threadIdx.x >> 5, lane = threadIdx.x & 31;
    const int w = blockIdx.x * 8 + wid;
    const int b = w / NUM_CAPS;
    const uint4* up = (const uint4*)(d_uhat + (size_t)w * UHAT_TILE);
    float* blp = d_bl + (size_t)w * 96;

    float bl0, bl1, bl2;
    if (FIRST) {
        const int o = w - b * NUM_CAPS;
        const float* cbp = caps_b + o * 96;
        bl0 = cbp[lane]; bl1 = cbp[32 + lane]; bl2 = cbp[64 + lane];
    } else {
        bl0 = blp[lane]; bl1 = blp[32 + lane]; bl2 = blp[64 + lane];
    }
    const float2* msp = FIRST ? d_ms : (d_ms + b * 96);
    float2 ms0 = msp[lane], ms1 = msp[32 + lane], ms2 = msp[64 + lane];
    float c0 = expf(bl0 - ms0.x) * ms0.y;
    float c1 = expf(bl1 - ms1.x) * ms1.y;
    float c2 = expf(bl2 - ms2.x) * ms2.y;

    uint4 uv[6];
    float acc[8];
    #pragma unroll
    for (int q = 0; q < 8; q++) acc[q] = 0.f;
    #pragma unroll
    for (int j = 0; j < 6; j++) {
        uv[j] = up[j * 32 + lane];
        float cr = (j < 2) ? c0 : (j < 4) ? c1 : c2;
        float cv = __shfl_sync(0xffffffffu, cr, ((j & 1) << 4) + (lane >> 1));
        const __half2* h = (const __half2*)&uv[j];
        #pragma unroll
        for (int q = 0; q < 4; q++) {
            float2 f = __half22float2(h[q]);
            acc[2*q]   += cv * f.x;
            acc[2*q+1] += cv * f.y;
        }
    }
    #pragma unroll
    for (int m = 2; m <= 16; m <<= 1)
        #pragma unroll
        for (int q = 0; q < 8; q++)
            acc[q] += __shfl_xor_sync(0xffffffffu, acc[q], m);
    float sq = 0.f;
    #pragma unroll
    for (int q = 0; q < 8; q++) sq += acc[q] * acc[q];
    sq += __shfl_xor_sync(0xffffffffu, sq, 1);
    float n = sqrtf(sq);
    float sc = (1.0f - expf(-n)) / (n + 1e-8f);
    #pragma unroll
    for (int q = 0; q < 8; q++) acc[q] *= sc;

    if (LAST) {
        if (lane < 2) {
            float4* xp = (float4*)(d_x + (size_t)w * 16);
            xp[lane * 2 + 0] = make_float4(acc[0], acc[1], acc[2], acc[3]);
            xp[lane * 2 + 1] = make_float4(acc[4], acc[5], acc[6], acc[7]);
        }
    } else {
        #pragma unroll
        for (int j = 0; j < 6; j++) {
            const __half2* h = (const __half2*)&uv[j];
            float p = 0.f;
            #pragma unroll
            for (int q = 0; q < 4; q++) {
                float2 f = __half22float2(h[q]);
                p += acc[2*q] * f.x + acc[2*q+1] * f.y;
            }
            p += __shfl_xor_sync(0xffffffffu, p, 1);
            if (!(lane & 1)) incsh[wid][j * 16 + (lane >> 1)] = p;
        }
        __syncwarp();
        blp[lane]      = bl0 + incsh[wid][lane];
        blp[32 + lane] = bl1 + incsh[wid][32 + lane];
        blp[64 + lane] = bl2 + incsh[wid][64 + lane];
    }
}

// ---------------- 4) length, peaks, top-K, gather ------------------------------
__global__ void finalize_kernel(float* __restrict__ outL) {
    const int b = blockIdx.x, t = threadIdx.x;
    __shared__ float len[192], lnN[192], pk[192], red[256];
    float L = 0.f;
    if (t < NUM_CAPS) {
        const float* xp = d_x + ((size_t)b * NUM_CAPS + t) * 16;
        float n2 = 0.f;
        #pragma unroll
        for (int d = 0; d < 16; d++) { float v = xp[d]; n2 += v * v; }
        L = sqrtf(n2);
        len[t] = L;
    }
    red[t] = (t < NUM_CAPS) ? L : 0.f;
    __syncthreads();
    for (int s = 128; s > 0; s >>= 1) {
        if (t < s) red[t] += red[t + s];
        __syncthreads();
    }
    float tot = red[0];
    if (t < NUM_CAPS) {
        float ln = len[t] / (tot + 1e-8f);
        lnN[t] = ln;
        outL[b * NUM_CAPS + t] = ln;
    }
    __syncthreads();
    if (t < NUM_CAPS) {
        int lo = t - 5 > 0 ? t - 5 : 0;
        int hi = t + 5 < 180 ? t + 5 : 180;
        float m = -1e30f;
        for (int o = lo; o <= hi; o++) m = fmaxf(m, lnN[o]);
        pk[t] = (lnN[t] == m) ? lnN[t] : 0.f;
    }
    __syncthreads();
    if (t == 0) {
        int s0, s1, s2, s3;
        {
            int b0 = -1; float v0 = -1e30f;
            for (int o = 0; o < NUM_CAPS; o++)
                if (pk[o] > v0) { v0 = pk[o]; b0 = o; }
            pk[b0] = -1e30f; s0 = b0;
            int b1 = -1; float v1 = -1e30f;
            for (int o = 0; o < NUM_CAPS; o++)
                if (pk[o] > v1) { v1 = pk[o]; b1 = o; }
            pk[b1] = -1e30f; s1 = b1;
            int b2 = -1; float v2 = -1e30f;
            for (int o = 0; o < NUM_CAPS; o++)
                if (pk[o] > v2) { v2 = pk[o]; b2 = o; }
            pk[b2] = -1e30f; s2 = b2;
            int b3 = -1; float v3 = -1e30f;
            for (int o = 0; o < NUM_CAPS; o++)
                if (pk[o] > v3) { v3 = pk[o]; b3 = o; }
            s3 = b3;
        }
        int tmp;
        if (s0 > s1) { tmp = s0; s0 = s1; s1 = tmp; }
        if (s2 > s3) { tmp = s2; s2 = s3; s3 = tmp; }
        if (s0 > s2) { tmp = s0; s0 = s2; s2 = tmp; }
        if (s1 > s3) { tmp = s1; s1 = s3; s3 = tmp; }
        if (s1 > s2) { tmp = s1; s1 = s2; s2 = tmp; }
        pk[184] = __int_as_float(s0); pk[185] = __int_as_float(s1);
        pk[186] = __int_as_float(s2); pk[187] = __int_as_float(s3);
    }
    __syncthreads();
    if (t < 4 * 16) {
        int k = t >> 4, d = t & 15;
        int sel = __float_as_int(pk[184 + k]);
        if (d == 0) d_idx[b * KSEL + k] = sel;
        d_g[(b * KSEL + k) * 16 + d] = d_x[((size_t)b * NUM_CAPS + sel) * 16 + d];
    }
}

// ---------------- 5) MLP -------------------------------------------------------
__global__ void fc1_kernel(const float* __restrict__ w, const float* __restrict__ bias) {
    const int r = blockIdx.y;
    const int j = blockIdx.x * 256 + threadIdx.x;
    __shared__ float gr[16];
    __shared__ int base;
    if (threadIdx.x < 16) gr[threadIdx.x] = d_g[r * 16 + threadIdx.x];
    if (threadIdx.x == 0) base = d_idx[r] * 16;
    __syncthreads();
    float acc = bias[j];
    #pragma unroll
    for (int d = 0; d < 16; d++) acc += gr[d] * w[(size_t)(base + d) * 1024 + j];
    d_m0h[r * 1024 + j] = __float2half(gelu_f(acc));
}

#define MMA_ACC(CC, A0, A1, A2, A3, B0, B1) \
    asm volatile( \
        "mma.sync.aligned.m16n8k16.row.col.f32.f16.f16.f32 " \
        "{%0,%1,%2,%3}, {%4,%5,%6,%7}, {%8,%9}, {%10,%11,%12,%13};" \
        : "=f"(CC.x), "=f"(CC.y), "=f"(CC.z), "=f"(CC.w) \
        : "r"(A0), "r"(A1), "r"(A2), "r"(A3), "r"(B0), "r"(B1), \
          "f"(CC.x), "f"(CC.y), "f"(CC.z), "f"(CC.w))

#define DO_NT(NT, CLO, CHI) do { \
    const __half* _bp = &Bs[(warp & 3) * 32 + (NT) * 8 + (lane >> 2)][kk + (lane & 3) * 2]; \
    unsigned _b0 = *(const unsigned*)_bp; \
    unsigned _b1 = *(const unsigned*)(_bp + 8); \
    MMA_ACC(CLO, a00, a01, a02, a03, _b0, _b1); \
    MMA_ACC(CHI, a10, a11, a12, a13, _b0, _b1); \
} while (0)

#define EPI(CC, MT, NT) do { \
    int _n0 = bn + (warp & 3) * 32 + (NT) * 8 + (lane & 3) * 2; \
    float _b0v = bias[_n0], _b1v = bias[_n0 + 1]; \
    int _m1 = bm + (warp >> 2) * 32 + (MT) * 16 + (lane >> 2), _m2 = _m1 + 8; \
    float _v0 = CC.x + _b0v, _v1 = CC.y + _b1v, _v2 = CC.z + _b0v, _v3 = CC.w + _b1v; \
    if (ACT) { _v0 = gelu_f(_v0); _v1 = gelu_f(_v1); _v2 = gelu_f(_v2); _v3 = gelu_f(_v3); } \
    if (!TRANS) { \
        *(__half2*)&Ch[(size_t)_m1 * N + _n0] = __floats2half2_rn(_v0, _v1); \
        *(__half2*)&Ch[(size_t)_m2 * N + _n0] = __floats2half2_rn(_v2, _v3); \
    } else { \
        Cf[(size_t)(_m1 >> 2) * (N * 4) + _n0 * 4 + (_m1 & 3)]       = _v0; \
        Cf[(size_t)(_m1 >> 2) * (N * 4) + (_n0 + 1) * 4 + (_m1 & 3)] = _v1; \
        Cf[(size_t)(_m2 >> 2) * (N * 4) + _n0 * 4 + (_m2 & 3)]       = _v2; \
        Cf[(size_t)(_m2 >> 2) * (N * 4) + (_n0 + 1) * 4 + (_m2 & 3)] = _v3; \
    } \
} while (0)

template<int ACT, int TRANS, int SRC, int DST, int WOFF>
__global__ __launch_bounds__(256) void mlp_mma_kernel(
        const float* __restrict__ bias, float* __restrict__ Cf, int Kd, int N) {
    const __half* __restrict__ A  = SRC ? d_m1h : d_m0h;
    const __half* __restrict__ Wt = d_wt + WOFF;
    __half* __restrict__ Ch       = DST ? d_m1h : d_m0h;
    __shared__ __half As[64][40];
    __shared__ __half Bs[128][40];
    const int bm = blockIdx.y * 64, bn = blockIdx.x * 128;
    const int t = threadIdx.x, warp = t >> 5, lane = t & 31;
    float4 c0 = make_float4(0.f, 0.f, 0.f, 0.f), c1 = c0, c2 = c0, c3 = c0;
    float4 c4 = c0, c5 = c0, c6 = c0, c7 = c0;

    for (int k0 = 0; k0 < Kd; k0 += 32) {
        {
            int r = t >> 2, q = t & 3;
            *(uint4*)&As[r][q * 8] =
                *(const uint4*)&A[(size_t)(bm + r) * Kd + k0 + q * 8];
        }
        #pragma unroll
        for (int it = 0; it < 2; it++) {
            int l = t + it * 256;
            int r = l >> 2, q = l & 3;
            *(uint4*)&Bs[r][q * 8] =
                *(const uint4*)&Wt[(size_t)(bn + r) * Kd + k0 + q * 8];
        }
        __syncthreads();
        #pragma unroll
        for (int ks = 0; ks < 2; ks++) {
            const int kk = ks * 16;
            const __half* ap = &As[(warp >> 2) * 32 + (lane >> 2)][kk + (lane & 3) * 2];
            unsigned a00 = *(const unsigned*)ap;
            unsigned a01 = *(const unsigned*)(ap + 8 * 40);
            unsigned a02 = *(const unsigned*)(ap + 8);
            unsigned a03 = *(const unsigned*)(ap + 8 * 40 + 8);
            const __half* ap1 = ap + 16 * 40;
            unsigned a10 = *(const unsigned*)ap1;
            unsigned a11 = *(const unsigned*)(ap1 + 8 * 40);
            unsigned a12 = *(const unsigned*)(ap1 + 8);
            unsigned a13 = *(const unsigned*)(ap1 + 8 * 40 + 8);
            DO_NT(0, c0, c4);
            DO_NT(1, c1, c5);
            DO_NT(2, c2, c6);
            DO_NT(3, c3, c7);
        }
        __syncthreads();
    }

    EPI(c0, 0, 0); EPI(c1, 0, 1); EPI(c2, 0, 2); EPI(c3, 0, 3);
    EPI(c4, 1, 0); EPI(c5, 1, 1); EPI(c6, 1, 2); EPI(c7, 1, 3);
}

// ---------------- launch -------------------------------------------------------
extern "C" void kernel_launch(void* const* d_in, const int* in_sizes, int n_in,
                              void* d_out, int out_size) {
    const float* scm  = (const float*)d_in[0];
    const float* c1w = (const float*)d_in[2];  const float* c1b = (const float*)d_in[3];
    const float* c2w = (const float*)d_in[4];  const float* c2b = (const float*)d_in[5];
    const float* c3w = (const float*)d_in[6];  const float* c3b = (const float*)d_in[7];
    const float* pcw = (const float*)d_in[8];  const float* pcb = (const float*)d_in[9];
    const float* capsW = (const float*)d_in[10];
    const float* capsb = (const float*)d_in[11];
    const float* f1w = (const float*)d_in[12]; const float* f1b = (const float*)d_in[13];
    const float* f2w = (const float*)d_in[14]; const float* f2b = (const float*)d_in[15];
    const float* f3w = (const float*)d_in[16]; const float* f3b = (const float*)d_in[17];
    const float* f4w = (const float*)d_in[18]; const float* f4b = (const float*)d_in[19];
    const float* f5w = (const float*)d_in[20]; const float* f5b = (const float*)d_in[21];
    const float* hw  = (const float*)d_in[22]; const float* hb  = (const float*)d_in[23];

    float* outW = (float*)d_out;                       // [512, 128, 4]
    float* outL = outW + BATCH * 128 * KSEL;           // [512, 181]

    static int smem_set = 0;
    const int smax_smem = (NUM_CAPS * 97) * sizeof(float);
    if (!smem_set) {
        cudaFuncSetAttribute(softmax3_kernel,
                             cudaFuncAttributeMaxDynamicSharedMemorySize, smax_smem);
        cudaFuncSetAttribute(softmax_first_kernel,
                             cudaFuncAttributeMaxDynamicSharedMemorySize, smax_smem);
        cudaFuncSetAttribute(conv_stack_kernel,
                             cudaFuncAttributeMaxDynamicSharedMemorySize, CONV_SMEM);
        cudaFuncSetAttribute(uhat_mma_kernel,
                             cudaFuncAttributeMaxDynamicSharedMemorySize, UHAT_SMEM);
        smem_set = 1;
    }

    const int route_grid = BATCH * NUM_CAPS / 8;

    wrepack_kernel<<<(NUM_CAPS * 1536 + 255) / 256, 256>>>(capsW);                   // 1
    softmax_first_kernel<<<1, 256, smax_smem>>>(capsb);                              // 2
    wtrepack_kernel<<<(1024 * 768 + 255) / 256, 256>>>(f2w, 1024, 768, OFF2);        // 3
    conv_stack_kernel<<<BATCH / 2, 256, CONV_SMEM>>>(scm, c1w, c1b, c2w, c2b,
                                                     c3w, c3b, pcw, pcb);            // 4 (ncu)
    uhat_mma_kernel<<<dim3(23, 96), 256, UHAT_SMEM>>>();                             // 5
    wtrepack_kernel<<<( 768 * 512 + 255) / 256, 256>>>(f3w,  768, 512, OFF3);
    wtrepack_kernel<<<( 512 * 512 + 255) / 256, 256>>>(f4w,  512, 512, OFF4);
    wtrepack_kernel<<<( 512 * 256 + 255) / 256, 256>>>(f5w,  512, 256, OFF5);
    wtrepack_kernel<<<( 256 * 128 + 255) / 256, 256>>>(hw,   256, 128, OFFH);
    route4_kernel<true,  false><<<route_grid, 256>>>(capsb);
    softmax3_kernel<<<BATCH, 256, smax_smem>>>();
    route4_kernel<false, false><<<route_grid, 256>>>(capsb);
    softmax3_kernel<<<BATCH, 256, smax_smem>>>();
    route4_kernel<false, true ><<<route_grid, 256>>>(capsb);

    finalize_kernel<<<BATCH, 256>>>(outL);
    fc1_kernel<<<dim3(4, MLP_ROWS), 256>>>(f1w, f1b);
    mlp_mma_kernel<1, 0, 0, 1, OFF2><<<dim3(6, 32), 256>>>(f2b, nullptr, 1024, 768);
    mlp_mma_kernel<1, 0, 1, 0, OFF3><<<dim3(4, 32), 256>>>(f3b, nullptr,  768, 512);
    mlp_mma_kernel<1, 0, 0, 1, OFF4><<<dim3(4, 32), 256>>>(f4b, nullptr,  512, 512);
    mlp_mma_kernel<1, 0, 1, 0, OFF5><<<dim3(2, 32), 256>>>(f5b, nullptr,  512, 256);
    mlp_mma_kernel<0, 1, 0, 1, OFFH><<<dim3(1, 32), 256>>>(hb,  outW,     256, 128);
}